// round 8
// baseline (speedup 1.0000x reference)
#include <cuda_runtime.h>
#include <cuda_bf16.h>
#include <math.h>
#include <cstdint>

// ---------------- problem constants ----------------
constexpr int Bsz  = 2;
constexpr int Nq   = 2048;
constexpr int My   = 512;
constexpr int Cdim = 1536;
constexpr int Hn   = 12;
constexpr int HDim = 128;          // Cdim / Hn
constexpr int RD   = 64;
constexpr int Sk   = Nq + My;      // 2560
constexpr float EPSV  = 1e-6f;
constexpr float SCALE = 0.08838834764831845f;   // 1/sqrt(128)

// ---------------- scratch (static device arrays; no allocs allowed) ----------------
// split-bf16 operand buffers
__device__ __nv_bfloat16 g_xh [(long long)Bsz * Nq * Cdim];
__device__ __nv_bfloat16 g_xl [(long long)Bsz * Nq * Cdim];
__device__ __nv_bfloat16 g_yh [(long long)Bsz * My * Cdim];
__device__ __nv_bfloat16 g_yl [(long long)Bsz * My * Cdim];
__device__ __nv_bfloat16 g_Wqkvh[(long long)3 * Cdim * Cdim];
__device__ __nv_bfloat16 g_Wqkvl[(long long)3 * Cdim * Cdim];
__device__ __nv_bfloat16 g_Wkvh [(long long)2 * Cdim * Cdim];
__device__ __nv_bfloat16 g_Wkvl [(long long)2 * Cdim * Cdim];
__device__ __nv_bfloat16 g_Wph  [(long long)Cdim * Cdim];
__device__ __nv_bfloat16 g_Wpl  [(long long)Cdim * Cdim];
__device__ __nv_bfloat16 g_Obh  [(long long)Bsz * Nq * Cdim];
__device__ __nv_bfloat16 g_Obl  [(long long)Bsz * Nq * Cdim];
// attention split operands
__device__ __nv_bfloat16 g_Qh [(long long)Bsz * Hn * Nq * HDim];
__device__ __nv_bfloat16 g_Ql [(long long)Bsz * Hn * Nq * HDim];
__device__ __nv_bfloat16 g_Kh [(long long)Bsz * Hn * Sk * HDim];
__device__ __nv_bfloat16 g_Kl [(long long)Bsz * Hn * Sk * HDim];
__device__ __nv_bfloat16 g_Vth[(long long)Bsz * Hn * HDim * Sk];  // V^T [bh][d][s]
__device__ __nv_bfloat16 g_Vtl[(long long)Bsz * Hn * HDim * Sk];

// ---------------- small PTX helpers (baseline PTX only) ----------------
__device__ __forceinline__ uint32_t smem_u32(const void* p) {
    uint32_t a;
    asm("{ .reg .u64 t; cvta.to.shared.u64 t, %1; cvt.u32.u64 %0, t; }" : "=r"(a) : "l"(p));
    return a;
}
__device__ __forceinline__ void cp16(uint32_t dst, const void* src) {
    asm volatile("cp.async.cg.shared.global [%0], [%1], 16;" :: "r"(dst), "l"(src));
}
#define CP_COMMIT()  asm volatile("cp.async.commit_group;" ::: "memory")
#define CP_WAIT(n)   asm volatile("cp.async.wait_group %0;" :: "n"(n) : "memory")

__device__ __forceinline__ void mma_bf16(float d[4], const uint32_t a[4], const uint32_t b[2]) {
    asm volatile(
        "mma.sync.aligned.m16n8k16.row.col.f32.bf16.bf16.f32 "
        "{%0,%1,%2,%3}, {%4,%5,%6,%7}, {%8,%9}, {%0,%1,%2,%3};"
        : "+f"(d[0]), "+f"(d[1]), "+f"(d[2]), "+f"(d[3])
        : "r"(a[0]), "r"(a[1]), "r"(a[2]), "r"(a[3]), "r"(b[0]), "r"(b[1]));
}
__device__ __forceinline__ void split_write(float v, __nv_bfloat16* h, __nv_bfloat16* l, long long idx) {
    const __nv_bfloat16 hb = __float2bfloat16(v);
    h[idx] = hb;
    l[idx] = __float2bfloat16(v - __bfloat162float(hb));
}

// ---------------- shared GEMM tile config (R6-proven 128x128) ----------------
constexpr int MM_STRIDE_B = 80;
constexpr int MM_ARR_B    = 128 * MM_STRIDE_B;
constexpr int MM_BUF_B    = 4 * MM_ARR_B;
constexpr int MM_SMEM_B   = 2 * MM_BUF_B;   // 81920

// Macro-free shared main loop is duplicated in the two GEMM kernels below
// (proven R4/R6 structure: K-chunk 32, double-buffered cp.async, LDS fragments).

#define GEMM_MAIN_LOOP(AhP, AlP, BhP, BlP, KD)                                             \
    const int s0   = tid * 2;                                                              \
    const int row_s0 = s0 >> 2,  q_s0 = s0 & 3;                                            \
    const int row_s1 = (s0 + 1) >> 2, q_s1 = (s0 + 1) & 3;                                 \
    auto stage = [&](int c, int buf) {                                                     \
        const long long k0 = (long long)c * 32;                                            \
        const uint32_t db = sbase + buf * MM_BUF_B;                                        \
        {                                                                                  \
            const long long ga = (long long)(row0 + row_s0) * (KD) + k0 + q_s0 * 8;        \
            const long long gb = (long long)(col0 + row_s0) * (KD) + k0 + q_s0 * 8;        \
            const uint32_t  so = row_s0 * MM_STRIDE_B + q_s0 * 16;                         \
            cp16(db + 0 * MM_ARR_B + so, (AhP) + ga);                                      \
            cp16(db + 1 * MM_ARR_B + so, (AlP) + ga);                                      \
            cp16(db + 2 * MM_ARR_B + so, (BhP) + gb);                                      \
            cp16(db + 3 * MM_ARR_B + so, (BlP) + gb);                                      \
        }                                                                                  \
        {                                                                                  \
            const long long ga = (long long)(row0 + row_s1) * (KD) + k0 + q_s1 * 8;        \
            const long long gb = (long long)(col0 + row_s1) * (KD) + k0 + q_s1 * 8;        \
            const uint32_t  so = row_s1 * MM_STRIDE_B + q_s1 * 16;                         \
            cp16(db + 0 * MM_ARR_B + so, (AhP) + ga);                                      \
            cp16(db + 1 * MM_ARR_B + so, (AlP) + ga);                                      \
            cp16(db + 2 * MM_ARR_B + so, (BhP) + gb);                                      \
            cp16(db + 3 * MM_ARR_B + so, (BlP) + gb);                                      \
        }                                                                                  \
    };                                                                                     \
    float acc[4][4][4];                                                                    \
    _Pragma("unroll")                                                                      \
    for (int i = 0; i < 4; i++)                                                            \
        _Pragma("unroll")                                                                  \
        for (int j = 0; j < 4; j++)                                                        \
            _Pragma("unroll")                                                              \
            for (int r = 0; r < 4; r++) acc[i][j][r] = 0.f;                                \
    const int nch = (KD) / 32;                                                             \
    stage(0, 0);                                                                           \
    CP_COMMIT();                                                                           \
    for (int c = 0; c < nch; c++) {                                                        \
        if (c + 1 < nch) { stage(c + 1, (c + 1) & 1); CP_COMMIT(); CP_WAIT(1); }           \
        else             { CP_WAIT(0); }                                                   \
        __syncthreads();                                                                   \
        const char* bp = smem + (c & 1) * MM_BUF_B;                                        \
        const char* pAh = bp;                                                              \
        const char* pAl = bp + MM_ARR_B;                                                   \
        const char* pBh = bp + 2 * MM_ARR_B;                                               \
        const char* pBl = bp + 3 * MM_ARR_B;                                               \
        _Pragma("unroll")                                                                  \
        for (int kk = 0; kk < 2; kk++) {                                                   \
            const int cbyte = (kk * 16 + 2 * tg) * 2;                                      \
            uint32_t ah[4][4], al[4][4], bh[4][2], bl[4][2];                               \
            _Pragma("unroll")                                                              \
            for (int mt = 0; mt < 4; mt++) {                                               \
                const int r = wm + mt * 16 + g;                                            \
                ah[mt][0] = *(const uint32_t*)(pAh + r * MM_STRIDE_B + cbyte);             \
                ah[mt][1] = *(const uint32_t*)(pAh + (r + 8) * MM_STRIDE_B + cbyte);       \
                ah[mt][2] = *(const uint32_t*)(pAh + r * MM_STRIDE_B + cbyte + 16);        \
                ah[mt][3] = *(const uint32_t*)(pAh + (r + 8) * MM_STRIDE_B + cbyte + 16);  \
                al[mt][0] = *(const uint32_t*)(pAl + r * MM_STRIDE_B + cbyte);             \
                al[mt][1] = *(const uint32_t*)(pAl + (r + 8) * MM_STRIDE_B + cbyte);       \
                al[mt][2] = *(const uint32_t*)(pAl + r * MM_STRIDE_B + cbyte + 16);        \
                al[mt][3] = *(const uint32_t*)(pAl + (r + 8) * MM_STRIDE_B + cbyte + 16);  \
            }                                                                              \
            _Pragma("unroll")                                                              \
            for (int nt = 0; nt < 4; nt++) {                                               \
                const int n = wn + nt * 8 + g;                                             \
                bh[nt][0] = *(const uint32_t*)(pBh + n * MM_STRIDE_B + cbyte);             \
                bh[nt][1] = *(const uint32_t*)(pBh + n * MM_STRIDE_B + cbyte + 16);        \
                bl[nt][0] = *(const uint32_t*)(pBl + n * MM_STRIDE_B + cbyte);             \
                bl[nt][1] = *(const uint32_t*)(pBl + n * MM_STRIDE_B + cbyte + 16);        \
            }                                                                              \
            _Pragma("unroll")                                                              \
            for (int mt = 0; mt < 4; mt++)                                                 \
                _Pragma("unroll")                                                          \
                for (int nt = 0; nt < 4; nt++) {                                           \
                    mma_bf16(acc[mt][nt], ah[mt], bh[nt]);                                 \
                    mma_bf16(acc[mt][nt], ah[mt], bl[nt]);                                 \
                    mma_bf16(acc[mt][nt], al[mt], bh[nt]);                                 \
                }                                                                          \
        }                                                                                  \
        __syncthreads();                                                                   \
    }

// ---------------- proj GEMM: fp32 out + bias ----------------
__global__ __launch_bounds__(256)
void mma_gemm_proj(const __nv_bfloat16* __restrict__ Ah, const __nv_bfloat16* __restrict__ Al,
                   const __nv_bfloat16* __restrict__ Bh, const __nv_bfloat16* __restrict__ Bl,
                   float* __restrict__ C, const float* __restrict__ bias)
{
    extern __shared__ char smem[];
    const uint32_t sbase = smem_u32(smem);
    const int tid  = threadIdx.x;
    const int lane = tid & 31;
    const int wid  = tid >> 5;
    const int row0 = blockIdx.y * 128;
    const int col0 = blockIdx.x * 128;
    const int wm   = (wid >> 2) * 64;
    const int wn   = (wid & 3) * 32;
    const int g    = lane >> 2;
    const int tg   = lane & 3;

    GEMM_MAIN_LOOP(Ah, Al, Bh, Bl, Cdim)

    #pragma unroll
    for (int nt = 0; nt < 4; nt++) {
        const int col = col0 + wn + nt * 8 + 2 * tg;
        const float b0 = bias[col], b1 = bias[col + 1];
        #pragma unroll
        for (int mt = 0; mt < 4; mt++) {
            const int r = row0 + wm + mt * 16 + g;
            float2 v0, v1;
            v0.x = acc[mt][nt][0] + b0; v0.y = acc[mt][nt][1] + b1;
            v1.x = acc[mt][nt][2] + b0; v1.y = acc[mt][nt][3] + b1;
            *(float2*)(C + (long long)r * Cdim + col)       = v0;
            *(float2*)(C + (long long)(r + 8) * Cdim + col) = v1;
        }
    }
}

// ---------------- QKV / KV GEMM with fused RMSNorm + RoPE + split + scatter -----
// MODE 0: A = x [Bsz*Nq, Cdim], W = Wqkv^T [4608, Cdim]; col tile = one head of q/k/v.
// MODE 1: A = y [Bsz*My, Cdim],  W = Wkv^T  [3072, Cdim]; col tile = one head of k/v.
template<int MODE>
__global__ __launch_bounds__(256)
void mma_gemm_qkv(const __nv_bfloat16* __restrict__ Ah, const __nv_bfloat16* __restrict__ Al,
                  const __nv_bfloat16* __restrict__ Bh, const __nv_bfloat16* __restrict__ Bl,
                  const float* __restrict__ pos,
                  const float* __restrict__ qw, const float* __restrict__ kw,
                  __nv_bfloat16* __restrict__ Qh, __nv_bfloat16* __restrict__ Ql,
                  __nv_bfloat16* __restrict__ Kh, __nv_bfloat16* __restrict__ Kl,
                  __nv_bfloat16* __restrict__ Vth, __nv_bfloat16* __restrict__ Vtl)
{
    extern __shared__ char smem[];
    const uint32_t sbase = smem_u32(smem);
    const int tid  = threadIdx.x;
    const int lane = tid & 31;
    const int wid  = tid >> 5;
    const int row0 = blockIdx.y * 128;
    const int col0 = blockIdx.x * 128;
    const int wm   = (wid >> 2) * 64;
    const int wn   = (wid & 3) * 32;
    const int g    = lane >> 2;
    const int tg   = lane & 3;

    GEMM_MAIN_LOOP(Ah, Al, Bh, Bl, Cdim)

    // ---- fused epilogue ----
    const int seg = MODE ? (col0 / Cdim + 1) : (col0 / Cdim);   // 0=q, 1=k, 2=v
    const int hh  = (col0 % Cdim) / HDim;
    constexpr int T = MODE ? My : Nq;
    const int bb   = row0 / T;
    const int n0   = row0 % T;
    constexpr int soff = MODE ? Nq : 0;

    float* sT = (float*)smem;                       // [128][132] fp32 tile
    float* sP = (float*)(smem + 128 * 132 * 4);     // [4][128] row partials

    if (seg != 2) {
        #pragma unroll
        for (int mt = 0; mt < 4; mt++) {
            float p0 = 0.f, p1 = 0.f;
            #pragma unroll
            for (int nt = 0; nt < 4; nt++) {
                p0 += acc[mt][nt][0] * acc[mt][nt][0] + acc[mt][nt][1] * acc[mt][nt][1];
                p1 += acc[mt][nt][2] * acc[mt][nt][2] + acc[mt][nt][3] * acc[mt][nt][3];
            }
            p0 += __shfl_xor_sync(0xffffffffu, p0, 1);
            p0 += __shfl_xor_sync(0xffffffffu, p0, 2);
            p1 += __shfl_xor_sync(0xffffffffu, p1, 1);
            p1 += __shfl_xor_sync(0xffffffffu, p1, 2);
            if (tg == 0) {
                sP[(wn >> 5) * 128 + wm + mt * 16 + g]     = p0;
                sP[(wn >> 5) * 128 + wm + mt * 16 + g + 8] = p1;
            }
        }
    }
    #pragma unroll
    for (int mt = 0; mt < 4; mt++)
        #pragma unroll
        for (int nt = 0; nt < 4; nt++) {
            const int r = wm + mt * 16 + g, c = wn + nt * 8 + 2 * tg;
            float2 v0, v1;
            v0.x = acc[mt][nt][0]; v0.y = acc[mt][nt][1];
            v1.x = acc[mt][nt][2]; v1.y = acc[mt][nt][3];
            *(float2*)&sT[r * 132 + c]       = v0;
            *(float2*)&sT[(r + 8) * 132 + c] = v1;
        }
    __syncthreads();

    if (seg == 2) {
        // V tile -> transposed split write: Vt[bh][d][s]
        const int d  = tid >> 1;
        const int sh = (tid & 1) * 64;
        const long long base = ((long long)(bb * Hn + hh) * HDim + d) * Sk + soff + n0 + sh;
        #pragma unroll 8
        for (int i = 0; i < 64; i++) {
            split_write(sT[(sh + i) * 132 + d], Vth, Vtl, base + i);
        }
    } else {
        const int r  = tid >> 1;
        const int c0 = (tid & 1) * 64;
        const int n  = n0 + r;
        const float sum = sP[r] + sP[128 + r] + sP[256 + r] + sP[384 + r];
        const float rinv = rsqrtf(sum * (1.0f / HDim) + EPSV);
        const float* w = (seg == 0) ? qw : kw;
        __nv_bfloat16 *oh, *ol;
        long long base;
        if (seg == 0) { base = ((long long)(bb * Hn + hh) * Nq + n) * HDim; oh = Qh; ol = Ql; }
        else          { base = ((long long)(bb * Hn + hh) * Sk + soff + n) * HDim; oh = Kh; ol = Kl; }

        if (MODE == 0 && c0 == 0) {
            // rotated half: pairs (j, j+32), both inside cols [0,64)
            #pragma unroll 4
            for (int j = 0; j < 32; j++) {
                const float a  = sT[r * 132 + j]      * rinv * w[j];
                const float bq = sT[r * 132 + j + 32] * rinv * w[j + 32];
                const float cs = pos[(n * 32 + j) * 2 + 0];
                const float sn = pos[(n * 32 + j) * 2 + 1];
                split_write(a * cs - bq * sn, oh, ol, base + j);
                split_write(a * sn + bq * cs, oh, ol, base + j + 32);
            }
        } else {
            #pragma unroll 8
            for (int i = 0; i < 64; i++) {
                const int d = c0 + i;
                split_write(sT[r * 132 + d] * rinv * w[d], oh, ol, base + d);
            }
        }
    }
}

// ---------------- fused attention: S = QK^T, exp(+bias), O = P V, normalize ------
constexpr int FA_NIT = Sk / 64;
constexpr int FQ   = 0;
constexpr int FQL  = 34816;
constexpr int FK   = 69632;
constexpr int FKHALF = 17408;
constexpr int FKBUF  = 34816;
constexpr int FV   = 139264;
constexpr int FVL  = 157696;
constexpr int FP   = 176128;
constexpr int FPL  = 194560;
constexpr int FRS  = 212992;
constexpr int FYB  = 214016;
constexpr int FA_SMEM = 216064;

__global__ __launch_bounds__(256, 1)
void fused_attn(const __nv_bfloat16* __restrict__ Qh, const __nv_bfloat16* __restrict__ Ql,
                const __nv_bfloat16* __restrict__ Kh, const __nv_bfloat16* __restrict__ Kl,
                const __nv_bfloat16* __restrict__ Vth, const __nv_bfloat16* __restrict__ Vtl,
                const float* __restrict__ ytw,
                __nv_bfloat16* __restrict__ Obh, __nv_bfloat16* __restrict__ Obl)
{
    extern __shared__ char smem[];
    const uint32_t sb = smem_u32(smem);

    const int z  = blockIdx.y;
    const int q0 = blockIdx.x * 128;
    const int b  = z / Hn;
    const int h  = z % Hn;

    const int tid  = threadIdx.x;
    const int lane = tid & 31;
    const int wid  = tid >> 5;
    const int g    = lane >> 2;
    const int tg   = lane & 3;
    const int wm   = (wid >> 1) * 32;
    const int wn   = (wid & 1) * 32;
    const int wn2  = (wid & 1) * 64;

    const __nv_bfloat16* Qhp = Qh + (long long)z * Nq * HDim;
    const __nv_bfloat16* Qlp = Ql + (long long)z * Nq * HDim;
    const __nv_bfloat16* Khp = Kh + (long long)z * Sk * HDim;
    const __nv_bfloat16* Klp = Kl + (long long)z * Sk * HDim;
    const __nv_bfloat16* Vhp = Vth + (long long)z * HDim * Sk;
    const __nv_bfloat16* Vlp = Vtl + (long long)z * HDim * Sk;

    float* sYB = (float*)(smem + FYB);
    sYB[tid]       = logf(fmaxf(ytw[b * My + tid], 1e-4f));
    sYB[tid + 256] = logf(fmaxf(ytw[b * My + tid + 256], 1e-4f));

    #pragma unroll
    for (int j = 0; j < 8; j++) {
        const int id = tid + j * 256, r = id >> 4, c = id & 15;
        cp16(sb + FQ  + r * 272 + c * 16, Qhp + (long long)(q0 + r) * HDim + c * 8);
        cp16(sb + FQL + r * 272 + c * 16, Qlp + (long long)(q0 + r) * HDim + c * 8);
    }
    #pragma unroll
    for (int j = 0; j < 4; j++) {
        const int id = tid + j * 256, r = id >> 4, c = id & 15;
        cp16(sb + FK +          r * 272 + c * 16, Khp + (long long)r * HDim + c * 8);
        cp16(sb + FK + FKHALF + r * 272 + c * 16, Klp + (long long)r * HDim + c * 8);
    }
    CP_COMMIT();

    float oacc[2][8][4];
    #pragma unroll
    for (int i = 0; i < 2; i++)
        #pragma unroll
        for (int j = 0; j < 8; j++)
            #pragma unroll
            for (int r = 0; r < 4; r++) oacc[i][j][r] = 0.f;
    float rowsum[4] = {0.f, 0.f, 0.f, 0.f};

    for (int it = 0; it < FA_NIT; it++) {
        __syncthreads();
        #pragma unroll
        for (int j = 0; j < 4; j++) {
            const int id = tid + j * 256, d = id >> 3, c = id & 7;
            cp16(sb + FV  + d * 144 + c * 16, Vhp + (long long)d * Sk + it * 64 + c * 8);
            cp16(sb + FVL + d * 144 + c * 16, Vlp + (long long)d * Sk + it * 64 + c * 8);
        }
        if (it + 1 < FA_NIT) {
            const int sblk = (it + 1) * 64;
            const uint32_t kb = sb + FK + ((it + 1) & 1) * FKBUF;
            #pragma unroll
            for (int j = 0; j < 4; j++) {
                const int id = tid + j * 256, r = id >> 4, c = id & 15;
                cp16(kb +          r * 272 + c * 16, Khp + (long long)(sblk + r) * HDim + c * 8);
                cp16(kb + FKHALF + r * 272 + c * 16, Klp + (long long)(sblk + r) * HDim + c * 8);
            }
        }
        CP_COMMIT();
        CP_WAIT(1);
        __syncthreads();

        const char* kbp = smem + FK + (it & 1) * FKBUF;
        float sacc[2][4][4];
        #pragma unroll
        for (int i = 0; i < 2; i++)
            #pragma unroll
            for (int j = 0; j < 4; j++)
                #pragma unroll
                for (int r = 0; r < 4; r++) sacc[i][j][r] = 0.f;

        #pragma unroll
        for (int kk = 0; kk < 8; kk++) {
            const int cb = kk * 32 + tg * 4;
            uint32_t qh_[2][4], ql_[2][4], kh_[4][2], kl_[4][2];
            #pragma unroll
            for (int mt = 0; mt < 2; mt++) {
                const char* p = smem + FQ + (wm + mt * 16 + g) * 272 + cb;
                qh_[mt][0] = *(const uint32_t*)(p);
                qh_[mt][1] = *(const uint32_t*)(p + 8 * 272);
                qh_[mt][2] = *(const uint32_t*)(p + 16);
                qh_[mt][3] = *(const uint32_t*)(p + 8 * 272 + 16);
                ql_[mt][0] = *(const uint32_t*)(p + FQL);
                ql_[mt][1] = *(const uint32_t*)(p + FQL + 8 * 272);
                ql_[mt][2] = *(const uint32_t*)(p + FQL + 16);
                ql_[mt][3] = *(const uint32_t*)(p + FQL + 8 * 272 + 16);
            }
            #pragma unroll
            for (int nt = 0; nt < 4; nt++) {
                const char* p = kbp + (wn + nt * 8 + g) * 272 + cb;
                kh_[nt][0] = *(const uint32_t*)(p);
                kh_[nt][1] = *(const uint32_t*)(p + 16);
                kl_[nt][0] = *(const uint32_t*)(p + FKHALF);
                kl_[nt][1] = *(const uint32_t*)(p + FKHALF + 16);
            }
            #pragma unroll
            for (int mt = 0; mt < 2; mt++)
                #pragma unroll
                for (int nt = 0; nt < 4; nt++) {
                    mma_bf16(sacc[mt][nt], qh_[mt], kh_[nt]);
                    mma_bf16(sacc[mt][nt], qh_[mt], kl_[nt]);
                    mma_bf16(sacc[mt][nt], ql_[mt], kh_[nt]);
                }
        }

        #pragma unroll
        for (int mt = 0; mt < 2; mt++) {
            #pragma unroll
            for (int nt = 0; nt < 4; nt++) {
                const int col0 = wn + nt * 8 + 2 * tg;
                const int gc   = it * 64 + col0;
                float b0 = 0.f, b1 = 0.f;
                if (gc >= Nq) { b0 = sYB[gc - Nq]; b1 = sYB[gc - Nq + 1]; }
                const float p0 = __expf(sacc[mt][nt][0] * SCALE + b0);
                const float p1 = __expf(sacc[mt][nt][1] * SCALE + b1);
                const float p2 = __expf(sacc[mt][nt][2] * SCALE + b0);
                const float p3 = __expf(sacc[mt][nt][3] * SCALE + b1);
                rowsum[mt * 2 + 0] += p0 + p1;
                rowsum[mt * 2 + 1] += p2 + p3;
                const int r0 = wm + mt * 16 + g;
                __nv_bfloat162 hv, lv;
                hv.x = __float2bfloat16(p0); hv.y = __float2bfloat16(p1);
                lv.x = __float2bfloat16(p0 - __bfloat162float(hv.x));
                lv.y = __float2bfloat16(p1 - __bfloat162float(hv.y));
                *(__nv_bfloat162*)(smem + FP  + r0 * 144 + col0 * 2) = hv;
                *(__nv_bfloat162*)(smem + FPL + r0 * 144 + col0 * 2) = lv;
                hv.x = __float2bfloat16(p2); hv.y = __float2bfloat16(p3);
                lv.x = __float2bfloat16(p2 - __bfloat162float(hv.x));
                lv.y = __float2bfloat16(p3 - __bfloat162float(hv.y));
                *(__nv_bfloat162*)(smem + FP  + (r0 + 8) * 144 + col0 * 2) = hv;
                *(__nv_bfloat162*)(smem + FPL + (r0 + 8) * 144 + col0 * 2) = lv;
            }
        }

        CP_WAIT(0);
        __syncthreads();

        #pragma unroll
        for (int kk = 0; kk < 4; kk++) {
            const int cb = kk * 32 + tg * 4;
            uint32_t ph_[2][4], pl_[2][4], vh_[8][2], vl_[8][2];
            #pragma unroll
            for (int mt = 0; mt < 2; mt++) {
                const char* p = smem + FP + (wm + mt * 16 + g) * 144 + cb;
                ph_[mt][0] = *(const uint32_t*)(p);
                ph_[mt][1] = *(const uint32_t*)(p + 8 * 144);
                ph_[mt][2] = *(const uint32_t*)(p + 16);
                ph_[mt][3] = *(const uint32_t*)(p + 8 * 144 + 16);
                const char* q = p + (FPL - FP);
                pl_[mt][0] = *(const uint32_t*)(q);
                pl_[mt][1] = *(const uint32_t*)(q + 8 * 144);
                pl_[mt][2] = *(const uint32_t*)(q + 16);
                pl_[mt][3] = *(const uint32_t*)(q + 8 * 144 + 16);
            }
            #pragma unroll
            for (int nt = 0; nt < 8; nt++) {
                const char* p = smem + FV + (wn2 + nt * 8 + g) * 144 + cb;
                vh_[nt][0] = *(const uint32_t*)(p);
                vh_[nt][1] = *(const uint32_t*)(p + 16);
                vl_[nt][0] = *(const uint32_t*)(p + (FVL - FV));
                vl_[nt][1] = *(const uint32_t*)(p + (FVL - FV) + 16);
            }
            #pragma unroll
            for (int mt = 0; mt < 2; mt++)
                #pragma unroll
                for (int nt = 0; nt < 8; nt++) {
                    mma_bf16(oacc[mt][nt], ph_[mt], vh_[nt]);
                    mma_bf16(oacc[mt][nt], ph_[mt], vl_[nt]);
                    mma_bf16(oacc[mt][nt], pl_[mt], vh_[nt]);
                }
        }
    }

    #pragma unroll
    for (int j = 0; j < 4; j++) {
        rowsum[j] += __shfl_xor_sync(0xffffffffu, rowsum[j], 1);
        rowsum[j] += __shfl_xor_sync(0xffffffffu, rowsum[j], 2);
    }
    float* sRS = (float*)(smem + FRS);
    if (tg == 0) {
        sRS[(wid & 1) * 128 + wm + g]      = rowsum[0];
        sRS[(wid & 1) * 128 + wm + g + 8]  = rowsum[1];
        sRS[(wid & 1) * 128 + wm + g + 16] = rowsum[2];
        sRS[(wid & 1) * 128 + wm + g + 24] = rowsum[3];
    }
    __syncthreads();

    #pragma unroll
    for (int mt = 0; mt < 2; mt++) {
        const int r = wm + mt * 16 + g;
        const float inv0 = 1.f / (sRS[r]     + sRS[128 + r]);
        const float inv1 = 1.f / (sRS[r + 8] + sRS[128 + r + 8]);
        #pragma unroll
        for (int nt = 0; nt < 8; nt++) {
            const int col = wn2 + nt * 8 + 2 * tg;
            const long long o0 = ((long long)b * Nq + q0 + r) * Cdim + h * HDim + col;
            const long long o1 = o0 + 8LL * Cdim;
            const float a0 = oacc[mt][nt][0] * inv0, a1 = oacc[mt][nt][1] * inv0;
            const float a2 = oacc[mt][nt][2] * inv1, a3 = oacc[mt][nt][3] * inv1;
            __nv_bfloat162 hv, lv;
            hv.x = __float2bfloat16(a0); hv.y = __float2bfloat16(a1);
            lv.x = __float2bfloat16(a0 - __bfloat162float(hv.x));
            lv.y = __float2bfloat16(a1 - __bfloat162float(hv.y));
            *(__nv_bfloat162*)(Obh + o0) = hv;
            *(__nv_bfloat162*)(Obl + o0) = lv;
            hv.x = __float2bfloat16(a2); hv.y = __float2bfloat16(a3);
            lv.x = __float2bfloat16(a2 - __bfloat162float(hv.x));
            lv.y = __float2bfloat16(a3 - __bfloat162float(hv.y));
            *(__nv_bfloat162*)(Obh + o1) = hv;
            *(__nv_bfloat162*)(Obl + o1) = lv;
        }
    }
}

// ---------------- fp32 -> split bf16 (row-major keep) ----------------
__global__ void cvt_split(const float* __restrict__ src, __nv_bfloat16* __restrict__ h,
                          __nv_bfloat16* __restrict__ l, long long n)
{
    const long long i = ((long long)blockIdx.x * blockDim.x + threadIdx.x) * 4;
    if (i >= n) return;
    const float4 v = *(const float4*)(src + i);
    __nv_bfloat16 hb[4], lb[4];
    const float f[4] = {v.x, v.y, v.z, v.w};
    #pragma unroll
    for (int j = 0; j < 4; j++) {
        hb[j] = __float2bfloat16(f[j]);
        lb[j] = __float2bfloat16(f[j] - __bfloat162float(hb[j]));
    }
    *(uint2*)(h + i) = *(uint2*)hb;
    *(uint2*)(l + i) = *(uint2*)lb;
}

// ---------------- fp32 [K][N] -> split bf16 transposed [N][K] ----------------
__global__ void cvt_split_T(const float* __restrict__ W, __nv_bfloat16* __restrict__ h,
                            __nv_bfloat16* __restrict__ l, int K, int N)
{
    __shared__ float tile[32][33];
    const int k0 = blockIdx.y * 32;
    const int n0 = blockIdx.x * 32;
    const int tx = threadIdx.x;
    const int ty = threadIdx.y;
    #pragma unroll
    for (int i = ty; i < 32; i += 8)
        tile[i][tx] = W[(long long)(k0 + i) * N + n0 + tx];
    __syncthreads();
    #pragma unroll
    for (int i = ty; i < 32; i += 8) {
        const float v = tile[tx][i];
        const __nv_bfloat16 hb = __float2bfloat16(v);
        const __nv_bfloat16 lb = __float2bfloat16(v - __bfloat162float(hb));
        const long long o = (long long)(n0 + i) * K + k0 + tx;
        h[o] = hb; l[o] = lb;
    }
}

// ---------------- launch ----------------
extern "C" void kernel_launch(void* const* d_in, const int* in_sizes, int n_in,
                              void* d_out, int out_size)
{
    const float* x    = (const float*)d_in[0];
    const float* y    = (const float*)d_in[1];
    const float* pos  = (const float*)d_in[2];
    const float* ytw  = (const float*)d_in[3];
    const float* Wqkv = (const float*)d_in[4];
    const float* Wkv  = (const float*)d_in[5];
    const float* qw   = (const float*)d_in[6];
    const float* kw   = (const float*)d_in[7];
    const float* Wproj= (const float*)d_in[8];
    const float* bproj= (const float*)d_in[9];
    float* out = (float*)d_out;

    __nv_bfloat16 *xh,*xl,*yh,*yl,*Wqh,*Wql,*Wkh,*Wkl,*Wph,*Wpl,*Obh,*Obl;
    __nv_bfloat16 *Qh,*Ql,*Kh,*Kl,*Vth,*Vtl;
    cudaGetSymbolAddress((void**)&xh, g_xh);   cudaGetSymbolAddress((void**)&xl, g_xl);
    cudaGetSymbolAddress((void**)&yh, g_yh);   cudaGetSymbolAddress((void**)&yl, g_yl);
    cudaGetSymbolAddress((void**)&Wqh, g_Wqkvh); cudaGetSymbolAddress((void**)&Wql, g_Wqkvl);
    cudaGetSymbolAddress((void**)&Wkh, g_Wkvh);  cudaGetSymbolAddress((void**)&Wkl, g_Wkvl);
    cudaGetSymbolAddress((void**)&Wph, g_Wph);   cudaGetSymbolAddress((void**)&Wpl, g_Wpl);
    cudaGetSymbolAddress((void**)&Obh, g_Obh);   cudaGetSymbolAddress((void**)&Obl, g_Obl);
    cudaGetSymbolAddress((void**)&Qh, g_Qh);     cudaGetSymbolAddress((void**)&Ql, g_Ql);
    cudaGetSymbolAddress((void**)&Kh, g_Kh);     cudaGetSymbolAddress((void**)&Kl, g_Kl);
    cudaGetSymbolAddress((void**)&Vth, g_Vth);   cudaGetSymbolAddress((void**)&Vtl, g_Vtl);

    cudaFuncSetAttribute(mma_gemm_proj, cudaFuncAttributeMaxDynamicSharedMemorySize, MM_SMEM_B);
    cudaFuncSetAttribute(mma_gemm_qkv<0>, cudaFuncAttributeMaxDynamicSharedMemorySize, MM_SMEM_B);
    cudaFuncSetAttribute(mma_gemm_qkv<1>, cudaFuncAttributeMaxDynamicSharedMemorySize, MM_SMEM_B);
    cudaFuncSetAttribute(fused_attn, cudaFuncAttributeMaxDynamicSharedMemorySize, FA_SMEM);

    // 0) split conversions
    auto cvt = [&](const float* s, __nv_bfloat16* h, __nv_bfloat16* l, long long n) {
        cvt_split<<<(int)((n / 4 + 255) / 256), 256>>>(s, h, l, n);
    };
    cvt(x, xh, xl, (long long)Bsz * Nq * Cdim);
    cvt(y, yh, yl, (long long)Bsz * My * Cdim);
    cvt_split_T<<<dim3(3 * Cdim / 32, Cdim / 32), dim3(32, 8)>>>(Wqkv, Wqh, Wql, Cdim, 3 * Cdim);
    cvt_split_T<<<dim3(2 * Cdim / 32, Cdim / 32), dim3(32, 8)>>>(Wkv,  Wkh, Wkl, Cdim, 2 * Cdim);
    cvt_split_T<<<dim3(Cdim / 32,     Cdim / 32), dim3(32, 8)>>>(Wproj, Wph, Wpl, Cdim, Cdim);

    // 1) QKV GEMM + fused RMSNorm/RoPE/split/scatter (Q, Kx, Vx^T)
    mma_gemm_qkv<0><<<dim3(3 * Cdim / 128, Bsz * Nq / 128), 256, MM_SMEM_B>>>(
        xh, xl, Wqh, Wql, pos, qw, kw, Qh, Ql, Kh, Kl, Vth, Vtl);

    // 2) KV GEMM + fused RMSNorm/split/scatter (Ky, Vy^T)
    mma_gemm_qkv<1><<<dim3(2 * Cdim / 128, Bsz * My / 128), 256, MM_SMEM_B>>>(
        yh, yl, Wkh, Wkl, pos, qw, kw, Qh, Ql, Kh, Kl, Vth, Vtl);

    // 3) fused attention -> split-bf16 O in [b][n][h*128]
    fused_attn<<<dim3(Nq / 128, Bsz * Hn), 256, FA_SMEM>>>(
        Qh, Ql, Kh, Kl, Vth, Vtl, ytw, Obh, Obl);

    // 4) out = O @ Wproj + bproj
    mma_gemm_proj<<<dim3(Cdim / 128, Bsz * Nq / 128), 256, MM_SMEM_B>>>(
        Obh, Obl, Wph, Wpl, out, bproj);
}

// round 9
// speedup vs baseline: 1.1573x; 1.1573x over previous
#include <cuda_runtime.h>
#include <cuda_bf16.h>
#include <math.h>
#include <cstdint>

// ---------------- problem constants ----------------
constexpr int Bsz  = 2;
constexpr int Nq   = 2048;
constexpr int My   = 512;
constexpr int Cdim = 1536;
constexpr int Hn   = 12;
constexpr int HDim = 128;          // Cdim / Hn
constexpr int RD   = 64;
constexpr int Sk   = Nq + My;      // 2560
constexpr float EPSV  = 1e-6f;
constexpr float SCALE = 0.08838834764831845f;   // 1/sqrt(128)

// ---------------- scratch (static device arrays; no allocs allowed) ----------------
__device__ float g_qkv [(long long)Bsz * Nq * 3 * Cdim];
__device__ float g_kvr [(long long)Bsz * My * 2 * Cdim];
__device__ float g_Vb  [(long long)Bsz * Hn * Sk * HDim];   // V fp32 [bh][s][d]

// split-bf16 operand buffers
__device__ __nv_bfloat16 g_xh [(long long)Bsz * Nq * Cdim];
__device__ __nv_bfloat16 g_xl [(long long)Bsz * Nq * Cdim];
__device__ __nv_bfloat16 g_yh [(long long)Bsz * My * Cdim];
__device__ __nv_bfloat16 g_yl [(long long)Bsz * My * Cdim];
__device__ __nv_bfloat16 g_Wqkvh[(long long)3 * Cdim * Cdim];
__device__ __nv_bfloat16 g_Wqkvl[(long long)3 * Cdim * Cdim];
__device__ __nv_bfloat16 g_Wkvh [(long long)2 * Cdim * Cdim];
__device__ __nv_bfloat16 g_Wkvl [(long long)2 * Cdim * Cdim];
__device__ __nv_bfloat16 g_Wph  [(long long)Cdim * Cdim];
__device__ __nv_bfloat16 g_Wpl  [(long long)Cdim * Cdim];
__device__ __nv_bfloat16 g_Obh  [(long long)Bsz * Nq * Cdim];
__device__ __nv_bfloat16 g_Obl  [(long long)Bsz * Nq * Cdim];
// attention split operands
__device__ __nv_bfloat16 g_Qh [(long long)Bsz * Hn * Nq * HDim];
__device__ __nv_bfloat16 g_Ql [(long long)Bsz * Hn * Nq * HDim];
__device__ __nv_bfloat16 g_Kh [(long long)Bsz * Hn * Sk * HDim];
__device__ __nv_bfloat16 g_Kl [(long long)Bsz * Hn * Sk * HDim];
__device__ __nv_bfloat16 g_Vth[(long long)Bsz * Hn * HDim * Sk];  // V^T [bh][d][s]
__device__ __nv_bfloat16 g_Vtl[(long long)Bsz * Hn * HDim * Sk];

// ---------------- small PTX helpers (baseline PTX only) ----------------
__device__ __forceinline__ uint32_t smem_u32(const void* p) {
    uint32_t a;
    asm("{ .reg .u64 t; cvta.to.shared.u64 t, %1; cvt.u32.u64 %0, t; }" : "=r"(a) : "l"(p));
    return a;
}
__device__ __forceinline__ void cp16(uint32_t dst, const void* src) {
    asm volatile("cp.async.cg.shared.global [%0], [%1], 16;" :: "r"(dst), "l"(src));
}
#define CP_COMMIT()  asm volatile("cp.async.commit_group;" ::: "memory")
#define CP_WAIT(n)   asm volatile("cp.async.wait_group %0;" :: "n"(n) : "memory")

__device__ __forceinline__ void mma_bf16(float d[4], const uint32_t a[4], const uint32_t b[2]) {
    asm volatile(
        "mma.sync.aligned.m16n8k16.row.col.f32.bf16.bf16.f32 "
        "{%0,%1,%2,%3}, {%4,%5,%6,%7}, {%8,%9}, {%0,%1,%2,%3};"
        : "+f"(d[0]), "+f"(d[1]), "+f"(d[2]), "+f"(d[3])
        : "r"(a[0]), "r"(a[1]), "r"(a[2]), "r"(a[3]), "r"(b[0]), "r"(b[1]));
}
__device__ __forceinline__ void split_write(float v, __nv_bfloat16* h, __nv_bfloat16* l, long long idx) {
    const __nv_bfloat16 hb = __float2bfloat16(v);
    h[idx] = hb;
    l[idx] = __float2bfloat16(v - __bfloat162float(hb));
}

// ---------------- 128x128 split-bf16 HMMA GEMM (KV GEMM; 2 CTAs/SM) ----------------
constexpr int MM_STRIDE_B = 80;
constexpr int MM_ARR_B    = 128 * MM_STRIDE_B;
constexpr int MM_BUF_B    = 4 * MM_ARR_B;
constexpr int MM_SMEM_B   = 2 * MM_BUF_B;   // 81920

__global__ __launch_bounds__(256)
void mma_gemm(const __nv_bfloat16* __restrict__ Ah, const __nv_bfloat16* __restrict__ Al,
              const __nv_bfloat16* __restrict__ Bh, const __nv_bfloat16* __restrict__ Bl,
              float* __restrict__ C, int Kd, int ldc)
{
    extern __shared__ char smem[];
    const uint32_t sbase = smem_u32(smem);

    const int tid  = threadIdx.x;
    const int lane = tid & 31;
    const int wid  = tid >> 5;
    const int row0 = blockIdx.y * 128;
    const int col0 = blockIdx.x * 128;
    const int wm   = (wid >> 2) * 64;
    const int wn   = (wid & 3) * 32;
    const int g    = lane >> 2;
    const int tg   = lane & 3;

    const int s0   = tid * 2;
    const int row_s0 = s0 >> 2,  q_s0 = s0 & 3;
    const int row_s1 = (s0 + 1) >> 2, q_s1 = (s0 + 1) & 3;

    auto stage = [&](int c, int buf) {
        const long long k0 = (long long)c * 32;
        const uint32_t db = sbase + buf * MM_BUF_B;
        {
            const long long ga = (long long)(row0 + row_s0) * Kd + k0 + q_s0 * 8;
            const long long gb = (long long)(col0 + row_s0) * Kd + k0 + q_s0 * 8;
            const uint32_t  so = row_s0 * MM_STRIDE_B + q_s0 * 16;
            cp16(db + 0 * MM_ARR_B + so, Ah + ga);
            cp16(db + 1 * MM_ARR_B + so, Al + ga);
            cp16(db + 2 * MM_ARR_B + so, Bh + gb);
            cp16(db + 3 * MM_ARR_B + so, Bl + gb);
        }
        {
            const long long ga = (long long)(row0 + row_s1) * Kd + k0 + q_s1 * 8;
            const long long gb = (long long)(col0 + row_s1) * Kd + k0 + q_s1 * 8;
            const uint32_t  so = row_s1 * MM_STRIDE_B + q_s1 * 16;
            cp16(db + 0 * MM_ARR_B + so, Ah + ga);
            cp16(db + 1 * MM_ARR_B + so, Al + ga);
            cp16(db + 2 * MM_ARR_B + so, Bh + gb);
            cp16(db + 3 * MM_ARR_B + so, Bl + gb);
        }
    };

    float acc[4][4][4];
    #pragma unroll
    for (int i = 0; i < 4; i++)
        #pragma unroll
        for (int j = 0; j < 4; j++)
            #pragma unroll
            for (int r = 0; r < 4; r++) acc[i][j][r] = 0.f;

    const int nch = Kd / 32;
    stage(0, 0);
    CP_COMMIT();

    for (int c = 0; c < nch; c++) {
        if (c + 1 < nch) { stage(c + 1, (c + 1) & 1); CP_COMMIT(); CP_WAIT(1); }
        else             { CP_WAIT(0); }
        __syncthreads();

        const char* bp = smem + (c & 1) * MM_BUF_B;
        const char* pAh = bp;
        const char* pAl = bp + MM_ARR_B;
        const char* pBh = bp + 2 * MM_ARR_B;
        const char* pBl = bp + 3 * MM_ARR_B;

        #pragma unroll
        for (int kk = 0; kk < 2; kk++) {
            const int cbyte = (kk * 16 + 2 * tg) * 2;
            uint32_t ah[4][4], al[4][4], bh[4][2], bl[4][2];
            #pragma unroll
            for (int mt = 0; mt < 4; mt++) {
                const int r = wm + mt * 16 + g;
                ah[mt][0] = *(const uint32_t*)(pAh + r * MM_STRIDE_B + cbyte);
                ah[mt][1] = *(const uint32_t*)(pAh + (r + 8) * MM_STRIDE_B + cbyte);
                ah[mt][2] = *(const uint32_t*)(pAh + r * MM_STRIDE_B + cbyte + 16);
                ah[mt][3] = *(const uint32_t*)(pAh + (r + 8) * MM_STRIDE_B + cbyte + 16);
                al[mt][0] = *(const uint32_t*)(pAl + r * MM_STRIDE_B + cbyte);
                al[mt][1] = *(const uint32_t*)(pAl + (r + 8) * MM_STRIDE_B + cbyte);
                al[mt][2] = *(const uint32_t*)(pAl + r * MM_STRIDE_B + cbyte + 16);
                al[mt][3] = *(const uint32_t*)(pAl + (r + 8) * MM_STRIDE_B + cbyte + 16);
            }
            #pragma unroll
            for (int nt = 0; nt < 4; nt++) {
                const int n = wn + nt * 8 + g;
                bh[nt][0] = *(const uint32_t*)(pBh + n * MM_STRIDE_B + cbyte);
                bh[nt][1] = *(const uint32_t*)(pBh + n * MM_STRIDE_B + cbyte + 16);
                bl[nt][0] = *(const uint32_t*)(pBl + n * MM_STRIDE_B + cbyte);
                bl[nt][1] = *(const uint32_t*)(pBl + n * MM_STRIDE_B + cbyte + 16);
            }
            #pragma unroll
            for (int mt = 0; mt < 4; mt++)
                #pragma unroll
                for (int nt = 0; nt < 4; nt++) {
                    mma_bf16(acc[mt][nt], ah[mt], bh[nt]);
                    mma_bf16(acc[mt][nt], ah[mt], bl[nt]);
                    mma_bf16(acc[mt][nt], al[mt], bh[nt]);
                }
        }
        __syncthreads();
    }

    #pragma unroll
    for (int nt = 0; nt < 4; nt++) {
        const int col = col0 + wn + nt * 8 + 2 * tg;
        #pragma unroll
        for (int mt = 0; mt < 4; mt++) {
            const int r = row0 + wm + mt * 16 + g;
            float2 v0, v1;
            v0.x = acc[mt][nt][0]; v0.y = acc[mt][nt][1];
            v1.x = acc[mt][nt][2]; v1.y = acc[mt][nt][3];
            *(float2*)(C + (long long)r * ldc + col)       = v0;
            *(float2*)(C + (long long)(r + 8) * ldc + col) = v1;
        }
    }
}

// ---------------- 256x128 split-bf16 HMMA GEMM, 512 threads (QKV + proj) ----------
// 16 warps of 64x32 (acc[4][4][4] per warp -> no spills). 1 CTA/SM, 120KB smem.
constexpr int BG_STRIDE = 80;
constexpr int BG_A_B    = 256 * BG_STRIDE;            // 20480 per A array
constexpr int BG_B_B    = 128 * BG_STRIDE;            // 10240 per B array
constexpr int BG_BUF    = 2 * BG_A_B + 2 * BG_B_B;    // 61440
constexpr int BG_SMEM   = 2 * BG_BUF;                 // 122880

template<bool ADD_BIAS>
__global__ __launch_bounds__(512, 1)
void mma_gemm_big(const __nv_bfloat16* __restrict__ Ah, const __nv_bfloat16* __restrict__ Al,
                  const __nv_bfloat16* __restrict__ Bh, const __nv_bfloat16* __restrict__ Bl,
                  float* __restrict__ C, const float* __restrict__ bias,
                  int Kd, int ldc)
{
    extern __shared__ char smem[];
    const uint32_t sbase = smem_u32(smem);

    const int tid  = threadIdx.x;
    const int lane = tid & 31;
    const int wid  = tid >> 5;            // 0..15
    const int row0 = blockIdx.y * 256;
    const int col0 = blockIdx.x * 128;
    const int wm   = (wid & 3) * 64;      // 0/64/128/192
    const int wn   = (wid >> 2) * 32;     // 0/32/64/96
    const int g    = lane >> 2;
    const int tg   = lane & 3;

    // staging: A has 1024 segs (256 rows x 4), 2 per thread; B has 512 segs, 1 per thread
    const int sA0 = tid * 2;
    const int arow0 = sA0 >> 2,       aq0 = sA0 & 3;
    const int arow1 = (sA0 + 1) >> 2, aq1 = (sA0 + 1) & 3;
    const int brow = tid >> 2;
    const int bq   = tid & 3;

    auto stage = [&](int c, int buf) {
        const long long k0 = (long long)c * 32;
        const uint32_t db = sbase + buf * BG_BUF;
        {
            const long long ga = (long long)(row0 + arow0) * Kd + k0 + aq0 * 8;
            const uint32_t  so = arow0 * BG_STRIDE + aq0 * 16;
            cp16(db + so,          Ah + ga);
            cp16(db + BG_A_B + so, Al + ga);
        }
        {
            const long long ga = (long long)(row0 + arow1) * Kd + k0 + aq1 * 8;
            const uint32_t  so = arow1 * BG_STRIDE + aq1 * 16;
            cp16(db + so,          Ah + ga);
            cp16(db + BG_A_B + so, Al + ga);
        }
        {
            const long long gb = (long long)(col0 + brow) * Kd + k0 + bq * 8;
            const uint32_t  so = brow * BG_STRIDE + bq * 16;
            cp16(db + 2 * BG_A_B + so,          Bh + gb);
            cp16(db + 2 * BG_A_B + BG_B_B + so, Bl + gb);
        }
    };

    float acc[4][4][4];
    #pragma unroll
    for (int i = 0; i < 4; i++)
        #pragma unroll
        for (int j = 0; j < 4; j++)
            #pragma unroll
            for (int r = 0; r < 4; r++) acc[i][j][r] = 0.f;

    const int nch = Kd / 32;
    stage(0, 0);
    CP_COMMIT();

    for (int c = 0; c < nch; c++) {
        if (c + 1 < nch) { stage(c + 1, (c + 1) & 1); CP_COMMIT(); CP_WAIT(1); }
        else             { CP_WAIT(0); }
        __syncthreads();

        const char* bp  = smem + (c & 1) * BG_BUF;
        const char* pAh = bp;
        const char* pAl = bp + BG_A_B;
        const char* pBh = bp + 2 * BG_A_B;
        const char* pBl = bp + 2 * BG_A_B + BG_B_B;

        #pragma unroll
        for (int kk = 0; kk < 2; kk++) {
            const int cbyte = (kk * 16 + 2 * tg) * 2;
            uint32_t ah[4][4], al[4][4], bh[4][2], bl[4][2];
            #pragma unroll
            for (int mt = 0; mt < 4; mt++) {
                const int r = wm + mt * 16 + g;
                ah[mt][0] = *(const uint32_t*)(pAh + r * BG_STRIDE + cbyte);
                ah[mt][1] = *(const uint32_t*)(pAh + (r + 8) * BG_STRIDE + cbyte);
                ah[mt][2] = *(const uint32_t*)(pAh + r * BG_STRIDE + cbyte + 16);
                ah[mt][3] = *(const uint32_t*)(pAh + (r + 8) * BG_STRIDE + cbyte + 16);
                al[mt][0] = *(const uint32_t*)(pAl + r * BG_STRIDE + cbyte);
                al[mt][1] = *(const uint32_t*)(pAl + (r + 8) * BG_STRIDE + cbyte);
                al[mt][2] = *(const uint32_t*)(pAl + r * BG_STRIDE + cbyte + 16);
                al[mt][3] = *(const uint32_t*)(pAl + (r + 8) * BG_STRIDE + cbyte + 16);
            }
            #pragma unroll
            for (int nt = 0; nt < 4; nt++) {
                const int n = wn + nt * 8 + g;
                bh[nt][0] = *(const uint32_t*)(pBh + n * BG_STRIDE + cbyte);
                bh[nt][1] = *(const uint32_t*)(pBh + n * BG_STRIDE + cbyte + 16);
                bl[nt][0] = *(const uint32_t*)(pBl + n * BG_STRIDE + cbyte);
                bl[nt][1] = *(const uint32_t*)(pBl + n * BG_STRIDE + cbyte + 16);
            }
            #pragma unroll
            for (int mt = 0; mt < 4; mt++)
                #pragma unroll
                for (int nt = 0; nt < 4; nt++) {
                    mma_bf16(acc[mt][nt], ah[mt], bh[nt]);
                    mma_bf16(acc[mt][nt], ah[mt], bl[nt]);
                    mma_bf16(acc[mt][nt], al[mt], bh[nt]);
                }
        }
        __syncthreads();
    }

    #pragma unroll
    for (int nt = 0; nt < 4; nt++) {
        const int col = col0 + wn + nt * 8 + 2 * tg;
        float b0 = 0.f, b1 = 0.f;
        if (ADD_BIAS) { b0 = bias[col]; b1 = bias[col + 1]; }
        #pragma unroll
        for (int mt = 0; mt < 4; mt++) {
            const int r = row0 + wm + mt * 16 + g;
            float2 v0, v1;
            v0.x = acc[mt][nt][0] + b0; v0.y = acc[mt][nt][1] + b1;
            v1.x = acc[mt][nt][2] + b0; v1.y = acc[mt][nt][3] + b1;
            *(float2*)(C + (long long)r * ldc + col)       = v0;
            *(float2*)(C + (long long)(r + 8) * ldc + col) = v1;
        }
    }
}

// ---------------- fused attention (R6-proven) ----------------
constexpr int FA_NIT = Sk / 64;
constexpr int FQ   = 0;
constexpr int FQL  = 34816;
constexpr int FK   = 69632;
constexpr int FKHALF = 17408;
constexpr int FKBUF  = 34816;
constexpr int FV   = 139264;
constexpr int FVL  = 157696;
constexpr int FP   = 176128;
constexpr int FPL  = 194560;
constexpr int FRS  = 212992;
constexpr int FYB  = 214016;
constexpr int FA_SMEM = 216064;

__global__ __launch_bounds__(256, 1)
void fused_attn(const __nv_bfloat16* __restrict__ Qh, const __nv_bfloat16* __restrict__ Ql,
                const __nv_bfloat16* __restrict__ Kh, const __nv_bfloat16* __restrict__ Kl,
                const __nv_bfloat16* __restrict__ Vth, const __nv_bfloat16* __restrict__ Vtl,
                const float* __restrict__ ytw,
                __nv_bfloat16* __restrict__ Obh, __nv_bfloat16* __restrict__ Obl)
{
    extern __shared__ char smem[];
    const uint32_t sb = smem_u32(smem);

    const int z  = blockIdx.y;
    const int q0 = blockIdx.x * 128;
    const int b  = z / Hn;
    const int h  = z % Hn;

    const int tid  = threadIdx.x;
    const int lane = tid & 31;
    const int wid  = tid >> 5;
    const int g    = lane >> 2;
    const int tg   = lane & 3;
    const int wm   = (wid >> 1) * 32;
    const int wn   = (wid & 1) * 32;
    const int wn2  = (wid & 1) * 64;

    const __nv_bfloat16* Qhp = Qh + (long long)z * Nq * HDim;
    const __nv_bfloat16* Qlp = Ql + (long long)z * Nq * HDim;
    const __nv_bfloat16* Khp = Kh + (long long)z * Sk * HDim;
    const __nv_bfloat16* Klp = Kl + (long long)z * Sk * HDim;
    const __nv_bfloat16* Vhp = Vth + (long long)z * HDim * Sk;
    const __nv_bfloat16* Vlp = Vtl + (long long)z * HDim * Sk;

    float* sYB = (float*)(smem + FYB);
    sYB[tid]       = logf(fmaxf(ytw[b * My + tid], 1e-4f));
    sYB[tid + 256] = logf(fmaxf(ytw[b * My + tid + 256], 1e-4f));

    #pragma unroll
    for (int j = 0; j < 8; j++) {
        const int id = tid + j * 256, r = id >> 4, c = id & 15;
        cp16(sb + FQ  + r * 272 + c * 16, Qhp + (long long)(q0 + r) * HDim + c * 8);
        cp16(sb + FQL + r * 272 + c * 16, Qlp + (long long)(q0 + r) * HDim + c * 8);
    }
    #pragma unroll
    for (int j = 0; j < 4; j++) {
        const int id = tid + j * 256, r = id >> 4, c = id & 15;
        cp16(sb + FK +          r * 272 + c * 16, Khp + (long long)r * HDim + c * 8);
        cp16(sb + FK + FKHALF + r * 272 + c * 16, Klp + (long long)r * HDim + c * 8);
    }
    CP_COMMIT();

    float oacc[2][8][4];
    #pragma unroll
    for (int i = 0; i < 2; i++)
        #pragma unroll
        for (int j = 0; j < 8; j++)
            #pragma unroll
            for (int r = 0; r < 4; r++) oacc[i][j][r] = 0.f;
    float rowsum[4] = {0.f, 0.f, 0.f, 0.f};

    for (int it = 0; it < FA_NIT; it++) {
        __syncthreads();
        #pragma unroll
        for (int j = 0; j < 4; j++) {
            const int id = tid + j * 256, d = id >> 3, c = id & 7;
            cp16(sb + FV  + d * 144 + c * 16, Vhp + (long long)d * Sk + it * 64 + c * 8);
            cp16(sb + FVL + d * 144 + c * 16, Vlp + (long long)d * Sk + it * 64 + c * 8);
        }
        if (it + 1 < FA_NIT) {
            const int sblk = (it + 1) * 64;
            const uint32_t kb = sb + FK + ((it + 1) & 1) * FKBUF;
            #pragma unroll
            for (int j = 0; j < 4; j++) {
                const int id = tid + j * 256, r = id >> 4, c = id & 15;
                cp16(kb +          r * 272 + c * 16, Khp + (long long)(sblk + r) * HDim + c * 8);
                cp16(kb + FKHALF + r * 272 + c * 16, Klp + (long long)(sblk + r) * HDim + c * 8);
            }
        }
        CP_COMMIT();
        CP_WAIT(1);
        __syncthreads();

        const char* kbp = smem + FK + (it & 1) * FKBUF;
        float sacc[2][4][4];
        #pragma unroll
        for (int i = 0; i < 2; i++)
            #pragma unroll
            for (int j = 0; j < 4; j++)
                #pragma unroll
                for (int r = 0; r < 4; r++) sacc[i][j][r] = 0.f;

        #pragma unroll
        for (int kk = 0; kk < 8; kk++) {
            const int cb = kk * 32 + tg * 4;
            uint32_t qh_[2][4], ql_[2][4], kh_[4][2], kl_[4][2];
            #pragma unroll
            for (int mt = 0; mt < 2; mt++) {
                const char* p = smem + FQ + (wm + mt * 16 + g) * 272 + cb;
                qh_[mt][0] = *(const uint32_t*)(p);
                qh_[mt][1] = *(const uint32_t*)(p + 8 * 272);
                qh_[mt][2] = *(const uint32_t*)(p + 16);
                qh_[mt][3] = *(const uint32_t*)(p + 8 * 272 + 16);
                ql_[mt][0] = *(const uint32_t*)(p + FQL);
                ql_[mt][1] = *(const uint32_t*)(p + FQL + 8 * 272);
                ql_[mt][2] = *(const uint32_t*)(p + FQL + 16);
                ql_[mt][3] = *(const uint32_t*)(p + FQL + 8 * 272 + 16);
            }
            #pragma unroll
            for (int nt = 0; nt < 4; nt++) {
                const char* p = kbp + (wn + nt * 8 + g) * 272 + cb;
                kh_[nt][0] = *(const uint32_t*)(p);
                kh_[nt][1] = *(const uint32_t*)(p + 16);
                kl_[nt][0] = *(const uint32_t*)(p + FKHALF);
                kl_[nt][1] = *(const uint32_t*)(p + FKHALF + 16);
            }
            #pragma unroll
            for (int mt = 0; mt < 2; mt++)
                #pragma unroll
                for (int nt = 0; nt < 4; nt++) {
                    mma_bf16(sacc[mt][nt], qh_[mt], kh_[nt]);
                    mma_bf16(sacc[mt][nt], qh_[mt], kl_[nt]);
                    mma_bf16(sacc[mt][nt], ql_[mt], kh_[nt]);
                }
        }

        #pragma unroll
        for (int mt = 0; mt < 2; mt++) {
            #pragma unroll
            for (int nt = 0; nt < 4; nt++) {
                const int col0 = wn + nt * 8 + 2 * tg;
                const int gc   = it * 64 + col0;
                float b0 = 0.f, b1 = 0.f;
                if (gc >= Nq) { b0 = sYB[gc - Nq]; b1 = sYB[gc - Nq + 1]; }
                const float p0 = __expf(sacc[mt][nt][0] * SCALE + b0);
                const float p1 = __expf(sacc[mt][nt][1] * SCALE + b1);
                const float p2 = __expf(sacc[mt][nt][2] * SCALE + b0);
                const float p3 = __expf(sacc[mt][nt][3] * SCALE + b1);
                rowsum[mt * 2 + 0] += p0 + p1;
                rowsum[mt * 2 + 1] += p2 + p3;
                const int r0 = wm + mt * 16 + g;
                __nv_bfloat162 hv, lv;
                hv.x = __float2bfloat16(p0); hv.y = __float2bfloat16(p1);
                lv.x = __float2bfloat16(p0 - __bfloat162float(hv.x));
                lv.y = __float2bfloat16(p1 - __bfloat162float(hv.y));
                *(__nv_bfloat162*)(smem + FP  + r0 * 144 + col0 * 2) = hv;
                *(__nv_bfloat162*)(smem + FPL + r0 * 144 + col0 * 2) = lv;
                hv.x = __float2bfloat16(p2); hv.y = __float2bfloat16(p3);
                lv.x = __float2bfloat16(p2 - __bfloat162float(hv.x));
                lv.y = __float2bfloat16(p3 - __bfloat162float(hv.y));
                *(__nv_bfloat162*)(smem + FP  + (r0 + 8) * 144 + col0 * 2) = hv;
                *(__nv_bfloat162*)(smem + FPL + (r0 + 8) * 144 + col0 * 2) = lv;
            }
        }

        CP_WAIT(0);
        __syncthreads();

        #pragma unroll
        for (int kk = 0; kk < 4; kk++) {
            const int cb = kk * 32 + tg * 4;
            uint32_t ph_[2][4], pl_[2][4], vh_[8][2], vl_[8][2];
            #pragma unroll
            for (int mt = 0; mt < 2; mt++) {
                const char* p = smem + FP + (wm + mt * 16 + g) * 144 + cb;
                ph_[mt][0] = *(const uint32_t*)(p);
                ph_[mt][1] = *(const uint32_t*)(p + 8 * 144);
                ph_[mt][2] = *(const uint32_t*)(p + 16);
                ph_[mt][3] = *(const uint32_t*)(p + 8 * 144 + 16);
                const char* q = p + (FPL - FP);
                pl_[mt][0] = *(const uint32_t*)(q);
                pl_[mt][1] = *(const uint32_t*)(q + 8 * 144);
                pl_[mt][2] = *(const uint32_t*)(q + 16);
                pl_[mt][3] = *(const uint32_t*)(q + 8 * 144 + 16);
            }
            #pragma unroll
            for (int nt = 0; nt < 8; nt++) {
                const char* p = smem + FV + (wn2 + nt * 8 + g) * 144 + cb;
                vh_[nt][0] = *(const uint32_t*)(p);
                vh_[nt][1] = *(const uint32_t*)(p + 16);
                vl_[nt][0] = *(const uint32_t*)(p + (FVL - FV));
                vl_[nt][1] = *(const uint32_t*)(p + (FVL - FV) + 16);
            }
            #pragma unroll
            for (int mt = 0; mt < 2; mt++)
                #pragma unroll
                for (int nt = 0; nt < 8; nt++) {
                    mma_bf16(oacc[mt][nt], ph_[mt], vh_[nt]);
                    mma_bf16(oacc[mt][nt], ph_[mt], vl_[nt]);
                    mma_bf16(oacc[mt][nt], pl_[mt], vh_[nt]);
                }
        }
    }

    #pragma unroll
    for (int j = 0; j < 4; j++) {
        rowsum[j] += __shfl_xor_sync(0xffffffffu, rowsum[j], 1);
        rowsum[j] += __shfl_xor_sync(0xffffffffu, rowsum[j], 2);
    }
    float* sRS = (float*)(smem + FRS);
    if (tg == 0) {
        sRS[(wid & 1) * 128 + wm + g]      = rowsum[0];
        sRS[(wid & 1) * 128 + wm + g + 8]  = rowsum[1];
        sRS[(wid & 1) * 128 + wm + g + 16] = rowsum[2];
        sRS[(wid & 1) * 128 + wm + g + 24] = rowsum[3];
    }
    __syncthreads();

    #pragma unroll
    for (int mt = 0; mt < 2; mt++) {
        const int r = wm + mt * 16 + g;
        const float inv0 = 1.f / (sRS[r]     + sRS[128 + r]);
        const float inv1 = 1.f / (sRS[r + 8] + sRS[128 + r + 8]);
        #pragma unroll
        for (int nt = 0; nt < 8; nt++) {
            const int col = wn2 + nt * 8 + 2 * tg;
            const long long o0 = ((long long)b * Nq + q0 + r) * Cdim + h * HDim + col;
            const long long o1 = o0 + 8LL * Cdim;
            const float a0 = oacc[mt][nt][0] * inv0, a1 = oacc[mt][nt][1] * inv0;
            const float a2 = oacc[mt][nt][2] * inv1, a3 = oacc[mt][nt][3] * inv1;
            __nv_bfloat162 hv, lv;
            hv.x = __float2bfloat16(a0); hv.y = __float2bfloat16(a1);
            lv.x = __float2bfloat16(a0 - __bfloat162float(hv.x));
            lv.y = __float2bfloat16(a1 - __bfloat162float(hv.y));
            *(__nv_bfloat162*)(Obh + o0) = hv;
            *(__nv_bfloat162*)(Obl + o0) = lv;
            hv.x = __float2bfloat16(a2); hv.y = __float2bfloat16(a3);
            lv.x = __float2bfloat16(a2 - __bfloat162float(hv.x));
            lv.y = __float2bfloat16(a3 - __bfloat162float(hv.y));
            *(__nv_bfloat162*)(Obh + o1) = hv;
            *(__nv_bfloat162*)(Obl + o1) = lv;
        }
    }
}

// ---------------- fp32 -> split bf16 (row-major keep) ----------------
__global__ void cvt_split(const float* __restrict__ src, __nv_bfloat16* __restrict__ h,
                          __nv_bfloat16* __restrict__ l, long long n)
{
    const long long i = ((long long)blockIdx.x * blockDim.x + threadIdx.x) * 4;
    if (i >= n) return;
    const float4 v = *(const float4*)(src + i);
    __nv_bfloat16 hb[4], lb[4];
    const float f[4] = {v.x, v.y, v.z, v.w};
    #pragma unroll
    for (int j = 0; j < 4; j++) {
        hb[j] = __float2bfloat16(f[j]);
        lb[j] = __float2bfloat16(f[j] - __bfloat162float(hb[j]));
    }
    *(uint2*)(h + i) = *(uint2*)hb;
    *(uint2*)(l + i) = *(uint2*)lb;
}

// ---------------- fp32 [K][N] -> split bf16 transposed [N][K] ----------------
__global__ void cvt_split_T(const float* __restrict__ W, __nv_bfloat16* __restrict__ h,
                            __nv_bfloat16* __restrict__ l, int K, int N)
{
    __shared__ float tile[32][33];
    const int k0 = blockIdx.y * 32;
    const int n0 = blockIdx.x * 32;
    const int tx = threadIdx.x;
    const int ty = threadIdx.y;
    #pragma unroll
    for (int i = ty; i < 32; i += 8)
        tile[i][tx] = W[(long long)(k0 + i) * N + n0 + tx];
    __syncthreads();
    #pragma unroll
    for (int i = ty; i < 32; i += 8) {
        const float v = tile[tx][i];
        const __nv_bfloat16 hb = __float2bfloat16(v);
        const __nv_bfloat16 lb = __float2bfloat16(v - __bfloat162float(hb));
        const long long o = (long long)(n0 + i) * K + k0 + tx;
        h[o] = hb; l[o] = lb;
    }
}

// ---------------- V: fp32 [bh][s][d] -> split bf16 transposed [bh][d][s] ----------
__global__ void v_transpose_split(const float* __restrict__ Vb,
                                  __nv_bfloat16* __restrict__ Vth,
                                  __nv_bfloat16* __restrict__ Vtl)
{
    __shared__ float tile[32][33];
    const int z  = blockIdx.z;
    const int ss0 = blockIdx.x * 32;
    const int dd0 = blockIdx.y * 32;
    const int tx = threadIdx.x;
    const int ty = threadIdx.y;
    const long long ib = (long long)z * Sk * HDim;
    const long long ob = (long long)z * HDim * Sk;
    #pragma unroll
    for (int i = ty; i < 32; i += 8)
        tile[i][tx] = Vb[ib + (long long)(ss0 + i) * HDim + dd0 + tx];
    __syncthreads();
    #pragma unroll
    for (int i = ty; i < 32; i += 8) {
        const float v = tile[tx][i];
        const __nv_bfloat16 hb = __float2bfloat16(v);
        const __nv_bfloat16 lb = __float2bfloat16(v - __bfloat162float(hb));
        const long long o = ob + (long long)(dd0 + i) * Sk + ss0 + tx;
        Vth[o] = hb; Vtl[o] = lb;
    }
}

// ---------------- warp reduction helpers ----------------
__device__ __forceinline__ float warpSum(float v) {
    #pragma unroll
    for (int o = 16; o > 0; o >>= 1) v += __shfl_xor_sync(0xffffffffu, v, o);
    return v;
}

// ---------------- QKV postprocess: RMSNorm + RoPE -> split bf16 Q,K; fp32 V ------
__global__ void qkv_post(const float* __restrict__ qkv, const float* __restrict__ pos,
                         const float* __restrict__ qw, const float* __restrict__ kw,
                         __nv_bfloat16* __restrict__ Qh, __nv_bfloat16* __restrict__ Ql,
                         __nv_bfloat16* __restrict__ Kh, __nv_bfloat16* __restrict__ Kl,
                         float* __restrict__ Vb)
{
    const int idx = blockIdx.x;
    const int h  = idx % Hn;
    const int bn = idx / Hn;
    const int n  = bn % Nq;
    const int b  = bn / Nq;
    const int d  = threadIdx.x;

    const float* row = qkv + (long long)bn * (3 * Cdim);
    const float qv = row[h * HDim + d];
    const float kv = row[Cdim + h * HDim + d];
    const float vv = row[2 * Cdim + h * HDim + d];

    __shared__ float sred[8];
    __shared__ float qs[HDim], ks[HDim];

    const float sq = warpSum(qv * qv);
    const float sk = warpSum(kv * kv);
    const int lane = d & 31, w = d >> 5;
    if (lane == 0) { sred[w] = sq; sred[4 + w] = sk; }
    __syncthreads();
    const float sumq = sred[0] + sred[1] + sred[2] + sred[3];
    const float sumk = sred[4] + sred[5] + sred[6] + sred[7];
    const float rq = rsqrtf(sumq * (1.0f / HDim) + EPSV);
    const float rk = rsqrtf(sumk * (1.0f / HDim) + EPSV);
    const float qn = qw[d] * qv * rq;
    const float kn = kw[d] * kv * rk;
    qs[d] = qn; ks[d] = kn;
    __syncthreads();

    float qo = qn, ko = kn;
    if (d < RD) {
        const int j = d & 31;
        const float c = pos[(n * 32 + j) * 2 + 0];
        const float s = pos[(n * 32 + j) * 2 + 1];
        if (d < RD / 2) { qo = qs[d] * c - qs[d + 32] * s;  ko = ks[d] * c - ks[d + 32] * s; }
        else            { qo = qs[d - 32] * s + qs[d] * c;  ko = ks[d - 32] * s + ks[d] * c; }
    }
    const long long qi = (((long long)(b * Hn + h)) * Nq + n) * HDim + d;
    const long long ki = (((long long)(b * Hn + h)) * Sk + n) * HDim + d;
    split_write(qo, Qh, Ql, qi);
    split_write(ko, Kh, Kl, ki);
    Vb[ki] = vv;
}

// ---------------- KV(y) postprocess ----------------
__global__ void kv_post(const float* __restrict__ kvr, const float* __restrict__ kw,
                        __nv_bfloat16* __restrict__ Kh, __nv_bfloat16* __restrict__ Kl,
                        float* __restrict__ Vb)
{
    const int idx = blockIdx.x;
    const int h  = idx % Hn;
    const int bm = idx / Hn;
    const int m  = bm % My;
    const int b  = bm / My;
    const int d  = threadIdx.x;

    const float* row = kvr + (long long)bm * (2 * Cdim);
    const float kv = row[h * HDim + d];
    const float vv = row[Cdim + h * HDim + d];

    __shared__ float sred[4];
    const float sk = warpSum(kv * kv);
    if ((d & 31) == 0) sred[d >> 5] = sk;
    __syncthreads();
    const float sumk = sred[0] + sred[1] + sred[2] + sred[3];
    const float rk = rsqrtf(sumk * (1.0f / HDim) + EPSV);
    const float kn = kw[d] * kv * rk;

    const long long ki = (((long long)(b * Hn + h)) * Sk + (Nq + m)) * HDim + d;
    split_write(kn, Kh, Kl, ki);
    Vb[ki] = vv;
}

// ---------------- launch ----------------
extern "C" void kernel_launch(void* const* d_in, const int* in_sizes, int n_in,
                              void* d_out, int out_size)
{
    const float* x    = (const float*)d_in[0];
    const float* y    = (const float*)d_in[1];
    const float* pos  = (const float*)d_in[2];
    const float* ytw  = (const float*)d_in[3];
    const float* Wqkv = (const float*)d_in[4];
    const float* Wkv  = (const float*)d_in[5];
    const float* qw   = (const float*)d_in[6];
    const float* kw   = (const float*)d_in[7];
    const float* Wproj= (const float*)d_in[8];
    const float* bproj= (const float*)d_in[9];
    float* out = (float*)d_out;

    float *qkv, *kvr, *Vb;
    cudaGetSymbolAddress((void**)&qkv, g_qkv);
    cudaGetSymbolAddress((void**)&kvr, g_kvr);
    cudaGetSymbolAddress((void**)&Vb,  g_Vb);

    __nv_bfloat16 *xh,*xl,*yh,*yl,*Wqh,*Wql,*Wkh,*Wkl,*Wph,*Wpl,*Obh,*Obl;
    __nv_bfloat16 *Qh,*Ql,*Kh,*Kl,*Vth,*Vtl;
    cudaGetSymbolAddress((void**)&xh, g_xh);   cudaGetSymbolAddress((void**)&xl, g_xl);
    cudaGetSymbolAddress((void**)&yh, g_yh);   cudaGetSymbolAddress((void**)&yl, g_yl);
    cudaGetSymbolAddress((void**)&Wqh, g_Wqkvh); cudaGetSymbolAddress((void**)&Wql, g_Wqkvl);
    cudaGetSymbolAddress((void**)&Wkh, g_Wkvh);  cudaGetSymbolAddress((void**)&Wkl, g_Wkvl);
    cudaGetSymbolAddress((void**)&Wph, g_Wph);   cudaGetSymbolAddress((void**)&Wpl, g_Wpl);
    cudaGetSymbolAddress((void**)&Obh, g_Obh);   cudaGetSymbolAddress((void**)&Obl, g_Obl);
    cudaGetSymbolAddress((void**)&Qh, g_Qh);     cudaGetSymbolAddress((void**)&Ql, g_Ql);
    cudaGetSymbolAddress((void**)&Kh, g_Kh);     cudaGetSymbolAddress((void**)&Kl, g_Kl);
    cudaGetSymbolAddress((void**)&Vth, g_Vth);   cudaGetSymbolAddress((void**)&Vtl, g_Vtl);

    cudaFuncSetAttribute(mma_gemm, cudaFuncAttributeMaxDynamicSharedMemorySize, MM_SMEM_B);
    cudaFuncSetAttribute(mma_gemm_big<false>, cudaFuncAttributeMaxDynamicSharedMemorySize, BG_SMEM);
    cudaFuncSetAttribute(mma_gemm_big<true>,  cudaFuncAttributeMaxDynamicSharedMemorySize, BG_SMEM);
    cudaFuncSetAttribute(fused_attn, cudaFuncAttributeMaxDynamicSharedMemorySize, FA_SMEM);

    // 0) split conversions
    auto cvt = [&](const float* s, __nv_bfloat16* h, __nv_bfloat16* l, long long n) {
        cvt_split<<<(int)((n / 4 + 255) / 256), 256>>>(s, h, l, n);
    };
    cvt(x, xh, xl, (long long)Bsz * Nq * Cdim);
    cvt(y, yh, yl, (long long)Bsz * My * Cdim);
    cvt_split_T<<<dim3(3 * Cdim / 32, Cdim / 32), dim3(32, 8)>>>(Wqkv, Wqh, Wql, Cdim, 3 * Cdim);
    cvt_split_T<<<dim3(2 * Cdim / 32, Cdim / 32), dim3(32, 8)>>>(Wkv,  Wkh, Wkl, Cdim, 2 * Cdim);
    cvt_split_T<<<dim3(Cdim / 32,     Cdim / 32), dim3(32, 8)>>>(Wproj, Wph, Wpl, Cdim, Cdim);

    // 1) QKV = x @ Wqkv   (256x128 tiles, 512 threads)
    mma_gemm_big<false><<<dim3(3 * Cdim / 128, Bsz * Nq / 256), 512, BG_SMEM>>>(
        xh, xl, Wqh, Wql, qkv, nullptr, Cdim, 3 * Cdim);

    // 2) KV = y @ Wkv     (128x128 tiles)
    mma_gemm<<<dim3(2 * Cdim / 128, Bsz * My / 128), 256, MM_SMEM_B>>>(
        yh, yl, Wkh, Wkl, kvr, Cdim, 2 * Cdim);

    // 3) postprocess
    qkv_post<<<Bsz * Nq * Hn, HDim>>>(qkv, pos, qw, kw, Qh, Ql, Kh, Kl, Vb);
    kv_post<<<Bsz * My * Hn, HDim>>>(kvr, kw, Kh, Kl, Vb);
    v_transpose_split<<<dim3(Sk / 32, HDim / 32, Bsz * Hn), dim3(32, 8)>>>(Vb, Vth, Vtl);

    // 4-6) fused attention -> split-bf16 O in [b][n][h*128]
    fused_attn<<<dim3(Nq / 128, Bsz * Hn), 256, FA_SMEM>>>(
        Qh, Ql, Kh, Kl, Vth, Vtl, ytw, Obh, Obl);

    // 7) out = O @ Wproj + bproj   (256x128 tiles, 512 threads)
    mma_gemm_big<true><<<dim3(Cdim / 128, Bsz * Nq / 256), 512, BG_SMEM>>>(
        Obh, Obl, Wph, Wpl, out, bproj, Cdim, Cdim);
}

// round 10
// speedup vs baseline: 1.2440x; 1.0749x over previous
#include <cuda_runtime.h>
#include <cuda_bf16.h>
#include <math.h>
#include <cstdint>

// ---------------- problem constants ----------------
constexpr int Bsz  = 2;
constexpr int Nq   = 2048;
constexpr int My   = 512;
constexpr int Cdim = 1536;
constexpr int Hn   = 12;
constexpr int HDim = 128;          // Cdim / Hn
constexpr int RD   = 64;
constexpr int Sk   = Nq + My;      // 2560
constexpr float EPSV  = 1e-6f;
constexpr float SCALE = 0.08838834764831845f;   // 1/sqrt(128)

// ---------------- scratch (static device arrays; no allocs allowed) ----------------
__device__ float g_qkv [(long long)Bsz * Nq * 3 * Cdim];
__device__ float g_kvr [(long long)Bsz * My * 2 * Cdim];
__device__ float g_Vb  [(long long)Bsz * Hn * Sk * HDim];   // V fp32 [bh][s][d]

// split-bf16 operand buffers
__device__ __nv_bfloat16 g_xh [(long long)Bsz * Nq * Cdim];
__device__ __nv_bfloat16 g_xl [(long long)Bsz * Nq * Cdim];
__device__ __nv_bfloat16 g_yh [(long long)Bsz * My * Cdim];
__device__ __nv_bfloat16 g_yl [(long long)Bsz * My * Cdim];
__device__ __nv_bfloat16 g_Wqkvh[(long long)3 * Cdim * Cdim];
__device__ __nv_bfloat16 g_Wqkvl[(long long)3 * Cdim * Cdim];
__device__ __nv_bfloat16 g_Wkvh [(long long)2 * Cdim * Cdim];
__device__ __nv_bfloat16 g_Wkvl [(long long)2 * Cdim * Cdim];
__device__ __nv_bfloat16 g_Wph  [(long long)Cdim * Cdim];
__device__ __nv_bfloat16 g_Wpl  [(long long)Cdim * Cdim];
__device__ __nv_bfloat16 g_Obh  [(long long)Bsz * Nq * Cdim];
__device__ __nv_bfloat16 g_Obl  [(long long)Bsz * Nq * Cdim];
// attention split operands
__device__ __nv_bfloat16 g_Qh [(long long)Bsz * Hn * Nq * HDim];
__device__ __nv_bfloat16 g_Ql [(long long)Bsz * Hn * Nq * HDim];
__device__ __nv_bfloat16 g_Kh [(long long)Bsz * Hn * Sk * HDim];
__device__ __nv_bfloat16 g_Kl [(long long)Bsz * Hn * Sk * HDim];
__device__ __nv_bfloat16 g_Vth[(long long)Bsz * Hn * HDim * Sk];  // V^T [bh][d][s]
__device__ __nv_bfloat16 g_Vtl[(long long)Bsz * Hn * HDim * Sk];

// ---------------- small PTX helpers (baseline PTX only) ----------------
__device__ __forceinline__ uint32_t smem_u32(const void* p) {
    uint32_t a;
    asm("{ .reg .u64 t; cvta.to.shared.u64 t, %1; cvt.u32.u64 %0, t; }" : "=r"(a) : "l"(p));
    return a;
}
__device__ __forceinline__ void cp16(uint32_t dst, const void* src) {
    asm volatile("cp.async.cg.shared.global [%0], [%1], 16;" :: "r"(dst), "l"(src));
}
#define CP_COMMIT()  asm volatile("cp.async.commit_group;" ::: "memory")
#define CP_WAIT(n)   asm volatile("cp.async.wait_group %0;" :: "n"(n) : "memory")

__device__ __forceinline__ void mma_bf16(float d[4], const uint32_t a[4], const uint32_t b[2]) {
    asm volatile(
        "mma.sync.aligned.m16n8k16.row.col.f32.bf16.bf16.f32 "
        "{%0,%1,%2,%3}, {%4,%5,%6,%7}, {%8,%9}, {%0,%1,%2,%3};"
        : "+f"(d[0]), "+f"(d[1]), "+f"(d[2]), "+f"(d[3])
        : "r"(a[0]), "r"(a[1]), "r"(a[2]), "r"(a[3]), "r"(b[0]), "r"(b[1]));
}
__device__ __forceinline__ void split_write(float v, __nv_bfloat16* h, __nv_bfloat16* l, long long idx) {
    const __nv_bfloat16 hb = __float2bfloat16(v);
    h[idx] = hb;
    l[idx] = __float2bfloat16(v - __bfloat162float(hb));
}
__device__ __forceinline__ uint32_t pack_bf2(float a, float b) {
    __nv_bfloat162 v; v.x = __float2bfloat16(a); v.y = __float2bfloat16(b);
    return *(uint32_t*)&v;
}

// ---------------- 128x128 split-bf16 HMMA GEMM (all weight GEMMs; 2 CTAs/SM) -------
constexpr int MM_STRIDE_B = 80;
constexpr int MM_ARR_B    = 128 * MM_STRIDE_B;
constexpr int MM_BUF_B    = 4 * MM_ARR_B;
constexpr int MM_SMEM_B   = 2 * MM_BUF_B;   // 81920

template<bool ADD_BIAS>
__global__ __launch_bounds__(256)
void mma_gemm(const __nv_bfloat16* __restrict__ Ah, const __nv_bfloat16* __restrict__ Al,
              const __nv_bfloat16* __restrict__ Bh, const __nv_bfloat16* __restrict__ Bl,
              float* __restrict__ C, const float* __restrict__ bias,
              int Kd, int ldc)
{
    extern __shared__ char smem[];
    const uint32_t sbase = smem_u32(smem);

    const int tid  = threadIdx.x;
    const int lane = tid & 31;
    const int wid  = tid >> 5;
    const int row0 = blockIdx.y * 128;
    const int col0 = blockIdx.x * 128;
    const int wm   = (wid >> 2) * 64;
    const int wn   = (wid & 3) * 32;
    const int g    = lane >> 2;
    const int tg   = lane & 3;

    const int s0   = tid * 2;
    const int row_s0 = s0 >> 2,  q_s0 = s0 & 3;
    const int row_s1 = (s0 + 1) >> 2, q_s1 = (s0 + 1) & 3;

    auto stage = [&](int c, int buf) {
        const long long k0 = (long long)c * 32;
        const uint32_t db = sbase + buf * MM_BUF_B;
        {
            const long long ga = (long long)(row0 + row_s0) * Kd + k0 + q_s0 * 8;
            const long long gb = (long long)(col0 + row_s0) * Kd + k0 + q_s0 * 8;
            const uint32_t  so = row_s0 * MM_STRIDE_B + q_s0 * 16;
            cp16(db + 0 * MM_ARR_B + so, Ah + ga);
            cp16(db + 1 * MM_ARR_B + so, Al + ga);
            cp16(db + 2 * MM_ARR_B + so, Bh + gb);
            cp16(db + 3 * MM_ARR_B + so, Bl + gb);
        }
        {
            const long long ga = (long long)(row0 + row_s1) * Kd + k0 + q_s1 * 8;
            const long long gb = (long long)(col0 + row_s1) * Kd + k0 + q_s1 * 8;
            const uint32_t  so = row_s1 * MM_STRIDE_B + q_s1 * 16;
            cp16(db + 0 * MM_ARR_B + so, Ah + ga);
            cp16(db + 1 * MM_ARR_B + so, Al + ga);
            cp16(db + 2 * MM_ARR_B + so, Bh + gb);
            cp16(db + 3 * MM_ARR_B + so, Bl + gb);
        }
    };

    float acc[4][4][4];
    #pragma unroll
    for (int i = 0; i < 4; i++)
        #pragma unroll
        for (int j = 0; j < 4; j++)
            #pragma unroll
            for (int r = 0; r < 4; r++) acc[i][j][r] = 0.f;

    const int nch = Kd / 32;
    stage(0, 0);
    CP_COMMIT();

    for (int c = 0; c < nch; c++) {
        if (c + 1 < nch) { stage(c + 1, (c + 1) & 1); CP_COMMIT(); CP_WAIT(1); }
        else             { CP_WAIT(0); }
        __syncthreads();

        const char* bp = smem + (c & 1) * MM_BUF_B;
        const char* pAh = bp;
        const char* pAl = bp + MM_ARR_B;
        const char* pBh = bp + 2 * MM_ARR_B;
        const char* pBl = bp + 3 * MM_ARR_B;

        #pragma unroll
        for (int kk = 0; kk < 2; kk++) {
            const int cbyte = (kk * 16 + 2 * tg) * 2;
            uint32_t ah[4][4], al[4][4], bh[4][2], bl[4][2];
            #pragma unroll
            for (int mt = 0; mt < 4; mt++) {
                const int r = wm + mt * 16 + g;
                ah[mt][0] = *(const uint32_t*)(pAh + r * MM_STRIDE_B + cbyte);
                ah[mt][1] = *(const uint32_t*)(pAh + (r + 8) * MM_STRIDE_B + cbyte);
                ah[mt][2] = *(const uint32_t*)(pAh + r * MM_STRIDE_B + cbyte + 16);
                ah[mt][3] = *(const uint32_t*)(pAh + (r + 8) * MM_STRIDE_B + cbyte + 16);
                al[mt][0] = *(const uint32_t*)(pAl + r * MM_STRIDE_B + cbyte);
                al[mt][1] = *(const uint32_t*)(pAl + (r + 8) * MM_STRIDE_B + cbyte);
                al[mt][2] = *(const uint32_t*)(pAl + r * MM_STRIDE_B + cbyte + 16);
                al[mt][3] = *(const uint32_t*)(pAl + (r + 8) * MM_STRIDE_B + cbyte + 16);
            }
            #pragma unroll
            for (int nt = 0; nt < 4; nt++) {
                const int n = wn + nt * 8 + g;
                bh[nt][0] = *(const uint32_t*)(pBh + n * MM_STRIDE_B + cbyte);
                bh[nt][1] = *(const uint32_t*)(pBh + n * MM_STRIDE_B + cbyte + 16);
                bl[nt][0] = *(const uint32_t*)(pBl + n * MM_STRIDE_B + cbyte);
                bl[nt][1] = *(const uint32_t*)(pBl + n * MM_STRIDE_B + cbyte + 16);
            }
            #pragma unroll
            for (int mt = 0; mt < 4; mt++)
                #pragma unroll
                for (int nt = 0; nt < 4; nt++) {
                    mma_bf16(acc[mt][nt], ah[mt], bh[nt]);
                    mma_bf16(acc[mt][nt], ah[mt], bl[nt]);
                    mma_bf16(acc[mt][nt], al[mt], bh[nt]);
                }
        }
        __syncthreads();
    }

    #pragma unroll
    for (int nt = 0; nt < 4; nt++) {
        const int col = col0 + wn + nt * 8 + 2 * tg;
        float b0 = 0.f, b1 = 0.f;
        if (ADD_BIAS) { b0 = bias[col]; b1 = bias[col + 1]; }
        #pragma unroll
        for (int mt = 0; mt < 4; mt++) {
            const int r = row0 + wm + mt * 16 + g;
            float2 v0, v1;
            v0.x = acc[mt][nt][0] + b0; v0.y = acc[mt][nt][1] + b1;
            v1.x = acc[mt][nt][2] + b0; v1.y = acc[mt][nt][3] + b1;
            *(float2*)(C + (long long)r * ldc + col)       = v0;
            *(float2*)(C + (long long)(r + 8) * ldc + col) = v1;
        }
    }
}

// ---------------- fused attention v2: register-resident P, 2 CTAs/SM ----------------
// Block = 128 threads (4 warps); q-tile 64; warp owns 16 q-rows x all 64 key-cols.
// S accumulator fragments are converted in-registers to PV A-fragments (hi+lo).
constexpr int FA_NIT = Sk / 64;                 // 40
constexpr int F2_QH = 0;                         // Q hi: 64 x 272B
constexpr int F2_QL = 17408;
constexpr int F2_KH = 34816;                     // K hi: 64 x 272B (single buffer)
constexpr int F2_KL = 52224;
constexpr int F2_VH = 69632;                     // V^T hi: 128 x 144B
constexpr int F2_VL = 88064;
constexpr int F2_YB = 106496;                    // yb: 512 floats
constexpr int FA_SMEM = 108544;

__global__ __launch_bounds__(128, 2)
void fused_attn(const __nv_bfloat16* __restrict__ Qh, const __nv_bfloat16* __restrict__ Ql,
                const __nv_bfloat16* __restrict__ Kh, const __nv_bfloat16* __restrict__ Kl,
                const __nv_bfloat16* __restrict__ Vth, const __nv_bfloat16* __restrict__ Vtl,
                const float* __restrict__ ytw,
                __nv_bfloat16* __restrict__ Obh, __nv_bfloat16* __restrict__ Obl)
{
    extern __shared__ char smem[];
    const uint32_t sb = smem_u32(smem);

    const int z  = blockIdx.y;
    const int q0 = blockIdx.x * 64;
    const int b  = z / Hn;
    const int h  = z % Hn;

    const int tid  = threadIdx.x;
    const int lane = tid & 31;
    const int wid  = tid >> 5;            // 0..3
    const int g    = lane >> 2;
    const int tg   = lane & 3;
    const int wm   = wid * 16;            // warp's q-row base

    const __nv_bfloat16* Qhp = Qh + (long long)z * Nq * HDim;
    const __nv_bfloat16* Qlp = Ql + (long long)z * Nq * HDim;
    const __nv_bfloat16* Khp = Kh + (long long)z * Sk * HDim;
    const __nv_bfloat16* Klp = Kl + (long long)z * Sk * HDim;
    const __nv_bfloat16* Vhp = Vth + (long long)z * HDim * Sk;
    const __nv_bfloat16* Vlp = Vtl + (long long)z * HDim * Sk;

    // y bias
    float* sYB = (float*)(smem + F2_YB);
    #pragma unroll
    for (int j = 0; j < 4; j++) {
        const int i = tid + j * 128;
        sYB[i] = logf(fmaxf(ytw[b * My + i], 1e-4f));
    }

    // preload Q (held for whole kernel): 64 rows x 16 segs, hi+lo (8+8 per thread)
    #pragma unroll
    for (int j = 0; j < 8; j++) {
        const int id = tid + j * 128, r = id >> 4, c = id & 15;
        cp16(sb + F2_QH + r * 272 + c * 16, Qhp + (long long)(q0 + r) * HDim + c * 8);
        cp16(sb + F2_QL + r * 272 + c * 16, Qlp + (long long)(q0 + r) * HDim + c * 8);
    }
    CP_COMMIT();

    float oacc[16][4];
    #pragma unroll
    for (int i = 0; i < 16; i++)
        #pragma unroll
        for (int r = 0; r < 4; r++) oacc[i][r] = 0.f;
    float rowsum0 = 0.f, rowsum1 = 0.f;

    for (int it = 0; it < FA_NIT; it++) {
        __syncthreads();                   // prev iteration done with K/V buffers

        // stage K(it): 64 rows x 16 segs hi+lo
        #pragma unroll
        for (int j = 0; j < 8; j++) {
            const int id = tid + j * 128, r = id >> 4, c = id & 15;
            cp16(sb + F2_KH + r * 272 + c * 16, Khp + (long long)(it * 64 + r) * HDim + c * 8);
            cp16(sb + F2_KL + r * 272 + c * 16, Klp + (long long)(it * 64 + r) * HDim + c * 8);
        }
        // stage V(it): 128 d-rows x 8 segs hi+lo
        #pragma unroll
        for (int j = 0; j < 8; j++) {
            const int id = tid + j * 128, d = id >> 3, c = id & 7;
            cp16(sb + F2_VH + d * 144 + c * 16, Vhp + (long long)d * Sk + it * 64 + c * 8);
            cp16(sb + F2_VL + d * 144 + c * 16, Vlp + (long long)d * Sk + it * 64 + c * 8);
        }
        CP_COMMIT();
        CP_WAIT(0);                        // K, V (and Q on it=0) ready
        __syncthreads();

        // ---- S phase: S[16 x 64] = Q K^T (split, 3 products) ----
        float sacc[8][4];
        #pragma unroll
        for (int i = 0; i < 8; i++)
            #pragma unroll
            for (int r = 0; r < 4; r++) sacc[i][r] = 0.f;

        #pragma unroll
        for (int kk = 0; kk < 8; kk++) {
            const int cb = kk * 32 + tg * 4;
            uint32_t qh_[4], ql_[4], kh_[8][2], kl_[8][2];
            {
                const char* p = smem + F2_QH + (wm + g) * 272 + cb;
                qh_[0] = *(const uint32_t*)(p);
                qh_[1] = *(const uint32_t*)(p + 8 * 272);
                qh_[2] = *(const uint32_t*)(p + 16);
                qh_[3] = *(const uint32_t*)(p + 8 * 272 + 16);
                const char* q = p + (F2_QL - F2_QH);
                ql_[0] = *(const uint32_t*)(q);
                ql_[1] = *(const uint32_t*)(q + 8 * 272);
                ql_[2] = *(const uint32_t*)(q + 16);
                ql_[3] = *(const uint32_t*)(q + 8 * 272 + 16);
            }
            #pragma unroll
            for (int nt = 0; nt < 8; nt++) {
                const char* p = smem + F2_KH + (nt * 8 + g) * 272 + cb;
                kh_[nt][0] = *(const uint32_t*)(p);
                kh_[nt][1] = *(const uint32_t*)(p + 16);
                kl_[nt][0] = *(const uint32_t*)(p + (F2_KL - F2_KH));
                kl_[nt][1] = *(const uint32_t*)(p + (F2_KL - F2_KH) + 16);
            }
            #pragma unroll
            for (int nt = 0; nt < 8; nt++) {
                mma_bf16(sacc[nt], qh_, kh_[nt]);
                mma_bf16(sacc[nt], qh_, kl_[nt]);
                mma_bf16(sacc[nt], ql_, kh_[nt]);
            }
        }

        // ---- exp (+scale +bias) -> PV A-fragments in registers (hi+lo) ----
        uint32_t ph_[4][4], pl_[4][4];
        #pragma unroll
        for (int nt = 0; nt < 8; nt++) {
            const int col0 = nt * 8 + 2 * tg;
            const int gc   = it * 64 + col0;
            float b0 = 0.f, b1 = 0.f;
            if (gc >= Nq) { b0 = sYB[gc - Nq]; b1 = sYB[gc - Nq + 1]; }
            const float p0 = __expf(sacc[nt][0] * SCALE + b0);
            const float p1 = __expf(sacc[nt][1] * SCALE + b1);
            const float p2 = __expf(sacc[nt][2] * SCALE + b0);
            const float p3 = __expf(sacc[nt][3] * SCALE + b1);
            rowsum0 += p0 + p1;
            rowsum1 += p2 + p3;
            const int j  = nt >> 1;
            const int rb = (nt & 1) * 2;
            const uint32_t h01 = pack_bf2(p0, p1);
            const uint32_t h23 = pack_bf2(p2, p3);
            ph_[j][rb + 0] = h01;
            ph_[j][rb + 1] = h23;
            const __nv_bfloat162 hb01 = *(const __nv_bfloat162*)&h01;
            const __nv_bfloat162 hb23 = *(const __nv_bfloat162*)&h23;
            pl_[j][rb + 0] = pack_bf2(p0 - __bfloat162float(hb01.x), p1 - __bfloat162float(hb01.y));
            pl_[j][rb + 1] = pack_bf2(p2 - __bfloat162float(hb23.x), p3 - __bfloat162float(hb23.y));
        }

        // ---- PV phase: O[16 x 128] += P V (split, 3 products) ----
        #pragma unroll
        for (int j = 0; j < 4; j++) {
            const int cb = j * 32 + tg * 4;
            #pragma unroll
            for (int nt = 0; nt < 16; nt++) {
                uint32_t vh_[2], vl_[2];
                const char* p = smem + F2_VH + (nt * 8 + g) * 144 + cb;
                vh_[0] = *(const uint32_t*)(p);
                vh_[1] = *(const uint32_t*)(p + 16);
                vl_[0] = *(const uint32_t*)(p + (F2_VL - F2_VH));
                vl_[1] = *(const uint32_t*)(p + (F2_VL - F2_VH) + 16);
                mma_bf16(oacc[nt], ph_[j], vh_);
                mma_bf16(oacc[nt], ph_[j], vl_);
                mma_bf16(oacc[nt], pl_[j], vh_);
            }
        }
    }

    // ---- rowsum reduce within tg quad (warp owns full rows) ----
    rowsum0 += __shfl_xor_sync(0xffffffffu, rowsum0, 1);
    rowsum0 += __shfl_xor_sync(0xffffffffu, rowsum0, 2);
    rowsum1 += __shfl_xor_sync(0xffffffffu, rowsum1, 1);
    rowsum1 += __shfl_xor_sync(0xffffffffu, rowsum1, 2);
    const float inv0 = 1.f / rowsum0;
    const float inv1 = 1.f / rowsum1;

    // ---- epilogue: normalize, split-bf16 write into [b][n][h*128 + d] ----
    const int r = wm + g;
    #pragma unroll
    for (int nt = 0; nt < 16; nt++) {
        const int col = nt * 8 + 2 * tg;
        const long long o0 = ((long long)b * Nq + q0 + r) * Cdim + h * HDim + col;
        const long long o1 = o0 + 8LL * Cdim;
        const float a0 = oacc[nt][0] * inv0, a1 = oacc[nt][1] * inv0;
        const float a2 = oacc[nt][2] * inv1, a3 = oacc[nt][3] * inv1;
        __nv_bfloat162 hv, lv;
        hv.x = __float2bfloat16(a0); hv.y = __float2bfloat16(a1);
        lv.x = __float2bfloat16(a0 - __bfloat162float(hv.x));
        lv.y = __float2bfloat16(a1 - __bfloat162float(hv.y));
        *(__nv_bfloat162*)(Obh + o0) = hv;
        *(__nv_bfloat162*)(Obl + o0) = lv;
        hv.x = __float2bfloat16(a2); hv.y = __float2bfloat16(a3);
        lv.x = __float2bfloat16(a2 - __bfloat162float(hv.x));
        lv.y = __float2bfloat16(a3 - __bfloat162float(hv.y));
        *(__nv_bfloat162*)(Obh + o1) = hv;
        *(__nv_bfloat162*)(Obl + o1) = lv;
    }
}

// ---------------- fp32 -> split bf16 (row-major keep) ----------------
__global__ void cvt_split(const float* __restrict__ src, __nv_bfloat16* __restrict__ h,
                          __nv_bfloat16* __restrict__ l, long long n)
{
    const long long i = ((long long)blockIdx.x * blockDim.x + threadIdx.x) * 4;
    if (i >= n) return;
    const float4 v = *(const float4*)(src + i);
    __nv_bfloat16 hb[4], lb[4];
    const float f[4] = {v.x, v.y, v.z, v.w};
    #pragma unroll
    for (int j = 0; j < 4; j++) {
        hb[j] = __float2bfloat16(f[j]);
        lb[j] = __float2bfloat16(f[j] - __bfloat162float(hb[j]));
    }
    *(uint2*)(h + i) = *(uint2*)hb;
    *(uint2*)(l + i) = *(uint2*)lb;
}

// ---------------- fp32 [K][N] -> split bf16 transposed [N][K] ----------------
__global__ void cvt_split_T(const float* __restrict__ W, __nv_bfloat16* __restrict__ h,
                            __nv_bfloat16* __restrict__ l, int K, int N)
{
    __shared__ float tile[32][33];
    const int k0 = blockIdx.y * 32;
    const int n0 = blockIdx.x * 32;
    const int tx = threadIdx.x;
    const int ty = threadIdx.y;
    #pragma unroll
    for (int i = ty; i < 32; i += 8)
        tile[i][tx] = W[(long long)(k0 + i) * N + n0 + tx];
    __syncthreads();
    #pragma unroll
    for (int i = ty; i < 32; i += 8) {
        const float v = tile[tx][i];
        const __nv_bfloat16 hb = __float2bfloat16(v);
        const __nv_bfloat16 lb = __float2bfloat16(v - __bfloat162float(hb));
        const long long o = (long long)(n0 + i) * K + k0 + tx;
        h[o] = hb; l[o] = lb;
    }
}

// ---------------- V: fp32 [bh][s][d] -> split bf16 transposed [bh][d][s] ----------
__global__ void v_transpose_split(const float* __restrict__ Vb,
                                  __nv_bfloat16* __restrict__ Vth,
                                  __nv_bfloat16* __restrict__ Vtl)
{
    __shared__ float tile[32][33];
    const int z  = blockIdx.z;
    const int ss0 = blockIdx.x * 32;
    const int dd0 = blockIdx.y * 32;
    const int tx = threadIdx.x;
    const int ty = threadIdx.y;
    const long long ib = (long long)z * Sk * HDim;
    const long long ob = (long long)z * HDim * Sk;
    #pragma unroll
    for (int i = ty; i < 32; i += 8)
        tile[i][tx] = Vb[ib + (long long)(ss0 + i) * HDim + dd0 + tx];
    __syncthreads();
    #pragma unroll
    for (int i = ty; i < 32; i += 8) {
        const float v = tile[tx][i];
        const __nv_bfloat16 hb = __float2bfloat16(v);
        const __nv_bfloat16 lb = __float2bfloat16(v - __bfloat162float(hb));
        const long long o = ob + (long long)(dd0 + i) * Sk + ss0 + tx;
        Vth[o] = hb; Vtl[o] = lb;
    }
}

// ---------------- warp reduction helpers ----------------
__device__ __forceinline__ float warpSum(float v) {
    #pragma unroll
    for (int o = 16; o > 0; o >>= 1) v += __shfl_xor_sync(0xffffffffu, v, o);
    return v;
}

// ---------------- QKV postprocess: RMSNorm + RoPE -> split bf16 Q,K; fp32 V ------
__global__ void qkv_post(const float* __restrict__ qkv, const float* __restrict__ pos,
                         const float* __restrict__ qw, const float* __restrict__ kw,
                         __nv_bfloat16* __restrict__ Qh, __nv_bfloat16* __restrict__ Ql,
                         __nv_bfloat16* __restrict__ Kh, __nv_bfloat16* __restrict__ Kl,
                         float* __restrict__ Vb)
{
    const int idx = blockIdx.x;
    const int h  = idx % Hn;
    const int bn = idx / Hn;
    const int n  = bn % Nq;
    const int b  = bn / Nq;
    const int d  = threadIdx.x;

    const float* row = qkv + (long long)bn * (3 * Cdim);
    const float qv = row[h * HDim + d];
    const float kv = row[Cdim + h * HDim + d];
    const float vv = row[2 * Cdim + h * HDim + d];

    __shared__ float sred[8];
    __shared__ float qs[HDim], ks[HDim];

    const float sq = warpSum(qv * qv);
    const float sk = warpSum(kv * kv);
    const int lane = d & 31, w = d >> 5;
    if (lane == 0) { sred[w] = sq; sred[4 + w] = sk; }
    __syncthreads();
    const float sumq = sred[0] + sred[1] + sred[2] + sred[3];
    const float sumk = sred[4] + sred[5] + sred[6] + sred[7];
    const float rq = rsqrtf(sumq * (1.0f / HDim) + EPSV);
    const float rk = rsqrtf(sumk * (1.0f / HDim) + EPSV);
    const float qn = qw[d] * qv * rq;
    const float kn = kw[d] * kv * rk;
    qs[d] = qn; ks[d] = kn;
    __syncthreads();

    float qo = qn, ko = kn;
    if (d < RD) {
        const int j = d & 31;
        const float c = pos[(n * 32 + j) * 2 + 0];
        const float s = pos[(n * 32 + j) * 2 + 1];
        if (d < RD / 2) { qo = qs[d] * c - qs[d + 32] * s;  ko = ks[d] * c - ks[d + 32] * s; }
        else            { qo = qs[d - 32] * s + qs[d] * c;  ko = ks[d - 32] * s + ks[d] * c; }
    }
    const long long qi = (((long long)(b * Hn + h)) * Nq + n) * HDim + d;
    const long long ki = (((long long)(b * Hn + h)) * Sk + n) * HDim + d;
    split_write(qo, Qh, Ql, qi);
    split_write(ko, Kh, Kl, ki);
    Vb[ki] = vv;
}

// ---------------- KV(y) postprocess ----------------
__global__ void kv_post(const float* __restrict__ kvr, const float* __restrict__ kw,
                        __nv_bfloat16* __restrict__ Kh, __nv_bfloat16* __restrict__ Kl,
                        float* __restrict__ Vb)
{
    const int idx = blockIdx.x;
    const int h  = idx % Hn;
    const int bm = idx / Hn;
    const int m  = bm % My;
    const int b  = bm / My;
    const int d  = threadIdx.x;

    const float* row = kvr + (long long)bm * (2 * Cdim);
    const float kv = row[h * HDim + d];
    const float vv = row[Cdim + h * HDim + d];

    __shared__ float sred[4];
    const float sk = warpSum(kv * kv);
    if ((d & 31) == 0) sred[d >> 5] = sk;
    __syncthreads();
    const float sumk = sred[0] + sred[1] + sred[2] + sred[3];
    const float rk = rsqrtf(sumk * (1.0f / HDim) + EPSV);
    const float kn = kw[d] * kv * rk;

    const long long ki = (((long long)(b * Hn + h)) * Sk + (Nq + m)) * HDim + d;
    split_write(kn, Kh, Kl, ki);
    Vb[ki] = vv;
}

// ---------------- launch ----------------
extern "C" void kernel_launch(void* const* d_in, const int* in_sizes, int n_in,
                              void* d_out, int out_size)
{
    const float* x    = (const float*)d_in[0];
    const float* y    = (const float*)d_in[1];
    const float* pos  = (const float*)d_in[2];
    const float* ytw  = (const float*)d_in[3];
    const float* Wqkv = (const float*)d_in[4];
    const float* Wkv  = (const float*)d_in[5];
    const float* qw   = (const float*)d_in[6];
    const float* kw   = (const float*)d_in[7];
    const float* Wproj= (const float*)d_in[8];
    const float* bproj= (const float*)d_in[9];
    float* out = (float*)d_out;

    float *qkv, *kvr, *Vb;
    cudaGetSymbolAddress((void**)&qkv, g_qkv);
    cudaGetSymbolAddress((void**)&kvr, g_kvr);
    cudaGetSymbolAddress((void**)&Vb,  g_Vb);

    __nv_bfloat16 *xh,*xl,*yh,*yl,*Wqh,*Wql,*Wkh,*Wkl,*Wph,*Wpl,*Obh,*Obl;
    __nv_bfloat16 *Qh,*Ql,*Kh,*Kl,*Vth,*Vtl;
    cudaGetSymbolAddress((void**)&xh, g_xh);   cudaGetSymbolAddress((void**)&xl, g_xl);
    cudaGetSymbolAddress((void**)&yh, g_yh);   cudaGetSymbolAddress((void**)&yl, g_yl);
    cudaGetSymbolAddress((void**)&Wqh, g_Wqkvh); cudaGetSymbolAddress((void**)&Wql, g_Wqkvl);
    cudaGetSymbolAddress((void**)&Wkh, g_Wkvh);  cudaGetSymbolAddress((void**)&Wkl, g_Wkvl);
    cudaGetSymbolAddress((void**)&Wph, g_Wph);   cudaGetSymbolAddress((void**)&Wpl, g_Wpl);
    cudaGetSymbolAddress((void**)&Obh, g_Obh);   cudaGetSymbolAddress((void**)&Obl, g_Obl);
    cudaGetSymbolAddress((void**)&Qh, g_Qh);     cudaGetSymbolAddress((void**)&Ql, g_Ql);
    cudaGetSymbolAddress((void**)&Kh, g_Kh);     cudaGetSymbolAddress((void**)&Kl, g_Kl);
    cudaGetSymbolAddress((void**)&Vth, g_Vth);   cudaGetSymbolAddress((void**)&Vtl, g_Vtl);

    cudaFuncSetAttribute(mma_gemm<false>, cudaFuncAttributeMaxDynamicSharedMemorySize, MM_SMEM_B);
    cudaFuncSetAttribute(mma_gemm<true>,  cudaFuncAttributeMaxDynamicSharedMemorySize, MM_SMEM_B);
    cudaFuncSetAttribute(fused_attn, cudaFuncAttributeMaxDynamicSharedMemorySize, FA_SMEM);

    // 0) split conversions
    auto cvt = [&](const float* s, __nv_bfloat16* h, __nv_bfloat16* l, long long n) {
        cvt_split<<<(int)((n / 4 + 255) / 256), 256>>>(s, h, l, n);
    };
    cvt(x, xh, xl, (long long)Bsz * Nq * Cdim);
    cvt(y, yh, yl, (long long)Bsz * My * Cdim);
    cvt_split_T<<<dim3(3 * Cdim / 32, Cdim / 32), dim3(32, 8)>>>(Wqkv, Wqh, Wql, Cdim, 3 * Cdim);
    cvt_split_T<<<dim3(2 * Cdim / 32, Cdim / 32), dim3(32, 8)>>>(Wkv,  Wkh, Wkl, Cdim, 2 * Cdim);
    cvt_split_T<<<dim3(Cdim / 32,     Cdim / 32), dim3(32, 8)>>>(Wproj, Wph, Wpl, Cdim, Cdim);

    // 1) QKV = x @ Wqkv   (128x128 tiles, 2 CTAs/SM)
    mma_gemm<false><<<dim3(3 * Cdim / 128, Bsz * Nq / 128), 256, MM_SMEM_B>>>(
        xh, xl, Wqh, Wql, qkv, nullptr, Cdim, 3 * Cdim);

    // 2) KV = y @ Wkv
    mma_gemm<false><<<dim3(2 * Cdim / 128, Bsz * My / 128), 256, MM_SMEM_B>>>(
        yh, yl, Wkh, Wkl, kvr, nullptr, Cdim, 2 * Cdim);

    // 3) postprocess
    qkv_post<<<Bsz * Nq * Hn, HDim>>>(qkv, pos, qw, kw, Qh, Ql, Kh, Kl, Vb);
    kv_post<<<Bsz * My * Hn, HDim>>>(kvr, kw, Kh, Kl, Vb);
    v_transpose_split<<<dim3(Sk / 32, HDim / 32, Bsz * Hn), dim3(32, 8)>>>(Vb, Vth, Vtl);

    // 4-6) fused attention v2 (q-tile 64, 128 threads, 2 CTAs/SM)
    fused_attn<<<dim3(Nq / 64, Bsz * Hn), 128, FA_SMEM>>>(
        Qh, Ql, Kh, Kl, Vth, Vtl, ytw, Obh, Obl);

    // 7) out = O @ Wproj + bproj
    mma_gemm<true><<<dim3(Cdim / 128, Bsz * Nq / 128), 256, MM_SMEM_B>>>(
        Obh, Obl, Wph, Wpl, out, bproj, Cdim, Cdim);
}

// round 11
// speedup vs baseline: 1.2563x; 1.0099x over previous
#include <cuda_runtime.h>
#include <cuda_bf16.h>
#include <math.h>
#include <cstdint>

// ---------------- problem constants ----------------
constexpr int Bsz  = 2;
constexpr int Nq   = 2048;
constexpr int My   = 512;
constexpr int Cdim = 1536;
constexpr int Hn   = 12;
constexpr int HDim = 128;          // Cdim / Hn
constexpr int RD   = 64;
constexpr int Sk   = Nq + My;      // 2560
constexpr float EPSV  = 1e-6f;
constexpr float SCALE = 0.08838834764831845f;   // 1/sqrt(128)

// ---------------- scratch (static device arrays; no allocs allowed) ----------------
__device__ float g_qkv [(long long)Bsz * Nq * 3 * Cdim];
__device__ float g_kvr [(long long)Bsz * My * 2 * Cdim];
__device__ float g_Vb  [(long long)Bsz * Hn * Sk * HDim];   // V fp32 [bh][s][d]

// split-bf16 operand buffers
__device__ __nv_bfloat16 g_xh [(long long)Bsz * Nq * Cdim];
__device__ __nv_bfloat16 g_xl [(long long)Bsz * Nq * Cdim];
__device__ __nv_bfloat16 g_yh [(long long)Bsz * My * Cdim];
__device__ __nv_bfloat16 g_yl [(long long)Bsz * My * Cdim];
__device__ __nv_bfloat16 g_Wqkvh[(long long)3 * Cdim * Cdim];
__device__ __nv_bfloat16 g_Wqkvl[(long long)3 * Cdim * Cdim];
__device__ __nv_bfloat16 g_Wkvh [(long long)2 * Cdim * Cdim];
__device__ __nv_bfloat16 g_Wkvl [(long long)2 * Cdim * Cdim];
__device__ __nv_bfloat16 g_Wph  [(long long)Cdim * Cdim];
__device__ __nv_bfloat16 g_Wpl  [(long long)Cdim * Cdim];
__device__ __nv_bfloat16 g_Obh  [(long long)Bsz * Nq * Cdim];
__device__ __nv_bfloat16 g_Obl  [(long long)Bsz * Nq * Cdim];
// attention split operands
__device__ __nv_bfloat16 g_Qh [(long long)Bsz * Hn * Nq * HDim];
__device__ __nv_bfloat16 g_Ql [(long long)Bsz * Hn * Nq * HDim];
__device__ __nv_bfloat16 g_Kh [(long long)Bsz * Hn * Sk * HDim];
__device__ __nv_bfloat16 g_Kl [(long long)Bsz * Hn * Sk * HDim];
__device__ __nv_bfloat16 g_Vth[(long long)Bsz * Hn * HDim * Sk];  // V^T [bh][d][s]
__device__ __nv_bfloat16 g_Vtl[(long long)Bsz * Hn * HDim * Sk];

// ---------------- small PTX helpers (baseline PTX only) ----------------
__device__ __forceinline__ uint32_t smem_u32(const void* p) {
    uint32_t a;
    asm("{ .reg .u64 t; cvta.to.shared.u64 t, %1; cvt.u32.u64 %0, t; }" : "=r"(a) : "l"(p));
    return a;
}
__device__ __forceinline__ void cp16(uint32_t dst, const void* src) {
    asm volatile("cp.async.cg.shared.global [%0], [%1], 16;" :: "r"(dst), "l"(src));
}
#define CP_COMMIT()  asm volatile("cp.async.commit_group;" ::: "memory")
#define CP_WAIT(n)   asm volatile("cp.async.wait_group %0;" :: "n"(n) : "memory")

__device__ __forceinline__ void mma_bf16(float d[4], const uint32_t a[4], const uint32_t b[2]) {
    asm volatile(
        "mma.sync.aligned.m16n8k16.row.col.f32.bf16.bf16.f32 "
        "{%0,%1,%2,%3}, {%4,%5,%6,%7}, {%8,%9}, {%0,%1,%2,%3};"
        : "+f"(d[0]), "+f"(d[1]), "+f"(d[2]), "+f"(d[3])
        : "r"(a[0]), "r"(a[1]), "r"(a[2]), "r"(a[3]), "r"(b[0]), "r"(b[1]));
}
__device__ __forceinline__ void split_write(float v, __nv_bfloat16* h, __nv_bfloat16* l, long long idx) {
    const __nv_bfloat16 hb = __float2bfloat16(v);
    h[idx] = hb;
    l[idx] = __float2bfloat16(v - __bfloat162float(hb));
}
__device__ __forceinline__ uint32_t pack_bf2(float a, float b) {
    __nv_bfloat162 v; v.x = __float2bfloat16(a); v.y = __float2bfloat16(b);
    return *(uint32_t*)&v;
}

// ---------------- 128x128 split-bf16 HMMA GEMM (all weight GEMMs; 2 CTAs/SM) -------
// __launch_bounds__(256, 2) caps regs at 128/thread so TWO CTAs genuinely co-reside.
constexpr int MM_STRIDE_B = 80;
constexpr int MM_ARR_B    = 128 * MM_STRIDE_B;
constexpr int MM_BUF_B    = 4 * MM_ARR_B;
constexpr int MM_SMEM_B   = 2 * MM_BUF_B;   // 81920

template<bool ADD_BIAS>
__global__ __launch_bounds__(256, 2)
void mma_gemm(const __nv_bfloat16* __restrict__ Ah, const __nv_bfloat16* __restrict__ Al,
              const __nv_bfloat16* __restrict__ Bh, const __nv_bfloat16* __restrict__ Bl,
              float* __restrict__ C, const float* __restrict__ bias,
              int Kd, int ldc)
{
    extern __shared__ char smem[];
    const uint32_t sbase = smem_u32(smem);

    const int tid  = threadIdx.x;
    const int lane = tid & 31;
    const int wid  = tid >> 5;
    const int row0 = blockIdx.y * 128;
    const int col0 = blockIdx.x * 128;
    const int wm   = (wid >> 2) * 64;
    const int wn   = (wid & 3) * 32;
    const int g    = lane >> 2;
    const int tg   = lane & 3;

    const int s0   = tid * 2;
    const int row_s0 = s0 >> 2,  q_s0 = s0 & 3;
    const int row_s1 = (s0 + 1) >> 2, q_s1 = (s0 + 1) & 3;

    auto stage = [&](int c, int buf) {
        const long long k0 = (long long)c * 32;
        const uint32_t db = sbase + buf * MM_BUF_B;
        {
            const long long ga = (long long)(row0 + row_s0) * Kd + k0 + q_s0 * 8;
            const long long gb = (long long)(col0 + row_s0) * Kd + k0 + q_s0 * 8;
            const uint32_t  so = row_s0 * MM_STRIDE_B + q_s0 * 16;
            cp16(db + 0 * MM_ARR_B + so, Ah + ga);
            cp16(db + 1 * MM_ARR_B + so, Al + ga);
            cp16(db + 2 * MM_ARR_B + so, Bh + gb);
            cp16(db + 3 * MM_ARR_B + so, Bl + gb);
        }
        {
            const long long ga = (long long)(row0 + row_s1) * Kd + k0 + q_s1 * 8;
            const long long gb = (long long)(col0 + row_s1) * Kd + k0 + q_s1 * 8;
            const uint32_t  so = row_s1 * MM_STRIDE_B + q_s1 * 16;
            cp16(db + 0 * MM_ARR_B + so, Ah + ga);
            cp16(db + 1 * MM_ARR_B + so, Al + ga);
            cp16(db + 2 * MM_ARR_B + so, Bh + gb);
            cp16(db + 3 * MM_ARR_B + so, Bl + gb);
        }
    };

    float acc[4][4][4];
    #pragma unroll
    for (int i = 0; i < 4; i++)
        #pragma unroll
        for (int j = 0; j < 4; j++)
            #pragma unroll
            for (int r = 0; r < 4; r++) acc[i][j][r] = 0.f;

    const int nch = Kd / 32;
    stage(0, 0);
    CP_COMMIT();

    for (int c = 0; c < nch; c++) {
        if (c + 1 < nch) { stage(c + 1, (c + 1) & 1); CP_COMMIT(); CP_WAIT(1); }
        else             { CP_WAIT(0); }
        __syncthreads();

        const char* bp = smem + (c & 1) * MM_BUF_B;
        const char* pAh = bp;
        const char* pAl = bp + MM_ARR_B;
        const char* pBh = bp + 2 * MM_ARR_B;
        const char* pBl = bp + 3 * MM_ARR_B;

        #pragma unroll
        for (int kk = 0; kk < 2; kk++) {
            const int cbyte = (kk * 16 + 2 * tg) * 2;
            uint32_t ah[4][4], al[4][4], bh[4][2], bl[4][2];
            #pragma unroll
            for (int mt = 0; mt < 4; mt++) {
                const int r = wm + mt * 16 + g;
                ah[mt][0] = *(const uint32_t*)(pAh + r * MM_STRIDE_B + cbyte);
                ah[mt][1] = *(const uint32_t*)(pAh + (r + 8) * MM_STRIDE_B + cbyte);
                ah[mt][2] = *(const uint32_t*)(pAh + r * MM_STRIDE_B + cbyte + 16);
                ah[mt][3] = *(const uint32_t*)(pAh + (r + 8) * MM_STRIDE_B + cbyte + 16);
                al[mt][0] = *(const uint32_t*)(pAl + r * MM_STRIDE_B + cbyte);
                al[mt][1] = *(const uint32_t*)(pAl + (r + 8) * MM_STRIDE_B + cbyte);
                al[mt][2] = *(const uint32_t*)(pAl + r * MM_STRIDE_B + cbyte + 16);
                al[mt][3] = *(const uint32_t*)(pAl + (r + 8) * MM_STRIDE_B + cbyte + 16);
            }
            #pragma unroll
            for (int nt = 0; nt < 4; nt++) {
                const int n = wn + nt * 8 + g;
                bh[nt][0] = *(const uint32_t*)(pBh + n * MM_STRIDE_B + cbyte);
                bh[nt][1] = *(const uint32_t*)(pBh + n * MM_STRIDE_B + cbyte + 16);
                bl[nt][0] = *(const uint32_t*)(pBl + n * MM_STRIDE_B + cbyte);
                bl[nt][1] = *(const uint32_t*)(pBl + n * MM_STRIDE_B + cbyte + 16);
            }
            #pragma unroll
            for (int mt = 0; mt < 4; mt++)
                #pragma unroll
                for (int nt = 0; nt < 4; nt++) {
                    mma_bf16(acc[mt][nt], ah[mt], bh[nt]);
                    mma_bf16(acc[mt][nt], ah[mt], bl[nt]);
                    mma_bf16(acc[mt][nt], al[mt], bh[nt]);
                }
        }
        __syncthreads();
    }

    #pragma unroll
    for (int nt = 0; nt < 4; nt++) {
        const int col = col0 + wn + nt * 8 + 2 * tg;
        float b0 = 0.f, b1 = 0.f;
        if (ADD_BIAS) { b0 = bias[col]; b1 = bias[col + 1]; }
        #pragma unroll
        for (int mt = 0; mt < 4; mt++) {
            const int r = row0 + wm + mt * 16 + g;
            float2 v0, v1;
            v0.x = acc[mt][nt][0] + b0; v0.y = acc[mt][nt][1] + b1;
            v1.x = acc[mt][nt][2] + b0; v1.y = acc[mt][nt][3] + b1;
            *(float2*)(C + (long long)r * ldc + col)       = v0;
            *(float2*)(C + (long long)(r + 8) * ldc + col) = v1;
        }
    }
}

// ---------------- fused attention v2: register-resident P, 2 CTAs/SM ----------------
constexpr int FA_NIT = Sk / 64;                 // 40
constexpr int F2_QH = 0;                         // Q hi: 64 x 272B
constexpr int F2_QL = 17408;
constexpr int F2_KH = 34816;                     // K hi: 64 x 272B (single buffer)
constexpr int F2_KL = 52224;
constexpr int F2_VH = 69632;                     // V^T hi: 128 x 144B
constexpr int F2_VL = 88064;
constexpr int F2_YB = 106496;                    // yb: 512 floats
constexpr int FA_SMEM = 108544;

__global__ __launch_bounds__(128, 2)
void fused_attn(const __nv_bfloat16* __restrict__ Qh, const __nv_bfloat16* __restrict__ Ql,
                const __nv_bfloat16* __restrict__ Kh, const __nv_bfloat16* __restrict__ Kl,
                const __nv_bfloat16* __restrict__ Vth, const __nv_bfloat16* __restrict__ Vtl,
                const float* __restrict__ ytw,
                __nv_bfloat16* __restrict__ Obh, __nv_bfloat16* __restrict__ Obl)
{
    extern __shared__ char smem[];
    const uint32_t sb = smem_u32(smem);

    const int z  = blockIdx.y;
    const int q0 = blockIdx.x * 64;
    const int b  = z / Hn;
    const int h  = z % Hn;

    const int tid  = threadIdx.x;
    const int lane = tid & 31;
    const int wid  = tid >> 5;            // 0..3
    const int g    = lane >> 2;
    const int tg   = lane & 3;
    const int wm   = wid * 16;            // warp's q-row base

    const __nv_bfloat16* Qhp = Qh + (long long)z * Nq * HDim;
    const __nv_bfloat16* Qlp = Ql + (long long)z * Nq * HDim;
    const __nv_bfloat16* Khp = Kh + (long long)z * Sk * HDim;
    const __nv_bfloat16* Klp = Kl + (long long)z * Sk * HDim;
    const __nv_bfloat16* Vhp = Vth + (long long)z * HDim * Sk;
    const __nv_bfloat16* Vlp = Vtl + (long long)z * HDim * Sk;

    // y bias
    float* sYB = (float*)(smem + F2_YB);
    #pragma unroll
    for (int j = 0; j < 4; j++) {
        const int i = tid + j * 128;
        sYB[i] = logf(fmaxf(ytw[b * My + i], 1e-4f));
    }

    // preload Q (held for whole kernel)
    #pragma unroll
    for (int j = 0; j < 8; j++) {
        const int id = tid + j * 128, r = id >> 4, c = id & 15;
        cp16(sb + F2_QH + r * 272 + c * 16, Qhp + (long long)(q0 + r) * HDim + c * 8);
        cp16(sb + F2_QL + r * 272 + c * 16, Qlp + (long long)(q0 + r) * HDim + c * 8);
    }
    CP_COMMIT();

    float oacc[16][4];
    #pragma unroll
    for (int i = 0; i < 16; i++)
        #pragma unroll
        for (int r = 0; r < 4; r++) oacc[i][r] = 0.f;
    float rowsum0 = 0.f, rowsum1 = 0.f;

    for (int it = 0; it < FA_NIT; it++) {
        __syncthreads();                   // prev iteration done with K/V buffers

        // stage K(it)
        #pragma unroll
        for (int j = 0; j < 8; j++) {
            const int id = tid + j * 128, r = id >> 4, c = id & 15;
            cp16(sb + F2_KH + r * 272 + c * 16, Khp + (long long)(it * 64 + r) * HDim + c * 8);
            cp16(sb + F2_KL + r * 272 + c * 16, Klp + (long long)(it * 64 + r) * HDim + c * 8);
        }
        // stage V(it)
        #pragma unroll
        for (int j = 0; j < 8; j++) {
            const int id = tid + j * 128, d = id >> 3, c = id & 7;
            cp16(sb + F2_VH + d * 144 + c * 16, Vhp + (long long)d * Sk + it * 64 + c * 8);
            cp16(sb + F2_VL + d * 144 + c * 16, Vlp + (long long)d * Sk + it * 64 + c * 8);
        }
        CP_COMMIT();
        CP_WAIT(0);
        __syncthreads();

        // ---- S phase: S[16 x 64] = Q K^T (split, 3 products) ----
        float sacc[8][4];
        #pragma unroll
        for (int i = 0; i < 8; i++)
            #pragma unroll
            for (int r = 0; r < 4; r++) sacc[i][r] = 0.f;

        #pragma unroll
        for (int kk = 0; kk < 8; kk++) {
            const int cb = kk * 32 + tg * 4;
            uint32_t qh_[4], ql_[4], kh_[8][2], kl_[8][2];
            {
                const char* p = smem + F2_QH + (wm + g) * 272 + cb;
                qh_[0] = *(const uint32_t*)(p);
                qh_[1] = *(const uint32_t*)(p + 8 * 272);
                qh_[2] = *(const uint32_t*)(p + 16);
                qh_[3] = *(const uint32_t*)(p + 8 * 272 + 16);
                const char* q = p + (F2_QL - F2_QH);
                ql_[0] = *(const uint32_t*)(q);
                ql_[1] = *(const uint32_t*)(q + 8 * 272);
                ql_[2] = *(const uint32_t*)(q + 16);
                ql_[3] = *(const uint32_t*)(q + 8 * 272 + 16);
            }
            #pragma unroll
            for (int nt = 0; nt < 8; nt++) {
                const char* p = smem + F2_KH + (nt * 8 + g) * 272 + cb;
                kh_[nt][0] = *(const uint32_t*)(p);
                kh_[nt][1] = *(const uint32_t*)(p + 16);
                kl_[nt][0] = *(const uint32_t*)(p + (F2_KL - F2_KH));
                kl_[nt][1] = *(const uint32_t*)(p + (F2_KL - F2_KH) + 16);
            }
            #pragma unroll
            for (int nt = 0; nt < 8; nt++) {
                mma_bf16(sacc[nt], qh_, kh_[nt]);
                mma_bf16(sacc[nt], qh_, kl_[nt]);
                mma_bf16(sacc[nt], ql_, kh_[nt]);
            }
        }

        // ---- exp (+scale +bias) -> PV A-fragments in registers (hi+lo) ----
        uint32_t ph_[4][4], pl_[4][4];
        #pragma unroll
        for (int nt = 0; nt < 8; nt++) {
            const int col0 = nt * 8 + 2 * tg;
            const int gc   = it * 64 + col0;
            float b0 = 0.f, b1 = 0.f;
            if (gc >= Nq) { b0 = sYB[gc - Nq]; b1 = sYB[gc - Nq + 1]; }
            const float p0 = __expf(sacc[nt][0] * SCALE + b0);
            const float p1 = __expf(sacc[nt][1] * SCALE + b1);
            const float p2 = __expf(sacc[nt][2] * SCALE + b0);
            const float p3 = __expf(sacc[nt][3] * SCALE + b1);
            rowsum0 += p0 + p1;
            rowsum1 += p2 + p3;
            const int j  = nt >> 1;
            const int rb = (nt & 1) * 2;
            const uint32_t h01 = pack_bf2(p0, p1);
            const uint32_t h23 = pack_bf2(p2, p3);
            ph_[j][rb + 0] = h01;
            ph_[j][rb + 1] = h23;
            const __nv_bfloat162 hb01 = *(const __nv_bfloat162*)&h01;
            const __nv_bfloat162 hb23 = *(const __nv_bfloat162*)&h23;
            pl_[j][rb + 0] = pack_bf2(p0 - __bfloat162float(hb01.x), p1 - __bfloat162float(hb01.y));
            pl_[j][rb + 1] = pack_bf2(p2 - __bfloat162float(hb23.x), p3 - __bfloat162float(hb23.y));
        }

        // ---- PV phase: O[16 x 128] += P V (split, 3 products) ----
        #pragma unroll
        for (int j = 0; j < 4; j++) {
            const int cb = j * 32 + tg * 4;
            #pragma unroll
            for (int nt = 0; nt < 16; nt++) {
                uint32_t vh_[2], vl_[2];
                const char* p = smem + F2_VH + (nt * 8 + g) * 144 + cb;
                vh_[0] = *(const uint32_t*)(p);
                vh_[1] = *(const uint32_t*)(p + 16);
                vl_[0] = *(const uint32_t*)(p + (F2_VL - F2_VH));
                vl_[1] = *(const uint32_t*)(p + (F2_VL - F2_VH) + 16);
                mma_bf16(oacc[nt], ph_[j], vh_);
                mma_bf16(oacc[nt], ph_[j], vl_);
                mma_bf16(oacc[nt], pl_[j], vh_);
            }
        }
    }

    // ---- rowsum reduce within tg quad ----
    rowsum0 += __shfl_xor_sync(0xffffffffu, rowsum0, 1);
    rowsum0 += __shfl_xor_sync(0xffffffffu, rowsum0, 2);
    rowsum1 += __shfl_xor_sync(0xffffffffu, rowsum1, 1);
    rowsum1 += __shfl_xor_sync(0xffffffffu, rowsum1, 2);
    const float inv0 = 1.f / rowsum0;
    const float inv1 = 1.f / rowsum1;

    // ---- epilogue ----
    const int r = wm + g;
    #pragma unroll
    for (int nt = 0; nt < 16; nt++) {
        const int col = nt * 8 + 2 * tg;
        const long long o0 = ((long long)b * Nq + q0 + r) * Cdim + h * HDim + col;
        const long long o1 = o0 + 8LL * Cdim;
        const float a0 = oacc[nt][0] * inv0, a1 = oacc[nt][1] * inv0;
        const float a2 = oacc[nt][2] * inv1, a3 = oacc[nt][3] * inv1;
        __nv_bfloat162 hv, lv;
        hv.x = __float2bfloat16(a0); hv.y = __float2bfloat16(a1);
        lv.x = __float2bfloat16(a0 - __bfloat162float(hv.x));
        lv.y = __float2bfloat16(a1 - __bfloat162float(hv.y));
        *(__nv_bfloat162*)(Obh + o0) = hv;
        *(__nv_bfloat162*)(Obl + o0) = lv;
        hv.x = __float2bfloat16(a2); hv.y = __float2bfloat16(a3);
        lv.x = __float2bfloat16(a2 - __bfloat162float(hv.x));
        lv.y = __float2bfloat16(a3 - __bfloat162float(hv.y));
        *(__nv_bfloat162*)(Obh + o1) = hv;
        *(__nv_bfloat162*)(Obl + o1) = lv;
    }
}

// ---------------- fp32 -> split bf16 (row-major keep) ----------------
__global__ void cvt_split(const float* __restrict__ src, __nv_bfloat16* __restrict__ h,
                          __nv_bfloat16* __restrict__ l, long long n)
{
    const long long i = ((long long)blockIdx.x * blockDim.x + threadIdx.x) * 4;
    if (i >= n) return;
    const float4 v = *(const float4*)(src + i);
    __nv_bfloat16 hb[4], lb[4];
    const float f[4] = {v.x, v.y, v.z, v.w};
    #pragma unroll
    for (int j = 0; j < 4; j++) {
        hb[j] = __float2bfloat16(f[j]);
        lb[j] = __float2bfloat16(f[j] - __bfloat162float(hb[j]));
    }
    *(uint2*)(h + i) = *(uint2*)hb;
    *(uint2*)(l + i) = *(uint2*)lb;
}

// ---------------- fp32 [K][N] -> split bf16 transposed [N][K] ----------------
__global__ void cvt_split_T(const float* __restrict__ W, __nv_bfloat16* __restrict__ h,
                            __nv_bfloat16* __restrict__ l, int K, int N)
{
    __shared__ float tile[32][33];
    const int k0 = blockIdx.y * 32;
    const int n0 = blockIdx.x * 32;
    const int tx = threadIdx.x;
    const int ty = threadIdx.y;
    #pragma unroll
    for (int i = ty; i < 32; i += 8)
        tile[i][tx] = W[(long long)(k0 + i) * N + n0 + tx];
    __syncthreads();
    #pragma unroll
    for (int i = ty; i < 32; i += 8) {
        const float v = tile[tx][i];
        const __nv_bfloat16 hb = __float2bfloat16(v);
        const __nv_bfloat16 lb = __float2bfloat16(v - __bfloat162float(hb));
        const long long o = (long long)(n0 + i) * K + k0 + tx;
        h[o] = hb; l[o] = lb;
    }
}

// ---------------- V: fp32 [bh][s][d] -> split bf16 transposed [bh][d][s] ----------
__global__ void v_transpose_split(const float* __restrict__ Vb,
                                  __nv_bfloat16* __restrict__ Vth,
                                  __nv_bfloat16* __restrict__ Vtl)
{
    __shared__ float tile[32][33];
    const int z  = blockIdx.z;
    const int ss0 = blockIdx.x * 32;
    const int dd0 = blockIdx.y * 32;
    const int tx = threadIdx.x;
    const int ty = threadIdx.y;
    const long long ib = (long long)z * Sk * HDim;
    const long long ob = (long long)z * HDim * Sk;
    #pragma unroll
    for (int i = ty; i < 32; i += 8)
        tile[i][tx] = Vb[ib + (long long)(ss0 + i) * HDim + dd0 + tx];
    __syncthreads();
    #pragma unroll
    for (int i = ty; i < 32; i += 8) {
        const float v = tile[tx][i];
        const __nv_bfloat16 hb = __float2bfloat16(v);
        const __nv_bfloat16 lb = __float2bfloat16(v - __bfloat162float(hb));
        const long long o = ob + (long long)(dd0 + i) * Sk + ss0 + tx;
        Vth[o] = hb; Vtl[o] = lb;
    }
}

// ---------------- warp reduction helpers ----------------
__device__ __forceinline__ float warpSum(float v) {
    #pragma unroll
    for (int o = 16; o > 0; o >>= 1) v += __shfl_xor_sync(0xffffffffu, v, o);
    return v;
}

// ---------------- QKV postprocess: RMSNorm + RoPE -> split bf16 Q,K; fp32 V ------
__global__ void qkv_post(const float* __restrict__ qkv, const float* __restrict__ pos,
                         const float* __restrict__ qw, const float* __restrict__ kw,
                         __nv_bfloat16* __restrict__ Qh, __nv_bfloat16* __restrict__ Ql,
                         __nv_bfloat16* __restrict__ Kh, __nv_bfloat16* __restrict__ Kl,
                         float* __restrict__ Vb)
{
    const int idx = blockIdx.x;
    const int h  = idx % Hn;
    const int bn = idx / Hn;
    const int n  = bn % Nq;
    const int b  = bn / Nq;
    const int d  = threadIdx.x;

    const float* row = qkv + (long long)bn * (3 * Cdim);
    const float qv = row[h * HDim + d];
    const float kv = row[Cdim + h * HDim + d];
    const float vv = row[2 * Cdim + h * HDim + d];

    __shared__ float sred[8];
    __shared__ float qs[HDim], ks[HDim];

    const float sq = warpSum(qv * qv);
    const float sk = warpSum(kv * kv);
    const int lane = d & 31, w = d >> 5;
    if (lane == 0) { sred[w] = sq; sred[4 + w] = sk; }
    __syncthreads();
    const float sumq = sred[0] + sred[1] + sred[2] + sred[3];
    const float sumk = sred[4] + sred[5] + sred[6] + sred[7];
    const float rq = rsqrtf(sumq * (1.0f / HDim) + EPSV);
    const float rk = rsqrtf(sumk * (1.0f / HDim) + EPSV);
    const float qn = qw[d] * qv * rq;
    const float kn = kw[d] * kv * rk;
    qs[d] = qn; ks[d] = kn;
    __syncthreads();

    float qo = qn, ko = kn;
    if (d < RD) {
        const int j = d & 31;
        const float c = pos[(n * 32 + j) * 2 + 0];
        const float s = pos[(n * 32 + j) * 2 + 1];
        if (d < RD / 2) { qo = qs[d] * c - qs[d + 32] * s;  ko = ks[d] * c - ks[d + 32] * s; }
        else            { qo = qs[d - 32] * s + qs[d] * c;  ko = ks[d - 32] * s + ks[d] * c; }
    }
    const long long qi = (((long long)(b * Hn + h)) * Nq + n) * HDim + d;
    const long long ki = (((long long)(b * Hn + h)) * Sk + n) * HDim + d;
    split_write(qo, Qh, Ql, qi);
    split_write(ko, Kh, Kl, ki);
    Vb[ki] = vv;
}

// ---------------- KV(y) postprocess ----------------
__global__ void kv_post(const float* __restrict__ kvr, const float* __restrict__ kw,
                        __nv_bfloat16* __restrict__ Kh, __nv_bfloat16* __restrict__ Kl,
                        float* __restrict__ Vb)
{
    const int idx = blockIdx.x;
    const int h  = idx % Hn;
    const int bm = idx / Hn;
    const int m  = bm % My;
    const int b  = bm / My;
    const int d  = threadIdx.x;

    const float* row = kvr + (long long)bm * (2 * Cdim);
    const float kv = row[h * HDim + d];
    const float vv = row[Cdim + h * HDim + d];

    __shared__ float sred[4];
    const float sk = warpSum(kv * kv);
    if ((d & 31) == 0) sred[d >> 5] = sk;
    __syncthreads();
    const float sumk = sred[0] + sred[1] + sred[2] + sred[3];
    const float rk = rsqrtf(sumk * (1.0f / HDim) + EPSV);
    const float kn = kw[d] * kv * rk;

    const long long ki = (((long long)(b * Hn + h)) * Sk + (Nq + m)) * HDim + d;
    split_write(kn, Kh, Kl, ki);
    Vb[ki] = vv;
}

// ---------------- launch ----------------
extern "C" void kernel_launch(void* const* d_in, const int* in_sizes, int n_in,
                              void* d_out, int out_size)
{
    const float* x    = (const float*)d_in[0];
    const float* y    = (const float*)d_in[1];
    const float* pos  = (const float*)d_in[2];
    const float* ytw  = (const float*)d_in[3];
    const float* Wqkv = (const float*)d_in[4];
    const float* Wkv  = (const float*)d_in[5];
    const float* qw   = (const float*)d_in[6];
    const float* kw   = (const float*)d_in[7];
    const float* Wproj= (const float*)d_in[8];
    const float* bproj= (const float*)d_in[9];
    float* out = (float*)d_out;

    float *qkv, *kvr, *Vb;
    cudaGetSymbolAddress((void**)&qkv, g_qkv);
    cudaGetSymbolAddress((void**)&kvr, g_kvr);
    cudaGetSymbolAddress((void**)&Vb,  g_Vb);

    __nv_bfloat16 *xh,*xl,*yh,*yl,*Wqh,*Wql,*Wkh,*Wkl,*Wph,*Wpl,*Obh,*Obl;
    __nv_bfloat16 *Qh,*Ql,*Kh,*Kl,*Vth,*Vtl;
    cudaGetSymbolAddress((void**)&xh, g_xh);   cudaGetSymbolAddress((void**)&xl, g_xl);
    cudaGetSymbolAddress((void**)&yh, g_yh);   cudaGetSymbolAddress((void**)&yl, g_yl);
    cudaGetSymbolAddress((void**)&Wqh, g_Wqkvh); cudaGetSymbolAddress((void**)&Wql, g_Wqkvl);
    cudaGetSymbolAddress((void**)&Wkh, g_Wkvh);  cudaGetSymbolAddress((void**)&Wkl, g_Wkvl);
    cudaGetSymbolAddress((void**)&Wph, g_Wph);   cudaGetSymbolAddress((void**)&Wpl, g_Wpl);
    cudaGetSymbolAddress((void**)&Obh, g_Obh);   cudaGetSymbolAddress((void**)&Obl, g_Obl);
    cudaGetSymbolAddress((void**)&Qh, g_Qh);     cudaGetSymbolAddress((void**)&Ql, g_Ql);
    cudaGetSymbolAddress((void**)&Kh, g_Kh);     cudaGetSymbolAddress((void**)&Kl, g_Kl);
    cudaGetSymbolAddress((void**)&Vth, g_Vth);   cudaGetSymbolAddress((void**)&Vtl, g_Vtl);

    cudaFuncSetAttribute(mma_gemm<false>, cudaFuncAttributeMaxDynamicSharedMemorySize, MM_SMEM_B);
    cudaFuncSetAttribute(mma_gemm<true>,  cudaFuncAttributeMaxDynamicSharedMemorySize, MM_SMEM_B);
    cudaFuncSetAttribute(fused_attn, cudaFuncAttributeMaxDynamicSharedMemorySize, FA_SMEM);

    // 0) split conversions
    auto cvt = [&](const float* s, __nv_bfloat16* h, __nv_bfloat16* l, long long n) {
        cvt_split<<<(int)((n / 4 + 255) / 256), 256>>>(s, h, l, n);
    };
    cvt(x, xh, xl, (long long)Bsz * Nq * Cdim);
    cvt(y, yh, yl, (long long)Bsz * My * Cdim);
    cvt_split_T<<<dim3(3 * Cdim / 32, Cdim / 32), dim3(32, 8)>>>(Wqkv, Wqh, Wql, Cdim, 3 * Cdim);
    cvt_split_T<<<dim3(2 * Cdim / 32, Cdim / 32), dim3(32, 8)>>>(Wkv,  Wkh, Wkl, Cdim, 2 * Cdim);
    cvt_split_T<<<dim3(Cdim / 32,     Cdim / 32), dim3(32, 8)>>>(Wproj, Wph, Wpl, Cdim, Cdim);

    // 1) QKV = x @ Wqkv   (128x128 tiles, forced 2 CTAs/SM)
    mma_gemm<false><<<dim3(3 * Cdim / 128, Bsz * Nq / 128), 256, MM_SMEM_B>>>(
        xh, xl, Wqh, Wql, qkv, nullptr, Cdim, 3 * Cdim);

    // 2) KV = y @ Wkv
    mma_gemm<false><<<dim3(2 * Cdim / 128, Bsz * My / 128), 256, MM_SMEM_B>>>(
        yh, yl, Wkh, Wkl, kvr, nullptr, Cdim, 2 * Cdim);

    // 3) postprocess
    qkv_post<<<Bsz * Nq * Hn, HDim>>>(qkv, pos, qw, kw, Qh, Ql, Kh, Kl, Vb);
    kv_post<<<Bsz * My * Hn, HDim>>>(kvr, kw, Kh, Kl, Vb);
    v_transpose_split<<<dim3(Sk / 32, HDim / 32, Bsz * Hn), dim3(32, 8)>>>(Vb, Vth, Vtl);

    // 4-6) fused attention v2 (q-tile 64, 128 threads, 2 CTAs/SM)
    fused_attn<<<dim3(Nq / 64, Bsz * Hn), 128, FA_SMEM>>>(
        Qh, Ql, Kh, Kl, Vth, Vtl, ytw, Obh, Obl);

    // 7) out = O @ Wproj + bproj
    mma_gemm<true><<<dim3(Cdim / 128, Bsz * Nq / 128), 256, MM_SMEM_B>>>(
        Obh, Obl, Wph, Wpl, out, bproj, Cdim, Cdim);
}

// round 12
// speedup vs baseline: 1.2660x; 1.0077x over previous
#include <cuda_runtime.h>
#include <cuda_bf16.h>
#include <math.h>
#include <cstdint>

// ---------------- problem constants ----------------
constexpr int Bsz  = 2;
constexpr int Nq   = 2048;
constexpr int My   = 512;
constexpr int Cdim = 1536;
constexpr int Hn   = 12;
constexpr int HDim = 128;          // Cdim / Hn
constexpr int RD   = 64;
constexpr int Sk   = Nq + My;      // 2560
constexpr float EPSV  = 1e-6f;
constexpr float SCALE = 0.08838834764831845f;   // 1/sqrt(128)

// ---------------- scratch (static device arrays; no allocs allowed) ----------------
__device__ float g_qkv [(long long)Bsz * Nq * 3 * Cdim];
__device__ float g_kvr [(long long)Bsz * My * 2 * Cdim];
__device__ float g_Vb  [(long long)Bsz * Hn * Sk * HDim];   // V fp32 [bh][s][d]

// split-bf16 operand buffers
__device__ __nv_bfloat16 g_xh [(long long)Bsz * Nq * Cdim];
__device__ __nv_bfloat16 g_xl [(long long)Bsz * Nq * Cdim];
__device__ __nv_bfloat16 g_yh [(long long)Bsz * My * Cdim];
__device__ __nv_bfloat16 g_yl [(long long)Bsz * My * Cdim];
__device__ __nv_bfloat16 g_Wqkvh[(long long)3 * Cdim * Cdim];
__device__ __nv_bfloat16 g_Wqkvl[(long long)3 * Cdim * Cdim];
__device__ __nv_bfloat16 g_Wkvh [(long long)2 * Cdim * Cdim];
__device__ __nv_bfloat16 g_Wkvl [(long long)2 * Cdim * Cdim];
__device__ __nv_bfloat16 g_Wph  [(long long)Cdim * Cdim];
__device__ __nv_bfloat16 g_Wpl  [(long long)Cdim * Cdim];
__device__ __nv_bfloat16 g_Obh  [(long long)Bsz * Nq * Cdim];
__device__ __nv_bfloat16 g_Obl  [(long long)Bsz * Nq * Cdim];
// attention split operands
__device__ __nv_bfloat16 g_Qh [(long long)Bsz * Hn * Nq * HDim];
__device__ __nv_bfloat16 g_Ql [(long long)Bsz * Hn * Nq * HDim];
__device__ __nv_bfloat16 g_Kh [(long long)Bsz * Hn * Sk * HDim];
__device__ __nv_bfloat16 g_Kl [(long long)Bsz * Hn * Sk * HDim];
__device__ __nv_bfloat16 g_Vth[(long long)Bsz * Hn * HDim * Sk];  // V^T [bh][d][s]
__device__ __nv_bfloat16 g_Vtl[(long long)Bsz * Hn * HDim * Sk];

// ---------------- small PTX helpers (baseline PTX only) ----------------
__device__ __forceinline__ uint32_t smem_u32(const void* p) {
    uint32_t a;
    asm("{ .reg .u64 t; cvta.to.shared.u64 t, %1; cvt.u32.u64 %0, t; }" : "=r"(a) : "l"(p));
    return a;
}
__device__ __forceinline__ void cp16(uint32_t dst, const void* src) {
    asm volatile("cp.async.cg.shared.global [%0], [%1], 16;" :: "r"(dst), "l"(src));
}
#define CP_COMMIT()  asm volatile("cp.async.commit_group;" ::: "memory")
#define CP_WAIT(n)   asm volatile("cp.async.wait_group %0;" :: "n"(n) : "memory")

__device__ __forceinline__ void mma_bf16(float d[4], const uint32_t a[4], const uint32_t b[2]) {
    asm volatile(
        "mma.sync.aligned.m16n8k16.row.col.f32.bf16.bf16.f32 "
        "{%0,%1,%2,%3}, {%4,%5,%6,%7}, {%8,%9}, {%0,%1,%2,%3};"
        : "+f"(d[0]), "+f"(d[1]), "+f"(d[2]), "+f"(d[3])
        : "r"(a[0]), "r"(a[1]), "r"(a[2]), "r"(a[3]), "r"(b[0]), "r"(b[1]));
}
__device__ __forceinline__ void split_write(float v, __nv_bfloat16* h, __nv_bfloat16* l, long long idx) {
    const __nv_bfloat16 hb = __float2bfloat16(v);
    h[idx] = hb;
    l[idx] = __float2bfloat16(v - __bfloat162float(hb));
}
__device__ __forceinline__ uint32_t pack_bf2(float a, float b) {
    __nv_bfloat162 v; v.x = __float2bfloat16(a); v.y = __float2bfloat16(b);
    return *(uint32_t*)&v;
}

// ---------------- 128x128 split-bf16 HMMA GEMM core ----------------
constexpr int MM_STRIDE_B = 80;
constexpr int MM_ARR_B    = 128 * MM_STRIDE_B;
constexpr int MM_BUF_B    = 4 * MM_ARR_B;
constexpr int MM_SMEM_B   = 2 * MM_BUF_B;   // 81920

// QKV tile grid: 36 cols x 32 rows = 1152 CTAs; KV: 24 cols x 8 rows = 192 CTAs.
constexpr int QKV_COLT = 3 * Cdim / 128;     // 36
constexpr int QKV_CTAS = QKV_COLT * (Bsz * Nq / 128);   // 1152
constexpr int KV_COLT  = 2 * Cdim / 128;     // 24
constexpr int FUSED_CTAS = QKV_CTAS + KV_COLT * (Bsz * My / 128);  // 1344

// Shared main loop body used by both GEMM kernels.
#define MM_BODY(AhP, AlP, BhP, BlP)                                                         \
    const int s0   = tid * 2;                                                               \
    const int row_s0 = s0 >> 2,  q_s0 = s0 & 3;                                             \
    const int row_s1 = (s0 + 1) >> 2, q_s1 = (s0 + 1) & 3;                                  \
    auto stage = [&](int c, int buf) {                                                      \
        const long long k0 = (long long)c * 32;                                             \
        const uint32_t db = sbase + buf * MM_BUF_B;                                         \
        {                                                                                   \
            const long long ga = (long long)(row0 + row_s0) * Cdim + k0 + q_s0 * 8;         \
            const long long gb = (long long)(col0 + row_s0) * Cdim + k0 + q_s0 * 8;         \
            const uint32_t  so = row_s0 * MM_STRIDE_B + q_s0 * 16;                          \
            cp16(db + 0 * MM_ARR_B + so, (AhP) + ga);                                       \
            cp16(db + 1 * MM_ARR_B + so, (AlP) + ga);                                       \
            cp16(db + 2 * MM_ARR_B + so, (BhP) + gb);                                       \
            cp16(db + 3 * MM_ARR_B + so, (BlP) + gb);                                       \
        }                                                                                   \
        {                                                                                   \
            const long long ga = (long long)(row0 + row_s1) * Cdim + k0 + q_s1 * 8;         \
            const long long gb = (long long)(col0 + row_s1) * Cdim + k0 + q_s1 * 8;         \
            const uint32_t  so = row_s1 * MM_STRIDE_B + q_s1 * 16;                          \
            cp16(db + 0 * MM_ARR_B + so, (AhP) + ga);                                       \
            cp16(db + 1 * MM_ARR_B + so, (AlP) + ga);                                       \
            cp16(db + 2 * MM_ARR_B + so, (BhP) + gb);                                       \
            cp16(db + 3 * MM_ARR_B + so, (BlP) + gb);                                       \
        }                                                                                   \
    };                                                                                      \
    float acc[4][4][4];                                                                     \
    _Pragma("unroll")                                                                       \
    for (int i = 0; i < 4; i++)                                                             \
        _Pragma("unroll")                                                                   \
        for (int j = 0; j < 4; j++)                                                         \
            _Pragma("unroll")                                                               \
            for (int r = 0; r < 4; r++) acc[i][j][r] = 0.f;                                 \
    constexpr int nch = Cdim / 32;                                                          \
    stage(0, 0);                                                                            \
    CP_COMMIT();                                                                            \
    for (int c = 0; c < nch; c++) {                                                         \
        if (c + 1 < nch) { stage(c + 1, (c + 1) & 1); CP_COMMIT(); CP_WAIT(1); }            \
        else             { CP_WAIT(0); }                                                    \
        __syncthreads();                                                                    \
        const char* bp = smem + (c & 1) * MM_BUF_B;                                         \
        const char* pAh = bp;                                                               \
        const char* pAl = bp + MM_ARR_B;                                                    \
        const char* pBh = bp + 2 * MM_ARR_B;                                                \
        const char* pBl = bp + 3 * MM_ARR_B;                                                \
        _Pragma("unroll")                                                                   \
        for (int kk = 0; kk < 2; kk++) {                                                    \
            const int cbyte = (kk * 16 + 2 * tg) * 2;                                       \
            uint32_t ah[4][4], al[4][4], bh[4][2], bl[4][2];                                \
            _Pragma("unroll")                                                               \
            for (int mt = 0; mt < 4; mt++) {                                                \
                const int r = wm + mt * 16 + g;                                             \
                ah[mt][0] = *(const uint32_t*)(pAh + r * MM_STRIDE_B + cbyte);              \
                ah[mt][1] = *(const uint32_t*)(pAh + (r + 8) * MM_STRIDE_B + cbyte);        \
                ah[mt][2] = *(const uint32_t*)(pAh + r * MM_STRIDE_B + cbyte + 16);         \
                ah[mt][3] = *(const uint32_t*)(pAh + (r + 8) * MM_STRIDE_B + cbyte + 16);   \
                al[mt][0] = *(const uint32_t*)(pAl + r * MM_STRIDE_B + cbyte);              \
                al[mt][1] = *(const uint32_t*)(pAl + (r + 8) * MM_STRIDE_B + cbyte);        \
                al[mt][2] = *(const uint32_t*)(pAl + r * MM_STRIDE_B + cbyte + 16);         \
                al[mt][3] = *(const uint32_t*)(pAl + (r + 8) * MM_STRIDE_B + cbyte + 16);   \
            }                                                                               \
            _Pragma("unroll")                                                               \
            for (int nt = 0; nt < 4; nt++) {                                                \
                const int n = wn + nt * 8 + g;                                              \
                bh[nt][0] = *(const uint32_t*)(pBh + n * MM_STRIDE_B + cbyte);              \
                bh[nt][1] = *(const uint32_t*)(pBh + n * MM_STRIDE_B + cbyte + 16);         \
                bl[nt][0] = *(const uint32_t*)(pBl + n * MM_STRIDE_B + cbyte);              \
                bl[nt][1] = *(const uint32_t*)(pBl + n * MM_STRIDE_B + cbyte + 16);         \
            }                                                                               \
            _Pragma("unroll")                                                               \
            for (int mt = 0; mt < 4; mt++)                                                  \
                _Pragma("unroll")                                                           \
                for (int nt = 0; nt < 4; nt++) {                                            \
                    mma_bf16(acc[mt][nt], ah[mt], bh[nt]);                                  \
                    mma_bf16(acc[mt][nt], ah[mt], bl[nt]);                                  \
                    mma_bf16(acc[mt][nt], al[mt], bh[nt]);                                  \
                }                                                                           \
        }                                                                                   \
        __syncthreads();                                                                    \
    }

// ---- fused QKV + KV weight GEMM: one 1D grid packs both problems' tiles ----
__global__ __launch_bounds__(256, 2)
void mma_gemm_fused(const __nv_bfloat16* __restrict__ xh, const __nv_bfloat16* __restrict__ xl,
                    const __nv_bfloat16* __restrict__ Wqh, const __nv_bfloat16* __restrict__ Wql,
                    float* __restrict__ Cq,
                    const __nv_bfloat16* __restrict__ yh, const __nv_bfloat16* __restrict__ yl,
                    const __nv_bfloat16* __restrict__ Wkh, const __nv_bfloat16* __restrict__ Wkl,
                    float* __restrict__ Ck)
{
    extern __shared__ char smem[];
    const uint32_t sbase = smem_u32(smem);

    const int tid  = threadIdx.x;
    const int lane = tid & 31;
    const int wid  = tid >> 5;
    const int wm   = (wid >> 2) * 64;
    const int wn   = (wid & 3) * 32;
    const int g    = lane >> 2;
    const int tg   = lane & 3;

    const int bid = blockIdx.x;
    const __nv_bfloat16 *Ah, *Al, *Bh, *Bl;
    float* C;
    int row0, col0, ldc;
    if (bid < QKV_CTAS) {
        Ah = xh; Al = xl; Bh = Wqh; Bl = Wql; C = Cq;
        row0 = (bid / QKV_COLT) * 128;
        col0 = (bid % QKV_COLT) * 128;
        ldc  = 3 * Cdim;
    } else {
        const int b2 = bid - QKV_CTAS;
        Ah = yh; Al = yl; Bh = Wkh; Bl = Wkl; C = Ck;
        row0 = (b2 / KV_COLT) * 128;
        col0 = (b2 % KV_COLT) * 128;
        ldc  = 2 * Cdim;
    }

    MM_BODY(Ah, Al, Bh, Bl)

    #pragma unroll
    for (int nt = 0; nt < 4; nt++) {
        const int col = col0 + wn + nt * 8 + 2 * tg;
        #pragma unroll
        for (int mt = 0; mt < 4; mt++) {
            const int r = row0 + wm + mt * 16 + g;
            float2 v0, v1;
            v0.x = acc[mt][nt][0]; v0.y = acc[mt][nt][1];
            v1.x = acc[mt][nt][2]; v1.y = acc[mt][nt][3];
            *(float2*)(C + (long long)r * ldc + col)       = v0;
            *(float2*)(C + (long long)(r + 8) * ldc + col) = v1;
        }
    }
}

// ---- proj GEMM (bias) ----
__global__ __launch_bounds__(256, 2)
void mma_gemm_proj(const __nv_bfloat16* __restrict__ Ahp, const __nv_bfloat16* __restrict__ Alp,
                   const __nv_bfloat16* __restrict__ Bhp, const __nv_bfloat16* __restrict__ Blp,
                   float* __restrict__ C, const float* __restrict__ bias)
{
    extern __shared__ char smem[];
    const uint32_t sbase = smem_u32(smem);

    const int tid  = threadIdx.x;
    const int lane = tid & 31;
    const int wid  = tid >> 5;
    const int row0 = blockIdx.y * 128;
    const int col0 = blockIdx.x * 128;
    const int wm   = (wid >> 2) * 64;
    const int wn   = (wid & 3) * 32;
    const int g    = lane >> 2;
    const int tg   = lane & 3;

    MM_BODY(Ahp, Alp, Bhp, Blp)

    #pragma unroll
    for (int nt = 0; nt < 4; nt++) {
        const int col = col0 + wn + nt * 8 + 2 * tg;
        const float b0 = bias[col], b1 = bias[col + 1];
        #pragma unroll
        for (int mt = 0; mt < 4; mt++) {
            const int r = row0 + wm + mt * 16 + g;
            float2 v0, v1;
            v0.x = acc[mt][nt][0] + b0; v0.y = acc[mt][nt][1] + b1;
            v1.x = acc[mt][nt][2] + b0; v1.y = acc[mt][nt][3] + b1;
            *(float2*)(C + (long long)r * Cdim + col)       = v0;
            *(float2*)(C + (long long)(r + 8) * Cdim + col) = v1;
        }
    }
}

// ---------------- fused attention v2: register-resident P, split K/V waits -------
constexpr int FA_NIT = Sk / 64;                 // 40
constexpr int F2_QH = 0;                         // Q hi: 64 x 272B
constexpr int F2_QL = 17408;
constexpr int F2_KH = 34816;                     // K hi: 64 x 272B (single buffer)
constexpr int F2_KL = 52224;
constexpr int F2_VH = 69632;                     // V^T hi: 128 x 144B
constexpr int F2_VL = 88064;
constexpr int F2_YB = 106496;                    // yb: 512 floats
constexpr int FA_SMEM = 108544;

__global__ __launch_bounds__(128, 2)
void fused_attn(const __nv_bfloat16* __restrict__ Qh, const __nv_bfloat16* __restrict__ Ql,
                const __nv_bfloat16* __restrict__ Kh, const __nv_bfloat16* __restrict__ Kl,
                const __nv_bfloat16* __restrict__ Vth, const __nv_bfloat16* __restrict__ Vtl,
                const float* __restrict__ ytw,
                __nv_bfloat16* __restrict__ Obh, __nv_bfloat16* __restrict__ Obl)
{
    extern __shared__ char smem[];
    const uint32_t sb = smem_u32(smem);

    const int z  = blockIdx.y;
    const int q0 = blockIdx.x * 64;
    const int b  = z / Hn;
    const int h  = z % Hn;

    const int tid  = threadIdx.x;
    const int lane = tid & 31;
    const int wid  = tid >> 5;            // 0..3
    const int g    = lane >> 2;
    const int tg   = lane & 3;
    const int wm   = wid * 16;            // warp's q-row base

    const __nv_bfloat16* Qhp = Qh + (long long)z * Nq * HDim;
    const __nv_bfloat16* Qlp = Ql + (long long)z * Nq * HDim;
    const __nv_bfloat16* Khp = Kh + (long long)z * Sk * HDim;
    const __nv_bfloat16* Klp = Kl + (long long)z * Sk * HDim;
    const __nv_bfloat16* Vhp = Vth + (long long)z * HDim * Sk;
    const __nv_bfloat16* Vlp = Vtl + (long long)z * HDim * Sk;

    // y bias
    float* sYB = (float*)(smem + F2_YB);
    #pragma unroll
    for (int j = 0; j < 4; j++) {
        const int i = tid + j * 128;
        sYB[i] = logf(fmaxf(ytw[b * My + i], 1e-4f));
    }

    // preload Q (held for whole kernel)
    #pragma unroll
    for (int j = 0; j < 8; j++) {
        const int id = tid + j * 128, r = id >> 4, c = id & 15;
        cp16(sb + F2_QH + r * 272 + c * 16, Qhp + (long long)(q0 + r) * HDim + c * 8);
        cp16(sb + F2_QL + r * 272 + c * 16, Qlp + (long long)(q0 + r) * HDim + c * 8);
    }
    CP_COMMIT();

    float oacc[16][4];
    #pragma unroll
    for (int i = 0; i < 16; i++)
        #pragma unroll
        for (int r = 0; r < 4; r++) oacc[i][r] = 0.f;
    float rowsum0 = 0.f, rowsum1 = 0.f;

    for (int it = 0; it < FA_NIT; it++) {
        __syncthreads();                   // prev iteration done with K/V buffers

        // stage K(it) -- own group so S can start before V arrives
        #pragma unroll
        for (int j = 0; j < 8; j++) {
            const int id = tid + j * 128, r = id >> 4, c = id & 15;
            cp16(sb + F2_KH + r * 272 + c * 16, Khp + (long long)(it * 64 + r) * HDim + c * 8);
            cp16(sb + F2_KL + r * 272 + c * 16, Klp + (long long)(it * 64 + r) * HDim + c * 8);
        }
        CP_COMMIT();
        // stage V(it) -- separate group, overlaps S phase
        #pragma unroll
        for (int j = 0; j < 8; j++) {
            const int id = tid + j * 128, d = id >> 3, c = id & 7;
            cp16(sb + F2_VH + d * 144 + c * 16, Vhp + (long long)d * Sk + it * 64 + c * 8);
            cp16(sb + F2_VL + d * 144 + c * 16, Vlp + (long long)d * Sk + it * 64 + c * 8);
        }
        CP_COMMIT();
        CP_WAIT(1);                        // Q (it=0) + K ready; V may still fly
        __syncthreads();

        // ---- S phase: S[16 x 64] = Q K^T (split, 3 products) ----
        float sacc[8][4];
        #pragma unroll
        for (int i = 0; i < 8; i++)
            #pragma unroll
            for (int r = 0; r < 4; r++) sacc[i][r] = 0.f;

        #pragma unroll
        for (int kk = 0; kk < 8; kk++) {
            const int cb = kk * 32 + tg * 4;
            uint32_t qh_[4], ql_[4], kh_[8][2], kl_[8][2];
            {
                const char* p = smem + F2_QH + (wm + g) * 272 + cb;
                qh_[0] = *(const uint32_t*)(p);
                qh_[1] = *(const uint32_t*)(p + 8 * 272);
                qh_[2] = *(const uint32_t*)(p + 16);
                qh_[3] = *(const uint32_t*)(p + 8 * 272 + 16);
                const char* q = p + (F2_QL - F2_QH);
                ql_[0] = *(const uint32_t*)(q);
                ql_[1] = *(const uint32_t*)(q + 8 * 272);
                ql_[2] = *(const uint32_t*)(q + 16);
                ql_[3] = *(const uint32_t*)(q + 8 * 272 + 16);
            }
            #pragma unroll
            for (int nt = 0; nt < 8; nt++) {
                const char* p = smem + F2_KH + (nt * 8 + g) * 272 + cb;
                kh_[nt][0] = *(const uint32_t*)(p);
                kh_[nt][1] = *(const uint32_t*)(p + 16);
                kl_[nt][0] = *(const uint32_t*)(p + (F2_KL - F2_KH));
                kl_[nt][1] = *(const uint32_t*)(p + (F2_KL - F2_KH) + 16);
            }
            #pragma unroll
            for (int nt = 0; nt < 8; nt++) {
                mma_bf16(sacc[nt], qh_, kh_[nt]);
                mma_bf16(sacc[nt], qh_, kl_[nt]);
                mma_bf16(sacc[nt], ql_, kh_[nt]);
            }
        }

        // ---- exp (+scale +bias) -> PV A-fragments in registers (hi+lo) ----
        uint32_t ph_[4][4], pl_[4][4];
        #pragma unroll
        for (int nt = 0; nt < 8; nt++) {
            const int col0 = nt * 8 + 2 * tg;
            const int gc   = it * 64 + col0;
            float b0 = 0.f, b1 = 0.f;
            if (gc >= Nq) { b0 = sYB[gc - Nq]; b1 = sYB[gc - Nq + 1]; }
            const float p0 = __expf(sacc[nt][0] * SCALE + b0);
            const float p1 = __expf(sacc[nt][1] * SCALE + b1);
            const float p2 = __expf(sacc[nt][2] * SCALE + b0);
            const float p3 = __expf(sacc[nt][3] * SCALE + b1);
            rowsum0 += p0 + p1;
            rowsum1 += p2 + p3;
            const int j  = nt >> 1;
            const int rb = (nt & 1) * 2;
            const uint32_t h01 = pack_bf2(p0, p1);
            const uint32_t h23 = pack_bf2(p2, p3);
            ph_[j][rb + 0] = h01;
            ph_[j][rb + 1] = h23;
            const __nv_bfloat162 hb01 = *(const __nv_bfloat162*)&h01;
            const __nv_bfloat162 hb23 = *(const __nv_bfloat162*)&h23;
            pl_[j][rb + 0] = pack_bf2(p0 - __bfloat162float(hb01.x), p1 - __bfloat162float(hb01.y));
            pl_[j][rb + 1] = pack_bf2(p2 - __bfloat162float(hb23.x), p3 - __bfloat162float(hb23.y));
        }

        CP_WAIT(0);                        // V ready now
        // no __syncthreads needed: V buffer untouched since top-of-loop barrier

        // ---- PV phase: O[16 x 128] += P V (split, 3 products) ----
        #pragma unroll
        for (int j = 0; j < 4; j++) {
            const int cb = j * 32 + tg * 4;
            #pragma unroll
            for (int nt = 0; nt < 16; nt++) {
                uint32_t vh_[2], vl_[2];
                const char* p = smem + F2_VH + (nt * 8 + g) * 144 + cb;
                vh_[0] = *(const uint32_t*)(p);
                vh_[1] = *(const uint32_t*)(p + 16);
                vl_[0] = *(const uint32_t*)(p + (F2_VL - F2_VH));
                vl_[1] = *(const uint32_t*)(p + (F2_VL - F2_VH) + 16);
                mma_bf16(oacc[nt], ph_[j], vh_);
                mma_bf16(oacc[nt], ph_[j], vl_);
                mma_bf16(oacc[nt], pl_[j], vh_);
            }
        }
    }

    // ---- rowsum reduce within tg quad ----
    rowsum0 += __shfl_xor_sync(0xffffffffu, rowsum0, 1);
    rowsum0 += __shfl_xor_sync(0xffffffffu, rowsum0, 2);
    rowsum1 += __shfl_xor_sync(0xffffffffu, rowsum1, 1);
    rowsum1 += __shfl_xor_sync(0xffffffffu, rowsum1, 2);
    const float inv0 = 1.f / rowsum0;
    const float inv1 = 1.f / rowsum1;

    // ---- epilogue ----
    const int r = wm + g;
    #pragma unroll
    for (int nt = 0; nt < 16; nt++) {
        const int col = nt * 8 + 2 * tg;
        const long long o0 = ((long long)b * Nq + q0 + r) * Cdim + h * HDim + col;
        const long long o1 = o0 + 8LL * Cdim;
        const float a0 = oacc[nt][0] * inv0, a1 = oacc[nt][1] * inv0;
        const float a2 = oacc[nt][2] * inv1, a3 = oacc[nt][3] * inv1;
        __nv_bfloat162 hv, lv;
        hv.x = __float2bfloat16(a0); hv.y = __float2bfloat16(a1);
        lv.x = __float2bfloat16(a0 - __bfloat162float(hv.x));
        lv.y = __float2bfloat16(a1 - __bfloat162float(hv.y));
        *(__nv_bfloat162*)(Obh + o0) = hv;
        *(__nv_bfloat162*)(Obl + o0) = lv;
        hv.x = __float2bfloat16(a2); hv.y = __float2bfloat16(a3);
        lv.x = __float2bfloat16(a2 - __bfloat162float(hv.x));
        lv.y = __float2bfloat16(a3 - __bfloat162float(hv.y));
        *(__nv_bfloat162*)(Obh + o1) = hv;
        *(__nv_bfloat162*)(Obl + o1) = lv;
    }
}

// ---------------- fp32 -> split bf16 (row-major keep) ----------------
__global__ void cvt_split(const float* __restrict__ src, __nv_bfloat16* __restrict__ h,
                          __nv_bfloat16* __restrict__ l, long long n)
{
    const long long i = ((long long)blockIdx.x * blockDim.x + threadIdx.x) * 4;
    if (i >= n) return;
    const float4 v = *(const float4*)(src + i);
    __nv_bfloat16 hb[4], lb[4];
    const float f[4] = {v.x, v.y, v.z, v.w};
    #pragma unroll
    for (int j = 0; j < 4; j++) {
        hb[j] = __float2bfloat16(f[j]);
        lb[j] = __float2bfloat16(f[j] - __bfloat162float(hb[j]));
    }
    *(uint2*)(h + i) = *(uint2*)hb;
    *(uint2*)(l + i) = *(uint2*)lb;
}

// ---------------- fp32 [K][N] -> split bf16 transposed [N][K] ----------------
__global__ void cvt_split_T(const float* __restrict__ W, __nv_bfloat16* __restrict__ h,
                            __nv_bfloat16* __restrict__ l, int K, int N)
{
    __shared__ float tile[32][33];
    const int k0 = blockIdx.y * 32;
    const int n0 = blockIdx.x * 32;
    const int tx = threadIdx.x;
    const int ty = threadIdx.y;
    #pragma unroll
    for (int i = ty; i < 32; i += 8)
        tile[i][tx] = W[(long long)(k0 + i) * N + n0 + tx];
    __syncthreads();
    #pragma unroll
    for (int i = ty; i < 32; i += 8) {
        const float v = tile[tx][i];
        const __nv_bfloat16 hb = __float2bfloat16(v);
        const __nv_bfloat16 lb = __float2bfloat16(v - __bfloat162float(hb));
        const long long o = (long long)(n0 + i) * K + k0 + tx;
        h[o] = hb; l[o] = lb;
    }
}

// ---------------- V: fp32 [bh][s][d] -> split bf16 transposed [bh][d][s] ----------
__global__ void v_transpose_split(const float* __restrict__ Vb,
                                  __nv_bfloat16* __restrict__ Vth,
                                  __nv_bfloat16* __restrict__ Vtl)
{
    __shared__ float tile[32][33];
    const int z  = blockIdx.z;
    const int ss0 = blockIdx.x * 32;
    const int dd0 = blockIdx.y * 32;
    const int tx = threadIdx.x;
    const int ty = threadIdx.y;
    const long long ib = (long long)z * Sk * HDim;
    const long long ob = (long long)z * HDim * Sk;
    #pragma unroll
    for (int i = ty; i < 32; i += 8)
        tile[i][tx] = Vb[ib + (long long)(ss0 + i) * HDim + dd0 + tx];
    __syncthreads();
    #pragma unroll
    for (int i = ty; i < 32; i += 8) {
        const float v = tile[tx][i];
        const __nv_bfloat16 hb = __float2bfloat16(v);
        const __nv_bfloat16 lb = __float2bfloat16(v - __bfloat162float(hb));
        const long long o = ob + (long long)(dd0 + i) * Sk + ss0 + tx;
        Vth[o] = hb; Vtl[o] = lb;
    }
}

// ---------------- warp reduction helpers ----------------
__device__ __forceinline__ float warpSum(float v) {
    #pragma unroll
    for (int o = 16; o > 0; o >>= 1) v += __shfl_xor_sync(0xffffffffu, v, o);
    return v;
}

// ---------------- QKV postprocess: RMSNorm + RoPE -> split bf16 Q,K; fp32 V ------
__global__ void qkv_post(const float* __restrict__ qkv, const float* __restrict__ pos,
                         const float* __restrict__ qw, const float* __restrict__ kw,
                         __nv_bfloat16* __restrict__ Qh, __nv_bfloat16* __restrict__ Ql,
                         __nv_bfloat16* __restrict__ Kh, __nv_bfloat16* __restrict__ Kl,
                         float* __restrict__ Vb)
{
    const int idx = blockIdx.x;
    const int h  = idx % Hn;
    const int bn = idx / Hn;
    const int n  = bn % Nq;
    const int b  = bn / Nq;
    const int d  = threadIdx.x;

    const float* row = qkv + (long long)bn * (3 * Cdim);
    const float qv = row[h * HDim + d];
    const float kv = row[Cdim + h * HDim + d];
    const float vv = row[2 * Cdim + h * HDim + d];

    __shared__ float sred[8];
    __shared__ float qs[HDim], ks[HDim];

    const float sq = warpSum(qv * qv);
    const float sk = warpSum(kv * kv);
    const int lane = d & 31, w = d >> 5;
    if (lane == 0) { sred[w] = sq; sred[4 + w] = sk; }
    __syncthreads();
    const float sumq = sred[0] + sred[1] + sred[2] + sred[3];
    const float sumk = sred[4] + sred[5] + sred[6] + sred[7];
    const float rq = rsqrtf(sumq * (1.0f / HDim) + EPSV);
    const float rk = rsqrtf(sumk * (1.0f / HDim) + EPSV);
    const float qn = qw[d] * qv * rq;
    const float kn = kw[d] * kv * rk;
    qs[d] = qn; ks[d] = kn;
    __syncthreads();

    float qo = qn, ko = kn;
    if (d < RD) {
        const int j = d & 31;
        const float c = pos[(n * 32 + j) * 2 + 0];
        const float s = pos[(n * 32 + j) * 2 + 1];
        if (d < RD / 2) { qo = qs[d] * c - qs[d + 32] * s;  ko = ks[d] * c - ks[d + 32] * s; }
        else            { qo = qs[d - 32] * s + qs[d] * c;  ko = ks[d - 32] * s + ks[d] * c; }
    }
    const long long qi = (((long long)(b * Hn + h)) * Nq + n) * HDim + d;
    const long long ki = (((long long)(b * Hn + h)) * Sk + n) * HDim + d;
    split_write(qo, Qh, Ql, qi);
    split_write(ko, Kh, Kl, ki);
    Vb[ki] = vv;
}

// ---------------- KV(y) postprocess ----------------
__global__ void kv_post(const float* __restrict__ kvr, const float* __restrict__ kw,
                        __nv_bfloat16* __restrict__ Kh, __nv_bfloat16* __restrict__ Kl,
                        float* __restrict__ Vb)
{
    const int idx = blockIdx.x;
    const int h  = idx % Hn;
    const int bm = idx / Hn;
    const int m  = bm % My;
    const int b  = bm / My;
    const int d  = threadIdx.x;

    const float* row = kvr + (long long)bm * (2 * Cdim);
    const float kv = row[h * HDim + d];
    const float vv = row[Cdim + h * HDim + d];

    __shared__ float sred[4];
    const float sk = warpSum(kv * kv);
    if ((d & 31) == 0) sred[d >> 5] = sk;
    __syncthreads();
    const float sumk = sred[0] + sred[1] + sred[2] + sred[3];
    const float rk = rsqrtf(sumk * (1.0f / HDim) + EPSV);
    const float kn = kw[d] * kv * rk;

    const long long ki = (((long long)(b * Hn + h)) * Sk + (Nq + m)) * HDim + d;
    split_write(kn, Kh, Kl, ki);
    Vb[ki] = vv;
}

// ---------------- launch ----------------
extern "C" void kernel_launch(void* const* d_in, const int* in_sizes, int n_in,
                              void* d_out, int out_size)
{
    const float* x    = (const float*)d_in[0];
    const float* y    = (const float*)d_in[1];
    const float* pos  = (const float*)d_in[2];
    const float* ytw  = (const float*)d_in[3];
    const float* Wqkv = (const float*)d_in[4];
    const float* Wkv  = (const float*)d_in[5];
    const float* qw   = (const float*)d_in[6];
    const float* kw   = (const float*)d_in[7];
    const float* Wproj= (const float*)d_in[8];
    const float* bproj= (const float*)d_in[9];
    float* out = (float*)d_out;

    float *qkv, *kvr, *Vb;
    cudaGetSymbolAddress((void**)&qkv, g_qkv);
    cudaGetSymbolAddress((void**)&kvr, g_kvr);
    cudaGetSymbolAddress((void**)&Vb,  g_Vb);

    __nv_bfloat16 *xh,*xl,*yh,*yl,*Wqh,*Wql,*Wkh,*Wkl,*Wph,*Wpl,*Obh,*Obl;
    __nv_bfloat16 *Qh,*Ql,*Kh,*Kl,*Vth,*Vtl;
    cudaGetSymbolAddress((void**)&xh, g_xh);   cudaGetSymbolAddress((void**)&xl, g_xl);
    cudaGetSymbolAddress((void**)&yh, g_yh);   cudaGetSymbolAddress((void**)&yl, g_yl);
    cudaGetSymbolAddress((void**)&Wqh, g_Wqkvh); cudaGetSymbolAddress((void**)&Wql, g_Wqkvl);
    cudaGetSymbolAddress((void**)&Wkh, g_Wkvh);  cudaGetSymbolAddress((void**)&Wkl, g_Wkvl);
    cudaGetSymbolAddress((void**)&Wph, g_Wph);   cudaGetSymbolAddress((void**)&Wpl, g_Wpl);
    cudaGetSymbolAddress((void**)&Obh, g_Obh);   cudaGetSymbolAddress((void**)&Obl, g_Obl);
    cudaGetSymbolAddress((void**)&Qh, g_Qh);     cudaGetSymbolAddress((void**)&Ql, g_Ql);
    cudaGetSymbolAddress((void**)&Kh, g_Kh);     cudaGetSymbolAddress((void**)&Kl, g_Kl);
    cudaGetSymbolAddress((void**)&Vth, g_Vth);   cudaGetSymbolAddress((void**)&Vtl, g_Vtl);

    cudaFuncSetAttribute(mma_gemm_fused, cudaFuncAttributeMaxDynamicSharedMemorySize, MM_SMEM_B);
    cudaFuncSetAttribute(mma_gemm_proj,  cudaFuncAttributeMaxDynamicSharedMemorySize, MM_SMEM_B);
    cudaFuncSetAttribute(fused_attn, cudaFuncAttributeMaxDynamicSharedMemorySize, FA_SMEM);

    // 0) split conversions
    auto cvt = [&](const float* s, __nv_bfloat16* h, __nv_bfloat16* l, long long n) {
        cvt_split<<<(int)((n / 4 + 255) / 256), 256>>>(s, h, l, n);
    };
    cvt(x, xh, xl, (long long)Bsz * Nq * Cdim);
    cvt(y, yh, yl, (long long)Bsz * My * Cdim);
    cvt_split_T<<<dim3(3 * Cdim / 32, Cdim / 32), dim3(32, 8)>>>(Wqkv, Wqh, Wql, Cdim, 3 * Cdim);
    cvt_split_T<<<dim3(2 * Cdim / 32, Cdim / 32), dim3(32, 8)>>>(Wkv,  Wkh, Wkl, Cdim, 2 * Cdim);
    cvt_split_T<<<dim3(Cdim / 32,     Cdim / 32), dim3(32, 8)>>>(Wproj, Wph, Wpl, Cdim, Cdim);

    // 1+2) fused QKV + KV weight GEMM (one 1D grid, packs partial waves)
    mma_gemm_fused<<<FUSED_CTAS, 256, MM_SMEM_B>>>(
        xh, xl, Wqh, Wql, qkv, yh, yl, Wkh, Wkl, kvr);

    // 3) postprocess
    qkv_post<<<Bsz * Nq * Hn, HDim>>>(qkv, pos, qw, kw, Qh, Ql, Kh, Kl, Vb);
    kv_post<<<Bsz * My * Hn, HDim>>>(kvr, kw, Kh, Kl, Vb);
    v_transpose_split<<<dim3(Sk / 32, HDim / 32, Bsz * Hn), dim3(32, 8)>>>(Vb, Vth, Vtl);

    // 4-6) fused attention v2 (q-tile 64, 128 threads, 2 CTAs/SM, split K/V waits)
    fused_attn<<<dim3(Nq / 64, Bsz * Hn), 128, FA_SMEM>>>(
        Qh, Ql, Kh, Kl, Vth, Vtl, ytw, Obh, Obl);

    // 7) out = O @ Wproj + bproj
    mma_gemm_proj<<<dim3(Cdim / 128, Bsz * Nq / 128), 256, MM_SMEM_B>>>(
        Obh, Obl, Wph, Wpl, out, bproj);
}

// round 13
// speedup vs baseline: 1.2924x; 1.0208x over previous
#include <cuda_runtime.h>
#include <cuda_bf16.h>
#include <math.h>
#include <cstdint>

// ---------------- problem constants ----------------
constexpr int Bsz  = 2;
constexpr int Nq   = 2048;
constexpr int My   = 512;
constexpr int Cdim = 1536;
constexpr int Hn   = 12;
constexpr int HDim = 128;          // Cdim / Hn
constexpr int RD   = 64;
constexpr int Sk   = Nq + My;      // 2560
constexpr float EPSV  = 1e-6f;
constexpr float SCALE = 0.08838834764831845f;   // 1/sqrt(128)

// ---------------- scratch (static device arrays; no allocs allowed) ----------------
__device__ float g_qkv [(long long)Bsz * Nq * 3 * Cdim];
__device__ float g_kvr [(long long)Bsz * My * 2 * Cdim];
__device__ float g_Vb  [(long long)Bsz * Hn * Sk * HDim];   // V fp32 [bh][s][d]

// split-bf16 operand buffers
__device__ __nv_bfloat16 g_xh [(long long)Bsz * Nq * Cdim];
__device__ __nv_bfloat16 g_xl [(long long)Bsz * Nq * Cdim];
__device__ __nv_bfloat16 g_yh [(long long)Bsz * My * Cdim];
__device__ __nv_bfloat16 g_yl [(long long)Bsz * My * Cdim];
__device__ __nv_bfloat16 g_Wqkvh[(long long)3 * Cdim * Cdim];
__device__ __nv_bfloat16 g_Wqkvl[(long long)3 * Cdim * Cdim];
__device__ __nv_bfloat16 g_Wkvh [(long long)2 * Cdim * Cdim];
__device__ __nv_bfloat16 g_Wkvl [(long long)2 * Cdim * Cdim];
__device__ __nv_bfloat16 g_Wph  [(long long)Cdim * Cdim];
__device__ __nv_bfloat16 g_Wpl  [(long long)Cdim * Cdim];
__device__ __nv_bfloat16 g_Obh  [(long long)Bsz * Nq * Cdim];
__device__ __nv_bfloat16 g_Obl  [(long long)Bsz * Nq * Cdim];
// attention split operands
__device__ __nv_bfloat16 g_Qh [(long long)Bsz * Hn * Nq * HDim];
__device__ __nv_bfloat16 g_Ql [(long long)Bsz * Hn * Nq * HDim];
__device__ __nv_bfloat16 g_Kh [(long long)Bsz * Hn * Sk * HDim];
__device__ __nv_bfloat16 g_Kl [(long long)Bsz * Hn * Sk * HDim];
__device__ __nv_bfloat16 g_Vth[(long long)Bsz * Hn * HDim * Sk];  // V^T [bh][d][s]
__device__ __nv_bfloat16 g_Vtl[(long long)Bsz * Hn * HDim * Sk];

// ---------------- small PTX helpers (baseline PTX only) ----------------
__device__ __forceinline__ uint32_t smem_u32(const void* p) {
    uint32_t a;
    asm("{ .reg .u64 t; cvta.to.shared.u64 t, %1; cvt.u32.u64 %0, t; }" : "=r"(a) : "l"(p));
    return a;
}
__device__ __forceinline__ void cp16(uint32_t dst, const void* src) {
    asm volatile("cp.async.cg.shared.global [%0], [%1], 16;" :: "r"(dst), "l"(src));
}
#define CP_COMMIT()  asm volatile("cp.async.commit_group;" ::: "memory")
#define CP_WAIT(n)   asm volatile("cp.async.wait_group %0;" :: "n"(n) : "memory")

__device__ __forceinline__ void mma_bf16(float d[4], const uint32_t a[4], const uint32_t b[2]) {
    asm volatile(
        "mma.sync.aligned.m16n8k16.row.col.f32.bf16.bf16.f32 "
        "{%0,%1,%2,%3}, {%4,%5,%6,%7}, {%8,%9}, {%0,%1,%2,%3};"
        : "+f"(d[0]), "+f"(d[1]), "+f"(d[2]), "+f"(d[3])
        : "r"(a[0]), "r"(a[1]), "r"(a[2]), "r"(a[3]), "r"(b[0]), "r"(b[1]));
}
__device__ __forceinline__ void split_write(float v, __nv_bfloat16* h, __nv_bfloat16* l, long long idx) {
    const __nv_bfloat16 hb = __float2bfloat16(v);
    h[idx] = hb;
    l[idx] = __float2bfloat16(v - __bfloat162float(hb));
}
__device__ __forceinline__ uint32_t pack_bf2(float a, float b) {
    __nv_bfloat162 v; v.x = __float2bfloat16(a); v.y = __float2bfloat16(b);
    return *(uint32_t*)&v;
}

// ---------------- 128x128 split-bf16 HMMA GEMM core ----------------
constexpr int MM_STRIDE_B = 80;
constexpr int MM_ARR_B    = 128 * MM_STRIDE_B;
constexpr int MM_BUF_B    = 4 * MM_ARR_B;
constexpr int MM_SMEM_B   = 2 * MM_BUF_B;   // 81920

constexpr int QKV_COLT = 3 * Cdim / 128;     // 36
constexpr int QKV_CTAS = QKV_COLT * (Bsz * Nq / 128);   // 1152
constexpr int KV_COLT  = 2 * Cdim / 128;     // 24
constexpr int FUSED_CTAS = QKV_CTAS + KV_COLT * (Bsz * My / 128);  // 1344

#define MM_BODY(AhP, AlP, BhP, BlP)                                                         \
    const int s0   = tid * 2;                                                               \
    const int row_s0 = s0 >> 2,  q_s0 = s0 & 3;                                             \
    const int row_s1 = (s0 + 1) >> 2, q_s1 = (s0 + 1) & 3;                                  \
    auto stage = [&](int c, int buf) {                                                      \
        const long long k0 = (long long)c * 32;                                             \
        const uint32_t db = sbase + buf * MM_BUF_B;                                         \
        {                                                                                   \
            const long long ga = (long long)(row0 + row_s0) * Cdim + k0 + q_s0 * 8;         \
            const long long gb = (long long)(col0 + row_s0) * Cdim + k0 + q_s0 * 8;         \
            const uint32_t  so = row_s0 * MM_STRIDE_B + q_s0 * 16;                          \
            cp16(db + 0 * MM_ARR_B + so, (AhP) + ga);                                       \
            cp16(db + 1 * MM_ARR_B + so, (AlP) + ga);                                       \
            cp16(db + 2 * MM_ARR_B + so, (BhP) + gb);                                       \
            cp16(db + 3 * MM_ARR_B + so, (BlP) + gb);                                       \
        }                                                                                   \
        {                                                                                   \
            const long long ga = (long long)(row0 + row_s1) * Cdim + k0 + q_s1 * 8;         \
            const long long gb = (long long)(col0 + row_s1) * Cdim + k0 + q_s1 * 8;         \
            const uint32_t  so = row_s1 * MM_STRIDE_B + q_s1 * 16;                          \
            cp16(db + 0 * MM_ARR_B + so, (AhP) + ga);                                       \
            cp16(db + 1 * MM_ARR_B + so, (AlP) + ga);                                       \
            cp16(db + 2 * MM_ARR_B + so, (BhP) + gb);                                       \
            cp16(db + 3 * MM_ARR_B + so, (BlP) + gb);                                       \
        }                                                                                   \
    };                                                                                      \
    float acc[4][4][4];                                                                     \
    _Pragma("unroll")                                                                       \
    for (int i = 0; i < 4; i++)                                                             \
        _Pragma("unroll")                                                                   \
        for (int j = 0; j < 4; j++)                                                         \
            _Pragma("unroll")                                                               \
            for (int r = 0; r < 4; r++) acc[i][j][r] = 0.f;                                 \
    constexpr int nch = Cdim / 32;                                                          \
    stage(0, 0);                                                                            \
    CP_COMMIT();                                                                            \
    for (int c = 0; c < nch; c++) {                                                         \
        if (c + 1 < nch) { stage(c + 1, (c + 1) & 1); CP_COMMIT(); CP_WAIT(1); }            \
        else             { CP_WAIT(0); }                                                    \
        __syncthreads();                                                                    \
        const char* bp = smem + (c & 1) * MM_BUF_B;                                         \
        const char* pAh = bp;                                                               \
        const char* pAl = bp + MM_ARR_B;                                                    \
        const char* pBh = bp + 2 * MM_ARR_B;                                                \
        const char* pBl = bp + 3 * MM_ARR_B;                                                \
        _Pragma("unroll")                                                                   \
        for (int kk = 0; kk < 2; kk++) {                                                    \
            const int cbyte = (kk * 16 + 2 * tg) * 2;                                       \
            uint32_t ah[4][4], al[4][4], bh[4][2], bl[4][2];                                \
            _Pragma("unroll")                                                               \
            for (int mt = 0; mt < 4; mt++) {                                                \
                const int r = wm + mt * 16 + g;                                             \
                ah[mt][0] = *(const uint32_t*)(pAh + r * MM_STRIDE_B + cbyte);              \
                ah[mt][1] = *(const uint32_t*)(pAh + (r + 8) * MM_STRIDE_B + cbyte);        \
                ah[mt][2] = *(const uint32_t*)(pAh + r * MM_STRIDE_B + cbyte + 16);         \
                ah[mt][3] = *(const uint32_t*)(pAh + (r + 8) * MM_STRIDE_B + cbyte + 16);   \
                al[mt][0] = *(const uint32_t*)(pAl + r * MM_STRIDE_B + cbyte);              \
                al[mt][1] = *(const uint32_t*)(pAl + (r + 8) * MM_STRIDE_B + cbyte);        \
                al[mt][2] = *(const uint32_t*)(pAl + r * MM_STRIDE_B + cbyte + 16);         \
                al[mt][3] = *(const uint32_t*)(pAl + (r + 8) * MM_STRIDE_B + cbyte + 16);   \
            }                                                                               \
            _Pragma("unroll")                                                               \
            for (int nt = 0; nt < 4; nt++) {                                                \
                const int n = wn + nt * 8 + g;                                              \
                bh[nt][0] = *(const uint32_t*)(pBh + n * MM_STRIDE_B + cbyte);              \
                bh[nt][1] = *(const uint32_t*)(pBh + n * MM_STRIDE_B + cbyte + 16);         \
                bl[nt][0] = *(const uint32_t*)(pBl + n * MM_STRIDE_B + cbyte);              \
                bl[nt][1] = *(const uint32_t*)(pBl + n * MM_STRIDE_B + cbyte + 16);         \
            }                                                                               \
            _Pragma("unroll")                                                               \
            for (int mt = 0; mt < 4; mt++)                                                  \
                _Pragma("unroll")                                                           \
                for (int nt = 0; nt < 4; nt++) {                                            \
                    mma_bf16(acc[mt][nt], ah[mt], bh[nt]);                                  \
                    mma_bf16(acc[mt][nt], ah[mt], bl[nt]);                                  \
                    mma_bf16(acc[mt][nt], al[mt], bh[nt]);                                  \
                }                                                                           \
        }                                                                                   \
        __syncthreads();                                                                    \
    }

// ---- fused QKV + KV weight GEMM ----
__global__ __launch_bounds__(256, 2)
void mma_gemm_fused(const __nv_bfloat16* __restrict__ xh, const __nv_bfloat16* __restrict__ xl,
                    const __nv_bfloat16* __restrict__ Wqh, const __nv_bfloat16* __restrict__ Wql,
                    float* __restrict__ Cq,
                    const __nv_bfloat16* __restrict__ yh, const __nv_bfloat16* __restrict__ yl,
                    const __nv_bfloat16* __restrict__ Wkh, const __nv_bfloat16* __restrict__ Wkl,
                    float* __restrict__ Ck)
{
    extern __shared__ char smem[];
    const uint32_t sbase = smem_u32(smem);

    const int tid  = threadIdx.x;
    const int lane = tid & 31;
    const int wid  = tid >> 5;
    const int wm   = (wid >> 2) * 64;
    const int wn   = (wid & 3) * 32;
    const int g    = lane >> 2;
    const int tg   = lane & 3;

    const int bid = blockIdx.x;
    const __nv_bfloat16 *Ah, *Al, *Bh, *Bl;
    float* C;
    int row0, col0, ldc;
    if (bid < QKV_CTAS) {
        Ah = xh; Al = xl; Bh = Wqh; Bl = Wql; C = Cq;
        row0 = (bid / QKV_COLT) * 128;
        col0 = (bid % QKV_COLT) * 128;
        ldc  = 3 * Cdim;
    } else {
        const int b2 = bid - QKV_CTAS;
        Ah = yh; Al = yl; Bh = Wkh; Bl = Wkl; C = Ck;
        row0 = (b2 / KV_COLT) * 128;
        col0 = (b2 % KV_COLT) * 128;
        ldc  = 2 * Cdim;
    }

    MM_BODY(Ah, Al, Bh, Bl)

    #pragma unroll
    for (int nt = 0; nt < 4; nt++) {
        const int col = col0 + wn + nt * 8 + 2 * tg;
        #pragma unroll
        for (int mt = 0; mt < 4; mt++) {
            const int r = row0 + wm + mt * 16 + g;
            float2 v0, v1;
            v0.x = acc[mt][nt][0]; v0.y = acc[mt][nt][1];
            v1.x = acc[mt][nt][2]; v1.y = acc[mt][nt][3];
            *(float2*)(C + (long long)r * ldc + col)       = v0;
            *(float2*)(C + (long long)(r + 8) * ldc + col) = v1;
        }
    }
}

// ---- proj GEMM (bias) ----
__global__ __launch_bounds__(256, 2)
void mma_gemm_proj(const __nv_bfloat16* __restrict__ Ahp, const __nv_bfloat16* __restrict__ Alp,
                   const __nv_bfloat16* __restrict__ Bhp, const __nv_bfloat16* __restrict__ Blp,
                   float* __restrict__ C, const float* __restrict__ bias)
{
    extern __shared__ char smem[];
    const uint32_t sbase = smem_u32(smem);

    const int tid  = threadIdx.x;
    const int lane = tid & 31;
    const int wid  = tid >> 5;
    const int row0 = blockIdx.y * 128;
    const int col0 = blockIdx.x * 128;
    const int wm   = (wid >> 2) * 64;
    const int wn   = (wid & 3) * 32;
    const int g    = lane >> 2;
    const int tg   = lane & 3;

    MM_BODY(Ahp, Alp, Bhp, Blp)

    #pragma unroll
    for (int nt = 0; nt < 4; nt++) {
        const int col = col0 + wn + nt * 8 + 2 * tg;
        const float b0 = bias[col], b1 = bias[col + 1];
        #pragma unroll
        for (int mt = 0; mt < 4; mt++) {
            const int r = row0 + wm + mt * 16 + g;
            float2 v0, v1;
            v0.x = acc[mt][nt][0] + b0; v0.y = acc[mt][nt][1] + b1;
            v1.x = acc[mt][nt][2] + b0; v1.y = acc[mt][nt][3] + b1;
            *(float2*)(C + (long long)r * Cdim + col)       = v0;
            *(float2*)(C + (long long)(r + 8) * Cdim + col) = v1;
        }
    }
}

// ---------------- fused attention v3: q-tile 128, 8 warps, double-buffered K -------
constexpr int FA_NIT  = Sk / 64;                 // 40
constexpr int F3_QH   = 0;                        // Q hi: 128 x 272B
constexpr int F3_QL   = 34816;
constexpr int F3_K0   = 69632;                    // 2 K buffers, each (hi+lo) 2x17408
constexpr int F3_KBUF = 34816;
constexpr int F3_KLOF = 17408;                    // lo offset within K buffer
constexpr int F3_VH   = 139264;                   // V^T hi: 128 x 144B
constexpr int F3_VL   = 157696;
constexpr int F3_YB   = 176128;                   // yb: 512 floats
constexpr int FA_SMEM = 178176;

__global__ __launch_bounds__(256, 1)
void fused_attn(const __nv_bfloat16* __restrict__ Qh, const __nv_bfloat16* __restrict__ Ql,
                const __nv_bfloat16* __restrict__ Kh, const __nv_bfloat16* __restrict__ Kl,
                const __nv_bfloat16* __restrict__ Vth, const __nv_bfloat16* __restrict__ Vtl,
                const float* __restrict__ ytw,
                __nv_bfloat16* __restrict__ Obh, __nv_bfloat16* __restrict__ Obl)
{
    extern __shared__ char smem[];
    const uint32_t sb = smem_u32(smem);

    const int z  = blockIdx.y;
    const int q0 = blockIdx.x * 128;
    const int b  = z / Hn;
    const int h  = z % Hn;

    const int tid  = threadIdx.x;
    const int lane = tid & 31;
    const int wid  = tid >> 5;            // 0..7
    const int g    = lane >> 2;
    const int tg   = lane & 3;
    const int wm   = wid * 16;            // warp's q-row base (0..112)

    const __nv_bfloat16* Qhp = Qh + (long long)z * Nq * HDim;
    const __nv_bfloat16* Qlp = Ql + (long long)z * Nq * HDim;
    const __nv_bfloat16* Khp = Kh + (long long)z * Sk * HDim;
    const __nv_bfloat16* Klp = Kl + (long long)z * Sk * HDim;
    const __nv_bfloat16* Vhp = Vth + (long long)z * HDim * Sk;
    const __nv_bfloat16* Vlp = Vtl + (long long)z * HDim * Sk;

    // y bias
    float* sYB = (float*)(smem + F3_YB);
    #pragma unroll
    for (int j = 0; j < 2; j++) {
        const int i = tid + j * 256;
        sYB[i] = logf(fmaxf(ytw[b * My + i], 1e-4f));
    }

    // group 1: Q (128 rows x 16 segs, hi+lo)
    #pragma unroll
    for (int j = 0; j < 8; j++) {
        const int id = tid + j * 256, r = id >> 4, c = id & 15;
        cp16(sb + F3_QH + r * 272 + c * 16, Qhp + (long long)(q0 + r) * HDim + c * 8);
        cp16(sb + F3_QL + r * 272 + c * 16, Qlp + (long long)(q0 + r) * HDim + c * 8);
    }
    CP_COMMIT();
    // group 2: K(0) into buffer 0
    #pragma unroll
    for (int j = 0; j < 4; j++) {
        const int id = tid + j * 256, r = id >> 4, c = id & 15;
        cp16(sb + F3_K0 +           r * 272 + c * 16, Khp + (long long)r * HDim + c * 8);
        cp16(sb + F3_K0 + F3_KLOF + r * 272 + c * 16, Klp + (long long)r * HDim + c * 8);
    }
    CP_COMMIT();

    float oacc[16][4];
    #pragma unroll
    for (int i = 0; i < 16; i++)
        #pragma unroll
        for (int r = 0; r < 4; r++) oacc[i][r] = 0.f;
    float rowsum0 = 0.f, rowsum1 = 0.f;

    for (int it = 0; it < FA_NIT; it++) {
        __syncthreads();                   // K(it+1) buffer + V buffer free

        // group: K(it+1) prefetch (empty group on last iteration)
        if (it + 1 < FA_NIT) {
            const uint32_t kb = sb + F3_K0 + ((it + 1) & 1) * F3_KBUF;
            const int sblk = (it + 1) * 64;
            #pragma unroll
            for (int j = 0; j < 4; j++) {
                const int id = tid + j * 256, r = id >> 4, c = id & 15;
                cp16(kb +           r * 272 + c * 16, Khp + (long long)(sblk + r) * HDim + c * 8);
                cp16(kb + F3_KLOF + r * 272 + c * 16, Klp + (long long)(sblk + r) * HDim + c * 8);
            }
        }
        CP_COMMIT();
        // group: V(it)
        #pragma unroll
        for (int j = 0; j < 4; j++) {
            const int id = tid + j * 256, d = id >> 3, c = id & 7;
            cp16(sb + F3_VH + d * 144 + c * 16, Vhp + (long long)d * Sk + it * 64 + c * 8);
            cp16(sb + F3_VL + d * 144 + c * 16, Vlp + (long long)d * Sk + it * 64 + c * 8);
        }
        CP_COMMIT();

        CP_WAIT(2);                        // everything older than {K(it+1), V(it)} done -> K(it) ready
        __syncthreads();

        // ---- S phase: S[16 x 64] = Q K(it)^T (split, 3 products) ----
        const uint32_t kcur = sb + F3_K0 + (it & 1) * F3_KBUF;
        float sacc[8][4];
        #pragma unroll
        for (int i = 0; i < 8; i++)
            #pragma unroll
            for (int r = 0; r < 4; r++) sacc[i][r] = 0.f;

        #pragma unroll
        for (int kk = 0; kk < 8; kk++) {
            const int cb = kk * 32 + tg * 4;
            uint32_t qh_[4], ql_[4], kh_[8][2], kl_[8][2];
            {
                const char* p = smem + F3_QH + (wm + g) * 272 + cb;
                qh_[0] = *(const uint32_t*)(p);
                qh_[1] = *(const uint32_t*)(p + 8 * 272);
                qh_[2] = *(const uint32_t*)(p + 16);
                qh_[3] = *(const uint32_t*)(p + 8 * 272 + 16);
                const char* q = p + (F3_QL - F3_QH);
                ql_[0] = *(const uint32_t*)(q);
                ql_[1] = *(const uint32_t*)(q + 8 * 272);
                ql_[2] = *(const uint32_t*)(q + 16);
                ql_[3] = *(const uint32_t*)(q + 8 * 272 + 16);
            }
            #pragma unroll
            for (int nt = 0; nt < 8; nt++) {
                const char* p = (const char*)smem + (kcur - sb) + (nt * 8 + g) * 272 + cb;
                kh_[nt][0] = *(const uint32_t*)(p);
                kh_[nt][1] = *(const uint32_t*)(p + 16);
                kl_[nt][0] = *(const uint32_t*)(p + F3_KLOF);
                kl_[nt][1] = *(const uint32_t*)(p + F3_KLOF + 16);
            }
            #pragma unroll
            for (int nt = 0; nt < 8; nt++) {
                mma_bf16(sacc[nt], qh_, kh_[nt]);
                mma_bf16(sacc[nt], qh_, kl_[nt]);
                mma_bf16(sacc[nt], ql_, kh_[nt]);
            }
        }

        // ---- exp (+scale +bias) -> PV A-fragments in registers (hi+lo) ----
        uint32_t ph_[4][4], pl_[4][4];
        #pragma unroll
        for (int nt = 0; nt < 8; nt++) {
            const int col0 = nt * 8 + 2 * tg;
            const int gc   = it * 64 + col0;
            float b0 = 0.f, b1 = 0.f;
            if (gc >= Nq) { b0 = sYB[gc - Nq]; b1 = sYB[gc - Nq + 1]; }
            const float p0 = __expf(sacc[nt][0] * SCALE + b0);
            const float p1 = __expf(sacc[nt][1] * SCALE + b1);
            const float p2 = __expf(sacc[nt][2] * SCALE + b0);
            const float p3 = __expf(sacc[nt][3] * SCALE + b1);
            rowsum0 += p0 + p1;
            rowsum1 += p2 + p3;
            const int j  = nt >> 1;
            const int rb = (nt & 1) * 2;
            const uint32_t h01 = pack_bf2(p0, p1);
            const uint32_t h23 = pack_bf2(p2, p3);
            ph_[j][rb + 0] = h01;
            ph_[j][rb + 1] = h23;
            const __nv_bfloat162 hb01 = *(const __nv_bfloat162*)&h01;
            const __nv_bfloat162 hb23 = *(const __nv_bfloat162*)&h23;
            pl_[j][rb + 0] = pack_bf2(p0 - __bfloat162float(hb01.x), p1 - __bfloat162float(hb01.y));
            pl_[j][rb + 1] = pack_bf2(p2 - __bfloat162float(hb23.x), p3 - __bfloat162float(hb23.y));
        }

        CP_WAIT(1);                        // V(it) done (K(it+1) still in flight)
        __syncthreads();                   // make all threads' V copies visible

        // ---- PV phase: O[16 x 128] += P V(it) (split, 3 products) ----
        #pragma unroll
        for (int j = 0; j < 4; j++) {
            const int cb = j * 32 + tg * 4;
            #pragma unroll
            for (int nt = 0; nt < 16; nt++) {
                uint32_t vh_[2], vl_[2];
                const char* p = smem + F3_VH + (nt * 8 + g) * 144 + cb;
                vh_[0] = *(const uint32_t*)(p);
                vh_[1] = *(const uint32_t*)(p + 16);
                vl_[0] = *(const uint32_t*)(p + (F3_VL - F3_VH));
                vl_[1] = *(const uint32_t*)(p + (F3_VL - F3_VH) + 16);
                mma_bf16(oacc[nt], ph_[j], vh_);
                mma_bf16(oacc[nt], ph_[j], vl_);
                mma_bf16(oacc[nt], pl_[j], vh_);
            }
        }
    }

    // ---- rowsum reduce within tg quad ----
    rowsum0 += __shfl_xor_sync(0xffffffffu, rowsum0, 1);
    rowsum0 += __shfl_xor_sync(0xffffffffu, rowsum0, 2);
    rowsum1 += __shfl_xor_sync(0xffffffffu, rowsum1, 1);
    rowsum1 += __shfl_xor_sync(0xffffffffu, rowsum1, 2);
    const float inv0 = 1.f / rowsum0;
    const float inv1 = 1.f / rowsum1;

    // ---- epilogue ----
    const int r = wm + g;
    #pragma unroll
    for (int nt = 0; nt < 16; nt++) {
        const int col = nt * 8 + 2 * tg;
        const long long o0 = ((long long)b * Nq + q0 + r) * Cdim + h * HDim + col;
        const long long o1 = o0 + 8LL * Cdim;
        const float a0 = oacc[nt][0] * inv0, a1 = oacc[nt][1] * inv0;
        const float a2 = oacc[nt][2] * inv1, a3 = oacc[nt][3] * inv1;
        __nv_bfloat162 hv, lv;
        hv.x = __float2bfloat16(a0); hv.y = __float2bfloat16(a1);
        lv.x = __float2bfloat16(a0 - __bfloat162float(hv.x));
        lv.y = __float2bfloat16(a1 - __bfloat162float(hv.y));
        *(__nv_bfloat162*)(Obh + o0) = hv;
        *(__nv_bfloat162*)(Obl + o0) = lv;
        hv.x = __float2bfloat16(a2); hv.y = __float2bfloat16(a3);
        lv.x = __float2bfloat16(a2 - __bfloat162float(hv.x));
        lv.y = __float2bfloat16(a3 - __bfloat162float(hv.y));
        *(__nv_bfloat162*)(Obh + o1) = hv;
        *(__nv_bfloat16*)0; // no-op
        *(__nv_bfloat162*)(Obl + o1) = lv;
    }
}

// ---------------- fp32 -> split bf16, two tensors in one launch ----------------
__global__ void cvt_split2(const float* __restrict__ s1, __nv_bfloat16* __restrict__ h1,
                           __nv_bfloat16* __restrict__ l1, long long n1,
                           const float* __restrict__ s2, __nv_bfloat16* __restrict__ h2,
                           __nv_bfloat16* __restrict__ l2, long long n2)
{
    long long i = ((long long)blockIdx.x * blockDim.x + threadIdx.x) * 4;
    const float* src; __nv_bfloat16 *h, *l;
    if (i < n1) { src = s1; h = h1; l = l1; }
    else        { i -= n1; if (i >= n2) return; src = s2; h = h2; l = l2; }
    const float4 v = *(const float4*)(src + i);
    __nv_bfloat16 hb[4], lb[4];
    const float f[4] = {v.x, v.y, v.z, v.w};
    #pragma unroll
    for (int j = 0; j < 4; j++) {
        hb[j] = __float2bfloat16(f[j]);
        lb[j] = __float2bfloat16(f[j] - __bfloat162float(hb[j]));
    }
    *(uint2*)(h + i) = *(uint2*)hb;
    *(uint2*)(l + i) = *(uint2*)lb;
}

// ---------------- fp32 [K][N] -> split bf16 transposed [N][K]; 2 weights packed ----
constexpr int WQ_BLKS = (3 * Cdim / 32) * (Cdim / 32);   // 6912
constexpr int WK_BLKS = (2 * Cdim / 32) * (Cdim / 32);   // 4608

__global__ void cvt_split_T2(const float* __restrict__ W1, __nv_bfloat16* __restrict__ h1,
                             __nv_bfloat16* __restrict__ l1,
                             const float* __restrict__ W2, __nv_bfloat16* __restrict__ h2,
                             __nv_bfloat16* __restrict__ l2)
{
    __shared__ float tile[32][33];
    const int tid = threadIdx.x;
    const int tx = tid & 31;
    const int ty = tid >> 5;

    const float* W; __nv_bfloat16 *h, *l;
    int N, n0, k0;
    int bid = blockIdx.x;
    if (bid < WQ_BLKS) {
        W = W1; h = h1; l = l1; N = 3 * Cdim;
        n0 = (bid % (N / 32)) * 32;  k0 = (bid / (N / 32)) * 32;
    } else {
        bid -= WQ_BLKS;
        W = W2; h = h2; l = l2; N = 2 * Cdim;
        n0 = (bid % (N / 32)) * 32;  k0 = (bid / (N / 32)) * 32;
    }

    #pragma unroll
    for (int i = ty; i < 32; i += 8)
        tile[i][tx] = W[(long long)(k0 + i) * N + n0 + tx];
    __syncthreads();
    #pragma unroll
    for (int i = ty; i < 32; i += 8) {
        const float v = tile[tx][i];
        const __nv_bfloat16 hb = __float2bfloat16(v);
        const __nv_bfloat16 lb = __float2bfloat16(v - __bfloat162float(hb));
        const long long o = (long long)(n0 + i) * Cdim + k0 + tx;
        h[o] = hb; l[o] = lb;
    }
}

// ---------------- single-weight transposed split (Wproj) ----------------
__global__ void cvt_split_T(const float* __restrict__ W, __nv_bfloat16* __restrict__ h,
                            __nv_bfloat16* __restrict__ l, int K, int N)
{
    __shared__ float tile[32][33];
    const int k0 = blockIdx.y * 32;
    const int n0 = blockIdx.x * 32;
    const int tx = threadIdx.x;
    const int ty = threadIdx.y;
    #pragma unroll
    for (int i = ty; i < 32; i += 8)
        tile[i][tx] = W[(long long)(k0 + i) * N + n0 + tx];
    __syncthreads();
    #pragma unroll
    for (int i = ty; i < 32; i += 8) {
        const float v = tile[tx][i];
        const __nv_bfloat16 hb = __float2bfloat16(v);
        const __nv_bfloat16 lb = __float2bfloat16(v - __bfloat162float(hb));
        const long long o = (long long)(n0 + i) * K + k0 + tx;
        h[o] = hb; l[o] = lb;
    }
}

// ---------------- V: fp32 [bh][s][d] -> split bf16 transposed [bh][d][s] ----------
__global__ void v_transpose_split(const float* __restrict__ Vb,
                                  __nv_bfloat16* __restrict__ Vth,
                                  __nv_bfloat16* __restrict__ Vtl)
{
    __shared__ float tile[32][33];
    const int z  = blockIdx.z;
    const int ss0 = blockIdx.x * 32;
    const int dd0 = blockIdx.y * 32;
    const int tx = threadIdx.x;
    const int ty = threadIdx.y;
    const long long ib = (long long)z * Sk * HDim;
    const long long ob = (long long)z * HDim * Sk;
    #pragma unroll
    for (int i = ty; i < 32; i += 8)
        tile[i][tx] = Vb[ib + (long long)(ss0 + i) * HDim + dd0 + tx];
    __syncthreads();
    #pragma unroll
    for (int i = ty; i < 32; i += 8) {
        const float v = tile[tx][i];
        const __nv_bfloat16 hb = __float2bfloat16(v);
        const __nv_bfloat16 lb = __float2bfloat16(v - __bfloat162float(hb));
        const long long o = ob + (long long)(dd0 + i) * Sk + ss0 + tx;
        Vth[o] = hb; Vtl[o] = lb;
    }
}

// ---------------- warp reduction helpers ----------------
__device__ __forceinline__ float warpSum(float v) {
    #pragma unroll
    for (int o = 16; o > 0; o >>= 1) v += __shfl_xor_sync(0xffffffffu, v, o);
    return v;
}

// ---------------- QKV postprocess ----------------
__global__ void qkv_post(const float* __restrict__ qkv, const float* __restrict__ pos,
                         const float* __restrict__ qw, const float* __restrict__ kw,
                         __nv_bfloat16* __restrict__ Qh, __nv_bfloat16* __restrict__ Ql,
                         __nv_bfloat16* __restrict__ Kh, __nv_bfloat16* __restrict__ Kl,
                         float* __restrict__ Vb)
{
    const int idx = blockIdx.x;
    const int h  = idx % Hn;
    const int bn = idx / Hn;
    const int n  = bn % Nq;
    const int b  = bn / Nq;
    const int d  = threadIdx.x;

    const float* row = qkv + (long long)bn * (3 * Cdim);
    const float qv = row[h * HDim + d];
    const float kv = row[Cdim + h * HDim + d];
    const float vv = row[2 * Cdim + h * HDim + d];

    __shared__ float sred[8];
    __shared__ float qs[HDim], ks[HDim];

    const float sq = warpSum(qv * qv);
    const float sk = warpSum(kv * kv);
    const int lane = d & 31, w = d >> 5;
    if (lane == 0) { sred[w] = sq; sred[4 + w] = sk; }
    __syncthreads();
    const float sumq = sred[0] + sred[1] + sred[2] + sred[3];
    const float sumk = sred[4] + sred[5] + sred[6] + sred[7];
    const float rq = rsqrtf(sumq * (1.0f / HDim) + EPSV);
    const float rk = rsqrtf(sumk * (1.0f / HDim) + EPSV);
    const float qn = qw[d] * qv * rq;
    const float kn = kw[d] * kv * rk;
    qs[d] = qn; ks[d] = kn;
    __syncthreads();

    float qo = qn, ko = kn;
    if (d < RD) {
        const int j = d & 31;
        const float c = pos[(n * 32 + j) * 2 + 0];
        const float s = pos[(n * 32 + j) * 2 + 1];
        if (d < RD / 2) { qo = qs[d] * c - qs[d + 32] * s;  ko = ks[d] * c - ks[d + 32] * s; }
        else            { qo = qs[d - 32] * s + qs[d] * c;  ko = ks[d - 32] * s + ks[d] * c; }
    }
    const long long qi = (((long long)(b * Hn + h)) * Nq + n) * HDim + d;
    const long long ki = (((long long)(b * Hn + h)) * Sk + n) * HDim + d;
    split_write(qo, Qh, Ql, qi);
    split_write(ko, Kh, Kl, ki);
    Vb[ki] = vv;
}

// ---------------- KV(y) postprocess ----------------
__global__ void kv_post(const float* __restrict__ kvr, const float* __restrict__ kw,
                        __nv_bfloat16* __restrict__ Kh, __nv_bfloat16* __restrict__ Kl,
                        float* __restrict__ Vb)
{
    const int idx = blockIdx.x;
    const int h  = idx % Hn;
    const int bm = idx / Hn;
    const int m  = bm % My;
    const int b  = bm / My;
    const int d  = threadIdx.x;

    const float* row = kvr + (long long)bm * (2 * Cdim);
    const float kv = row[h * HDim + d];
    const float vv = row[Cdim + h * HDim + d];

    __shared__ float sred[4];
    const float sk = warpSum(kv * kv);
    if ((d & 31) == 0) sred[d >> 5] = sk;
    __syncthreads();
    const float sumk = sred[0] + sred[1] + sred[2] + sred[3];
    const float rk = rsqrtf(sumk * (1.0f / HDim) + EPSV);
    const float kn = kw[d] * kv * rk;

    const long long ki = (((long long)(b * Hn + h)) * Sk + (Nq + m)) * HDim + d;
    split_write(kn, Kh, Kl, ki);
    Vb[ki] = vv;
}

// ---------------- launch ----------------
extern "C" void kernel_launch(void* const* d_in, const int* in_sizes, int n_in,
                              void* d_out, int out_size)
{
    const float* x    = (const float*)d_in[0];
    const float* y    = (const float*)d_in[1];
    const float* pos  = (const float*)d_in[2];
    const float* ytw  = (const float*)d_in[3];
    const float* Wqkv = (const float*)d_in[4];
    const float* Wkv  = (const float*)d_in[5];
    const float* qw   = (const float*)d_in[6];
    const float* kw   = (const float*)d_in[7];
    const float* Wproj= (const float*)d_in[8];
    const float* bproj= (const float*)d_in[9];
    float* out = (float*)d_out;

    float *qkv, *kvr, *Vb;
    cudaGetSymbolAddress((void**)&qkv, g_qkv);
    cudaGetSymbolAddress((void**)&kvr, g_kvr);
    cudaGetSymbolAddress((void**)&Vb,  g_Vb);

    __nv_bfloat16 *xh,*xl,*yh,*yl,*Wqh,*Wql,*Wkh,*Wkl,*Wph,*Wpl,*Obh,*Obl;
    __nv_bfloat16 *Qh,*Ql,*Kh,*Kl,*Vth,*Vtl;
    cudaGetSymbolAddress((void**)&xh, g_xh);   cudaGetSymbolAddress((void**)&xl, g_xl);
    cudaGetSymbolAddress((void**)&yh, g_yh);   cudaGetSymbolAddress((void**)&yl, g_yl);
    cudaGetSymbolAddress((void**)&Wqh, g_Wqkvh); cudaGetSymbolAddress((void**)&Wql, g_Wqkvl);
    cudaGetSymbolAddress((void**)&Wkh, g_Wkvh);  cudaGetSymbolAddress((void**)&Wkl, g_Wkvl);
    cudaGetSymbolAddress((void**)&Wph, g_Wph);   cudaGetSymbolAddress((void**)&Wpl, g_Wpl);
    cudaGetSymbolAddress((void**)&Obh, g_Obh);   cudaGetSymbolAddress((void**)&Obl, g_Obl);
    cudaGetSymbolAddress((void**)&Qh, g_Qh);     cudaGetSymbolAddress((void**)&Ql, g_Ql);
    cudaGetSymbolAddress((void**)&Kh, g_Kh);     cudaGetSymbolAddress((void**)&Kl, g_Kl);
    cudaGetSymbolAddress((void**)&Vth, g_Vth);   cudaGetSymbolAddress((void**)&Vtl, g_Vtl);

    cudaFuncSetAttribute(mma_gemm_fused, cudaFuncAttributeMaxDynamicSharedMemorySize, MM_SMEM_B);
    cudaFuncSetAttribute(mma_gemm_proj,  cudaFuncAttributeMaxDynamicSharedMemorySize, MM_SMEM_B);
    cudaFuncSetAttribute(fused_attn, cudaFuncAttributeMaxDynamicSharedMemorySize, FA_SMEM);

    // 0) conversions (packed launches)
    const long long nx = (long long)Bsz * Nq * Cdim;
    const long long ny = (long long)Bsz * My * Cdim;
    cvt_split2<<<(int)(((nx + ny) / 4 + 255) / 256), 256>>>(x, xh, xl, nx, y, yh, yl, ny);
    cvt_split_T2<<<WQ_BLKS + WK_BLKS, 256>>>(Wqkv, Wqh, Wql, Wkv, Wkh, Wkl);
    cvt_split_T<<<dim3(Cdim / 32, Cdim / 32), dim3(32, 8)>>>(Wproj, Wph, Wpl, Cdim, Cdim);

    // 1+2) fused QKV + KV weight GEMM
    mma_gemm_fused<<<FUSED_CTAS, 256, MM_SMEM_B>>>(
        xh, xl, Wqh, Wql, qkv, yh, yl, Wkh, Wkl, kvr);

    // 3) postprocess
    qkv_post<<<Bsz * Nq * Hn, HDim>>>(qkv, pos, qw, kw, Qh, Ql, Kh, Kl, Vb);
    kv_post<<<Bsz * My * Hn, HDim>>>(kvr, kw, Kh, Kl, Vb);
    v_transpose_split<<<dim3(Sk / 32, HDim / 32, Bsz * Hn), dim3(32, 8)>>>(Vb, Vth, Vtl);

    // 4-6) fused attention v3 (q-tile 128, 256 threads, double-buffered K)
    fused_attn<<<dim3(Nq / 128, Bsz * Hn), 256, FA_SMEM>>>(
        Qh, Ql, Kh, Kl, Vth, Vtl, ytw, Obh, Obl);

    // 7) out = O @ Wproj + bproj
    mma_gemm_proj<<<dim3(Cdim / 128, Bsz * Nq / 128), 256, MM_SMEM_B>>>(
        Obh, Obl, Wph, Wpl, out, bproj);
}

// round 14
// speedup vs baseline: 1.5695x; 1.2144x over previous
#include <cuda_runtime.h>
#include <cuda_bf16.h>
#include <cuda_fp16.h>
#include <math.h>
#include <cstdint>

// ---------------- problem constants ----------------
constexpr int Bsz  = 2;
constexpr int Nq   = 2048;
constexpr int My   = 512;
constexpr int Cdim = 1536;
constexpr int Hn   = 12;
constexpr int HDim = 128;          // Cdim / Hn
constexpr int RD   = 64;
constexpr int Sk   = Nq + My;      // 2560
constexpr float EPSV  = 1e-6f;
constexpr float SCALE = 0.08838834764831845f;   // 1/sqrt(128)

// ---------------- scratch (static device arrays; no allocs allowed) ----------------
__device__ float g_qkv [(long long)Bsz * Nq * 3 * Cdim];
__device__ float g_kvr [(long long)Bsz * My * 2 * Cdim];
__device__ float g_Vb  [(long long)Bsz * Hn * Sk * HDim];   // V fp32 [bh][s][d]

// fp16 operands for weight GEMMs (activations single, weights split hi/lo)
__device__ __half g_xh [(long long)Bsz * Nq * Cdim];
__device__ __half g_yh [(long long)Bsz * My * Cdim];
__device__ __half g_Wqkvh[(long long)3 * Cdim * Cdim];
__device__ __half g_Wqkvl[(long long)3 * Cdim * Cdim];
__device__ __half g_Wkvh [(long long)2 * Cdim * Cdim];
__device__ __half g_Wkvl [(long long)2 * Cdim * Cdim];
__device__ __half g_Wph  [(long long)Cdim * Cdim];
__device__ __half g_Wpl  [(long long)Cdim * Cdim];
__device__ __half g_Oh   [(long long)Bsz * Nq * Cdim];      // attention output (single fp16)
// attention split operands (bf16, 3-product path — unchanged)
__device__ __nv_bfloat16 g_Qh [(long long)Bsz * Hn * Nq * HDim];
__device__ __nv_bfloat16 g_Ql [(long long)Bsz * Hn * Nq * HDim];
__device__ __nv_bfloat16 g_Kh [(long long)Bsz * Hn * Sk * HDim];
__device__ __nv_bfloat16 g_Kl [(long long)Bsz * Hn * Sk * HDim];
__device__ __nv_bfloat16 g_Vth[(long long)Bsz * Hn * HDim * Sk];  // V^T [bh][d][s]
__device__ __nv_bfloat16 g_Vtl[(long long)Bsz * Hn * HDim * Sk];

// ---------------- small PTX helpers (baseline PTX only) ----------------
__device__ __forceinline__ uint32_t smem_u32(const void* p) {
    uint32_t a;
    asm("{ .reg .u64 t; cvta.to.shared.u64 t, %1; cvt.u32.u64 %0, t; }" : "=r"(a) : "l"(p));
    return a;
}
__device__ __forceinline__ void cp16(uint32_t dst, const void* src) {
    asm volatile("cp.async.cg.shared.global [%0], [%1], 16;" :: "r"(dst), "l"(src));
}
#define CP_COMMIT()  asm volatile("cp.async.commit_group;" ::: "memory")
#define CP_WAIT(n)   asm volatile("cp.async.wait_group %0;" :: "n"(n) : "memory")

__device__ __forceinline__ void mma_bf16(float d[4], const uint32_t a[4], const uint32_t b[2]) {
    asm volatile(
        "mma.sync.aligned.m16n8k16.row.col.f32.bf16.bf16.f32 "
        "{%0,%1,%2,%3}, {%4,%5,%6,%7}, {%8,%9}, {%0,%1,%2,%3};"
        : "+f"(d[0]), "+f"(d[1]), "+f"(d[2]), "+f"(d[3])
        : "r"(a[0]), "r"(a[1]), "r"(a[2]), "r"(a[3]), "r"(b[0]), "r"(b[1]));
}
__device__ __forceinline__ void mma_fp16(float d[4], const uint32_t a[4], const uint32_t b[2]) {
    asm volatile(
        "mma.sync.aligned.m16n8k16.row.col.f32.f16.f16.f32 "
        "{%0,%1,%2,%3}, {%4,%5,%6,%7}, {%8,%9}, {%0,%1,%2,%3};"
        : "+f"(d[0]), "+f"(d[1]), "+f"(d[2]), "+f"(d[3])
        : "r"(a[0]), "r"(a[1]), "r"(a[2]), "r"(a[3]), "r"(b[0]), "r"(b[1]));
}
__device__ __forceinline__ void split_write(float v, __nv_bfloat16* h, __nv_bfloat16* l, long long idx) {
    const __nv_bfloat16 hb = __float2bfloat16(v);
    h[idx] = hb;
    l[idx] = __float2bfloat16(v - __bfloat162float(hb));
}
__device__ __forceinline__ uint32_t pack_bf2(float a, float b) {
    __nv_bfloat162 v; v.x = __float2bfloat16(a); v.y = __float2bfloat16(b);
    return *(uint32_t*)&v;
}

// ---------------- 128x128 fp16 2-product HMMA GEMM core ----------------
// C[M,N] = A[M,K] @ W[K,N], A single fp16 [M,K]; W split fp16 (Wh+Wl) [N,K] transposed.
// D = A*Wh + A*Wl (W exact to 2^-22; only A rounding 2^-11 remains).
constexpr int MM_STRIDE_B = 80;
constexpr int MM_ARR_B    = 128 * MM_STRIDE_B;   // 10240
constexpr int MM_BUF_B    = 3 * MM_ARR_B;        // A, Bh, Bl = 30720
constexpr int MM_SMEM_B   = 2 * MM_BUF_B;        // 61440

constexpr int QKV_COLT = 3 * Cdim / 128;     // 36
constexpr int QKV_CTAS = QKV_COLT * (Bsz * Nq / 128);   // 1152
constexpr int KV_COLT  = 2 * Cdim / 128;     // 24
constexpr int FUSED_CTAS = QKV_CTAS + KV_COLT * (Bsz * My / 128);  // 1344

#define MM_BODY(AP, BhP, BlP)                                                               \
    const int s0   = tid * 2;                                                               \
    const int row_s0 = s0 >> 2,  q_s0 = s0 & 3;                                             \
    const int row_s1 = (s0 + 1) >> 2, q_s1 = (s0 + 1) & 3;                                  \
    auto stage = [&](int c, int buf) {                                                      \
        const long long k0 = (long long)c * 32;                                             \
        const uint32_t db = sbase + buf * MM_BUF_B;                                         \
        {                                                                                   \
            const long long ga = (long long)(row0 + row_s0) * Cdim + k0 + q_s0 * 8;         \
            const long long gb = (long long)(col0 + row_s0) * Cdim + k0 + q_s0 * 8;         \
            const uint32_t  so = row_s0 * MM_STRIDE_B + q_s0 * 16;                          \
            cp16(db + 0 * MM_ARR_B + so, (AP) + ga);                                        \
            cp16(db + 1 * MM_ARR_B + so, (BhP) + gb);                                       \
            cp16(db + 2 * MM_ARR_B + so, (BlP) + gb);                                       \
        }                                                                                   \
        {                                                                                   \
            const long long ga = (long long)(row0 + row_s1) * Cdim + k0 + q_s1 * 8;         \
            const long long gb = (long long)(col0 + row_s1) * Cdim + k0 + q_s1 * 8;         \
            const uint32_t  so = row_s1 * MM_STRIDE_B + q_s1 * 16;                          \
            cp16(db + 0 * MM_ARR_B + so, (AP) + ga);                                        \
            cp16(db + 1 * MM_ARR_B + so, (BhP) + gb);                                       \
            cp16(db + 2 * MM_ARR_B + so, (BlP) + gb);                                       \
        }                                                                                   \
    };                                                                                      \
    float acc[4][4][4];                                                                     \
    _Pragma("unroll")                                                                       \
    for (int i = 0; i < 4; i++)                                                             \
        _Pragma("unroll")                                                                   \
        for (int j = 0; j < 4; j++)                                                         \
            _Pragma("unroll")                                                               \
            for (int r = 0; r < 4; r++) acc[i][j][r] = 0.f;                                 \
    constexpr int nch = Cdim / 32;                                                          \
    stage(0, 0);                                                                            \
    CP_COMMIT();                                                                            \
    for (int c = 0; c < nch; c++) {                                                         \
        if (c + 1 < nch) { stage(c + 1, (c + 1) & 1); CP_COMMIT(); CP_WAIT(1); }            \
        else             { CP_WAIT(0); }                                                    \
        __syncthreads();                                                                    \
        const char* bp = smem + (c & 1) * MM_BUF_B;                                         \
        const char* pA  = bp;                                                               \
        const char* pBh = bp + 1 * MM_ARR_B;                                                \
        const char* pBl = bp + 2 * MM_ARR_B;                                                \
        _Pragma("unroll")                                                                   \
        for (int kk = 0; kk < 2; kk++) {                                                    \
            const int cbyte = (kk * 16 + 2 * tg) * 2;                                       \
            uint32_t av[4][4], bh[4][2], bl[4][2];                                          \
            _Pragma("unroll")                                                               \
            for (int mt = 0; mt < 4; mt++) {                                                \
                const int r = wm + mt * 16 + g;                                             \
                av[mt][0] = *(const uint32_t*)(pA + r * MM_STRIDE_B + cbyte);               \
                av[mt][1] = *(const uint32_t*)(pA + (r + 8) * MM_STRIDE_B + cbyte);         \
                av[mt][2] = *(const uint32_t*)(pA + r * MM_STRIDE_B + cbyte + 16);          \
                av[mt][3] = *(const uint32_t*)(pA + (r + 8) * MM_STRIDE_B + cbyte + 16);    \
            }                                                                               \
            _Pragma("unroll")                                                               \
            for (int nt = 0; nt < 4; nt++) {                                                \
                const int n = wn + nt * 8 + g;                                              \
                bh[nt][0] = *(const uint32_t*)(pBh + n * MM_STRIDE_B + cbyte);              \
                bh[nt][1] = *(const uint32_t*)(pBh + n * MM_STRIDE_B + cbyte + 16);         \
                bl[nt][0] = *(const uint32_t*)(pBl + n * MM_STRIDE_B + cbyte);              \
                bl[nt][1] = *(const uint32_t*)(pBl + n * MM_STRIDE_B + cbyte + 16);         \
            }                                                                               \
            _Pragma("unroll")                                                               \
            for (int mt = 0; mt < 4; mt++)                                                  \
                _Pragma("unroll")                                                           \
                for (int nt = 0; nt < 4; nt++) {                                            \
                    mma_fp16(acc[mt][nt], av[mt], bh[nt]);                                  \
                    mma_fp16(acc[mt][nt], av[mt], bl[nt]);                                  \
                }                                                                           \
        }                                                                                   \
        __syncthreads();                                                                    \
    }

// ---- fused QKV + KV weight GEMM ----
__global__ __launch_bounds__(256, 2)
void mma_gemm_fused(const __half* __restrict__ xh,
                    const __half* __restrict__ Wqh, const __half* __restrict__ Wql,
                    float* __restrict__ Cq,
                    const __half* __restrict__ yh,
                    const __half* __restrict__ Wkh, const __half* __restrict__ Wkl,
                    float* __restrict__ Ck)
{
    extern __shared__ char smem[];
    const uint32_t sbase = smem_u32(smem);

    const int tid  = threadIdx.x;
    const int lane = tid & 31;
    const int wid  = tid >> 5;
    const int wm   = (wid >> 2) * 64;
    const int wn   = (wid & 3) * 32;
    const int g    = lane >> 2;
    const int tg   = lane & 3;

    const int bid = blockIdx.x;
    const __half *A, *Bh, *Bl;
    float* C;
    int row0, col0, ldc;
    if (bid < QKV_CTAS) {
        A = xh; Bh = Wqh; Bl = Wql; C = Cq;
        row0 = (bid / QKV_COLT) * 128;
        col0 = (bid % QKV_COLT) * 128;
        ldc  = 3 * Cdim;
    } else {
        const int b2 = bid - QKV_CTAS;
        A = yh; Bh = Wkh; Bl = Wkl; C = Ck;
        row0 = (b2 / KV_COLT) * 128;
        col0 = (b2 % KV_COLT) * 128;
        ldc  = 2 * Cdim;
    }

    MM_BODY(A, Bh, Bl)

    #pragma unroll
    for (int nt = 0; nt < 4; nt++) {
        const int col = col0 + wn + nt * 8 + 2 * tg;
        #pragma unroll
        for (int mt = 0; mt < 4; mt++) {
            const int r = row0 + wm + mt * 16 + g;
            float2 v0, v1;
            v0.x = acc[mt][nt][0]; v0.y = acc[mt][nt][1];
            v1.x = acc[mt][nt][2]; v1.y = acc[mt][nt][3];
            *(float2*)(C + (long long)r * ldc + col)       = v0;
            *(float2*)(C + (long long)(r + 8) * ldc + col) = v1;
        }
    }
}

// ---- proj GEMM (bias): A = attention O (single fp16), B = Wproj split ----
__global__ __launch_bounds__(256, 2)
void mma_gemm_proj(const __half* __restrict__ Ap,
                   const __half* __restrict__ Bhp, const __half* __restrict__ Blp,
                   float* __restrict__ C, const float* __restrict__ bias)
{
    extern __shared__ char smem[];
    const uint32_t sbase = smem_u32(smem);

    const int tid  = threadIdx.x;
    const int lane = tid & 31;
    const int wid  = tid >> 5;
    const int row0 = blockIdx.y * 128;
    const int col0 = blockIdx.x * 128;
    const int wm   = (wid >> 2) * 64;
    const int wn   = (wid & 3) * 32;
    const int g    = lane >> 2;
    const int tg   = lane & 3;

    MM_BODY(Ap, Bhp, Blp)

    #pragma unroll
    for (int nt = 0; nt < 4; nt++) {
        const int col = col0 + wn + nt * 8 + 2 * tg;
        const float b0 = bias[col], b1 = bias[col + 1];
        #pragma unroll
        for (int mt = 0; mt < 4; mt++) {
            const int r = row0 + wm + mt * 16 + g;
            float2 v0, v1;
            v0.x = acc[mt][nt][0] + b0; v0.y = acc[mt][nt][1] + b1;
            v1.x = acc[mt][nt][2] + b0; v1.y = acc[mt][nt][3] + b1;
            *(float2*)(C + (long long)r * Cdim + col)       = v0;
            *(float2*)(C + (long long)(r + 8) * Cdim + col) = v1;
        }
    }
}

// ---------------- fused attention v3 (R13-proven; epilogue -> single fp16 O) -------
constexpr int FA_NIT  = Sk / 64;                 // 40
constexpr int F3_QH   = 0;
constexpr int F3_QL   = 34816;
constexpr int F3_K0   = 69632;
constexpr int F3_KBUF = 34816;
constexpr int F3_KLOF = 17408;
constexpr int F3_VH   = 139264;
constexpr int F3_VL   = 157696;
constexpr int F3_YB   = 176128;
constexpr int FA_SMEM = 178176;

__global__ __launch_bounds__(256, 1)
void fused_attn(const __nv_bfloat16* __restrict__ Qh, const __nv_bfloat16* __restrict__ Ql,
                const __nv_bfloat16* __restrict__ Kh, const __nv_bfloat16* __restrict__ Kl,
                const __nv_bfloat16* __restrict__ Vth, const __nv_bfloat16* __restrict__ Vtl,
                const float* __restrict__ ytw,
                __half* __restrict__ Oh)
{
    extern __shared__ char smem[];
    const uint32_t sb = smem_u32(smem);

    const int z  = blockIdx.y;
    const int q0 = blockIdx.x * 128;
    const int b  = z / Hn;
    const int h  = z % Hn;

    const int tid  = threadIdx.x;
    const int lane = tid & 31;
    const int wid  = tid >> 5;
    const int g    = lane >> 2;
    const int tg   = lane & 3;
    const int wm   = wid * 16;

    const __nv_bfloat16* Qhp = Qh + (long long)z * Nq * HDim;
    const __nv_bfloat16* Qlp = Ql + (long long)z * Nq * HDim;
    const __nv_bfloat16* Khp = Kh + (long long)z * Sk * HDim;
    const __nv_bfloat16* Klp = Kl + (long long)z * Sk * HDim;
    const __nv_bfloat16* Vhp = Vth + (long long)z * HDim * Sk;
    const __nv_bfloat16* Vlp = Vtl + (long long)z * HDim * Sk;

    float* sYB = (float*)(smem + F3_YB);
    #pragma unroll
    for (int j = 0; j < 2; j++) {
        const int i = tid + j * 256;
        sYB[i] = logf(fmaxf(ytw[b * My + i], 1e-4f));
    }

    #pragma unroll
    for (int j = 0; j < 8; j++) {
        const int id = tid + j * 256, r = id >> 4, c = id & 15;
        cp16(sb + F3_QH + r * 272 + c * 16, Qhp + (long long)(q0 + r) * HDim + c * 8);
        cp16(sb + F3_QL + r * 272 + c * 16, Qlp + (long long)(q0 + r) * HDim + c * 8);
    }
    CP_COMMIT();
    #pragma unroll
    for (int j = 0; j < 4; j++) {
        const int id = tid + j * 256, r = id >> 4, c = id & 15;
        cp16(sb + F3_K0 +           r * 272 + c * 16, Khp + (long long)r * HDim + c * 8);
        cp16(sb + F3_K0 + F3_KLOF + r * 272 + c * 16, Klp + (long long)r * HDim + c * 8);
    }
    CP_COMMIT();

    float oacc[16][4];
    #pragma unroll
    for (int i = 0; i < 16; i++)
        #pragma unroll
        for (int r = 0; r < 4; r++) oacc[i][r] = 0.f;
    float rowsum0 = 0.f, rowsum1 = 0.f;

    for (int it = 0; it < FA_NIT; it++) {
        __syncthreads();

        if (it + 1 < FA_NIT) {
            const uint32_t kb = sb + F3_K0 + ((it + 1) & 1) * F3_KBUF;
            const int sblk = (it + 1) * 64;
            #pragma unroll
            for (int j = 0; j < 4; j++) {
                const int id = tid + j * 256, r = id >> 4, c = id & 15;
                cp16(kb +           r * 272 + c * 16, Khp + (long long)(sblk + r) * HDim + c * 8);
                cp16(kb + F3_KLOF + r * 272 + c * 16, Klp + (long long)(sblk + r) * HDim + c * 8);
            }
        }
        CP_COMMIT();
        #pragma unroll
        for (int j = 0; j < 4; j++) {
            const int id = tid + j * 256, d = id >> 3, c = id & 7;
            cp16(sb + F3_VH + d * 144 + c * 16, Vhp + (long long)d * Sk + it * 64 + c * 8);
            cp16(sb + F3_VL + d * 144 + c * 16, Vlp + (long long)d * Sk + it * 64 + c * 8);
        }
        CP_COMMIT();

        CP_WAIT(2);
        __syncthreads();

        const uint32_t kcur = sb + F3_K0 + (it & 1) * F3_KBUF;
        float sacc[8][4];
        #pragma unroll
        for (int i = 0; i < 8; i++)
            #pragma unroll
            for (int r = 0; r < 4; r++) sacc[i][r] = 0.f;

        #pragma unroll
        for (int kk = 0; kk < 8; kk++) {
            const int cb = kk * 32 + tg * 4;
            uint32_t qh_[4], ql_[4], kh_[8][2], kl_[8][2];
            {
                const char* p = smem + F3_QH + (wm + g) * 272 + cb;
                qh_[0] = *(const uint32_t*)(p);
                qh_[1] = *(const uint32_t*)(p + 8 * 272);
                qh_[2] = *(const uint32_t*)(p + 16);
                qh_[3] = *(const uint32_t*)(p + 8 * 272 + 16);
                const char* q = p + (F3_QL - F3_QH);
                ql_[0] = *(const uint32_t*)(q);
                ql_[1] = *(const uint32_t*)(q + 8 * 272);
                ql_[2] = *(const uint32_t*)(q + 16);
                ql_[3] = *(const uint32_t*)(q + 8 * 272 + 16);
            }
            #pragma unroll
            for (int nt = 0; nt < 8; nt++) {
                const char* p = (const char*)smem + (kcur - sb) + (nt * 8 + g) * 272 + cb;
                kh_[nt][0] = *(const uint32_t*)(p);
                kh_[nt][1] = *(const uint32_t*)(p + 16);
                kl_[nt][0] = *(const uint32_t*)(p + F3_KLOF);
                kl_[nt][1] = *(const uint32_t*)(p + F3_KLOF + 16);
            }
            #pragma unroll
            for (int nt = 0; nt < 8; nt++) {
                mma_bf16(sacc[nt], qh_, kh_[nt]);
                mma_bf16(sacc[nt], qh_, kl_[nt]);
                mma_bf16(sacc[nt], ql_, kh_[nt]);
            }
        }

        uint32_t ph_[4][4], pl_[4][4];
        #pragma unroll
        for (int nt = 0; nt < 8; nt++) {
            const int col0 = nt * 8 + 2 * tg;
            const int gc   = it * 64 + col0;
            float b0 = 0.f, b1 = 0.f;
            if (gc >= Nq) { b0 = sYB[gc - Nq]; b1 = sYB[gc - Nq + 1]; }
            const float p0 = __expf(sacc[nt][0] * SCALE + b0);
            const float p1 = __expf(sacc[nt][1] * SCALE + b1);
            const float p2 = __expf(sacc[nt][2] * SCALE + b0);
            const float p3 = __expf(sacc[nt][3] * SCALE + b1);
            rowsum0 += p0 + p1;
            rowsum1 += p2 + p3;
            const int j  = nt >> 1;
            const int rb = (nt & 1) * 2;
            const uint32_t h01 = pack_bf2(p0, p1);
            const uint32_t h23 = pack_bf2(p2, p3);
            ph_[j][rb + 0] = h01;
            ph_[j][rb + 1] = h23;
            const __nv_bfloat162 hb01 = *(const __nv_bfloat162*)&h01;
            const __nv_bfloat162 hb23 = *(const __nv_bfloat162*)&h23;
            pl_[j][rb + 0] = pack_bf2(p0 - __bfloat162float(hb01.x), p1 - __bfloat162float(hb01.y));
            pl_[j][rb + 1] = pack_bf2(p2 - __bfloat162float(hb23.x), p3 - __bfloat162float(hb23.y));
        }

        CP_WAIT(1);
        __syncthreads();

        #pragma unroll
        for (int j = 0; j < 4; j++) {
            const int cb = j * 32 + tg * 4;
            #pragma unroll
            for (int nt = 0; nt < 16; nt++) {
                uint32_t vh_[2], vl_[2];
                const char* p = smem + F3_VH + (nt * 8 + g) * 144 + cb;
                vh_[0] = *(const uint32_t*)(p);
                vh_[1] = *(const uint32_t*)(p + 16);
                vl_[0] = *(const uint32_t*)(p + (F3_VL - F3_VH));
                vl_[1] = *(const uint32_t*)(p + (F3_VL - F3_VH) + 16);
                mma_bf16(oacc[nt], ph_[j], vh_);
                mma_bf16(oacc[nt], ph_[j], vl_);
                mma_bf16(oacc[nt], pl_[j], vh_);
            }
        }
    }

    rowsum0 += __shfl_xor_sync(0xffffffffu, rowsum0, 1);
    rowsum0 += __shfl_xor_sync(0xffffffffu, rowsum0, 2);
    rowsum1 += __shfl_xor_sync(0xffffffffu, rowsum1, 1);
    rowsum1 += __shfl_xor_sync(0xffffffffu, rowsum1, 2);
    const float inv0 = 1.f / rowsum0;
    const float inv1 = 1.f / rowsum1;

    // epilogue: normalize, write single fp16 O into [b][n][h*128 + d]
    const int r = wm + g;
    #pragma unroll
    for (int nt = 0; nt < 16; nt++) {
        const int col = nt * 8 + 2 * tg;
        const long long o0 = ((long long)b * Nq + q0 + r) * Cdim + h * HDim + col;
        const long long o1 = o0 + 8LL * Cdim;
        __half2 v0, v1;
        v0.x = __float2half(oacc[nt][0] * inv0);
        v0.y = __float2half(oacc[nt][1] * inv0);
        v1.x = __float2half(oacc[nt][2] * inv1);
        v1.y = __float2half(oacc[nt][3] * inv1);
        *(__half2*)(Oh + o0) = v0;
        *(__half2*)(Oh + o1) = v1;
    }
}

// ---------------- fp32 -> single fp16, two tensors in one launch ----------------
__global__ void cvt_single2(const float* __restrict__ s1, __half* __restrict__ h1, long long n1,
                            const float* __restrict__ s2, __half* __restrict__ h2, long long n2)
{
    long long i = ((long long)blockIdx.x * blockDim.x + threadIdx.x) * 4;
    const float* src; __half* h;
    if (i < n1) { src = s1; h = h1; }
    else        { i -= n1; if (i >= n2) return; src = s2; h = h2; }
    const float4 v = *(const float4*)(src + i);
    __half hb[4];
    hb[0] = __float2half(v.x); hb[1] = __float2half(v.y);
    hb[2] = __float2half(v.z); hb[3] = __float2half(v.w);
    *(uint2*)(h + i) = *(uint2*)hb;
}

// ---------------- fp32 [K][N] -> split fp16 transposed [N][K]; 2 weights packed ----
constexpr int WQ_BLKS = (3 * Cdim / 32) * (Cdim / 32);   // 6912
constexpr int WK_BLKS = (2 * Cdim / 32) * (Cdim / 32);   // 4608

__global__ void cvt_split_T2(const float* __restrict__ W1, __half* __restrict__ h1,
                             __half* __restrict__ l1,
                             const float* __restrict__ W2, __half* __restrict__ h2,
                             __half* __restrict__ l2)
{
    __shared__ float tile[32][33];
    const int tid = threadIdx.x;
    const int tx = tid & 31;
    const int ty = tid >> 5;

    const float* W; __half *h, *l;
    int N, n0, k0;
    int bid = blockIdx.x;
    if (bid < WQ_BLKS) {
        W = W1; h = h1; l = l1; N = 3 * Cdim;
        n0 = (bid % (N / 32)) * 32;  k0 = (bid / (N / 32)) * 32;
    } else {
        bid -= WQ_BLKS;
        W = W2; h = h2; l = l2; N = 2 * Cdim;
        n0 = (bid % (N / 32)) * 32;  k0 = (bid / (N / 32)) * 32;
    }

    #pragma unroll
    for (int i = ty; i < 32; i += 8)
        tile[i][tx] = W[(long long)(k0 + i) * N + n0 + tx];
    __syncthreads();
    #pragma unroll
    for (int i = ty; i < 32; i += 8) {
        const float v = tile[tx][i];
        const __half hb = __float2half(v);
        const __half lb = __float2half(v - __half2float(hb));
        const long long o = (long long)(n0 + i) * Cdim + k0 + tx;
        h[o] = hb; l[o] = lb;
    }
}

// ---------------- single-weight transposed split fp16 (Wproj) ----------------
__global__ void cvt_split_T(const float* __restrict__ W, __half* __restrict__ h,
                            __half* __restrict__ l, int K, int N)
{
    __shared__ float tile[32][33];
    const int k0 = blockIdx.y * 32;
    const int n0 = blockIdx.x * 32;
    const int tx = threadIdx.x;
    const int ty = threadIdx.y;
    #pragma unroll
    for (int i = ty; i < 32; i += 8)
        tile[i][tx] = W[(long long)(k0 + i) * N + n0 + tx];
    __syncthreads();
    #pragma unroll
    for (int i = ty; i < 32; i += 8) {
        const float v = tile[tx][i];
        const __half hb = __float2half(v);
        const __half lb = __float2half(v - __half2float(hb));
        const long long o = (long long)(n0 + i) * K + k0 + tx;
        h[o] = hb; l[o] = lb;
    }
}

// ---------------- V: fp32 [bh][s][d] -> split bf16 transposed [bh][d][s] ----------
__global__ void v_transpose_split(const float* __restrict__ Vb,
                                  __nv_bfloat16* __restrict__ Vth,
                                  __nv_bfloat16* __restrict__ Vtl)
{
    __shared__ float tile[32][33];
    const int z  = blockIdx.z;
    const int ss0 = blockIdx.x * 32;
    const int dd0 = blockIdx.y * 32;
    const int tx = threadIdx.x;
    const int ty = threadIdx.y;
    const long long ib = (long long)z * Sk * HDim;
    const long long ob = (long long)z * HDim * Sk;
    #pragma unroll
    for (int i = ty; i < 32; i += 8)
        tile[i][tx] = Vb[ib + (long long)(ss0 + i) * HDim + dd0 + tx];
    __syncthreads();
    #pragma unroll
    for (int i = ty; i < 32; i += 8) {
        const float v = tile[tx][i];
        const __nv_bfloat16 hb = __float2bfloat16(v);
        const __nv_bfloat16 lb = __float2bfloat16(v - __bfloat162float(hb));
        const long long o = ob + (long long)(dd0 + i) * Sk + ss0 + tx;
        Vth[o] = hb; Vtl[o] = lb;
    }
}

// ---------------- warp reduction helpers ----------------
__device__ __forceinline__ float warpSum(float v) {
    #pragma unroll
    for (int o = 16; o > 0; o >>= 1) v += __shfl_xor_sync(0xffffffffu, v, o);
    return v;
}

// ---------------- QKV postprocess: RMSNorm + RoPE -> split bf16 Q,K; fp32 V ------
__global__ void qkv_post(const float* __restrict__ qkv, const float* __restrict__ pos,
                         const float* __restrict__ qw, const float* __restrict__ kw,
                         __nv_bfloat16* __restrict__ Qh, __nv_bfloat16* __restrict__ Ql,
                         __nv_bfloat16* __restrict__ Kh, __nv_bfloat16* __restrict__ Kl,
                         float* __restrict__ Vb)
{
    const int idx = blockIdx.x;
    const int h  = idx % Hn;
    const int bn = idx / Hn;
    const int n  = bn % Nq;
    const int b  = bn / Nq;
    const int d  = threadIdx.x;

    const float* row = qkv + (long long)bn * (3 * Cdim);
    const float qv = row[h * HDim + d];
    const float kv = row[Cdim + h * HDim + d];
    const float vv = row[2 * Cdim + h * HDim + d];

    __shared__ float sred[8];
    __shared__ float qs[HDim], ks[HDim];

    const float sq = warpSum(qv * qv);
    const float sk = warpSum(kv * kv);
    const int lane = d & 31, w = d >> 5;
    if (lane == 0) { sred[w] = sq; sred[4 + w] = sk; }
    __syncthreads();
    const float sumq = sred[0] + sred[1] + sred[2] + sred[3];
    const float sumk = sred[4] + sred[5] + sred[6] + sred[7];
    const float rq = rsqrtf(sumq * (1.0f / HDim) + EPSV);
    const float rk = rsqrtf(sumk * (1.0f / HDim) + EPSV);
    const float qn = qw[d] * qv * rq;
    const float kn = kw[d] * kv * rk;
    qs[d] = qn; ks[d] = kn;
    __syncthreads();

    float qo = qn, ko = kn;
    if (d < RD) {
        const int j = d & 31;
        const float c = pos[(n * 32 + j) * 2 + 0];
        const float s = pos[(n * 32 + j) * 2 + 1];
        if (d < RD / 2) { qo = qs[d] * c - qs[d + 32] * s;  ko = ks[d] * c - ks[d + 32] * s; }
        else            { qo = qs[d - 32] * s + qs[d] * c;  ko = ks[d - 32] * s + ks[d] * c; }
    }
    const long long qi = (((long long)(b * Hn + h)) * Nq + n) * HDim + d;
    const long long ki = (((long long)(b * Hn + h)) * Sk + n) * HDim + d;
    split_write(qo, Qh, Ql, qi);
    split_write(ko, Kh, Kl, ki);
    Vb[ki] = vv;
}

// ---------------- KV(y) postprocess ----------------
__global__ void kv_post(const float* __restrict__ kvr, const float* __restrict__ kw,
                        __nv_bfloat16* __restrict__ Kh, __nv_bfloat16* __restrict__ Kl,
                        float* __restrict__ Vb)
{
    const int idx = blockIdx.x;
    const int h  = idx % Hn;
    const int bm = idx / Hn;
    const int m  = bm % My;
    const int b  = bm / My;
    const int d  = threadIdx.x;

    const float* row = kvr + (long long)bm * (2 * Cdim);
    const float kv = row[h * HDim + d];
    const float vv = row[Cdim + h * HDim + d];

    __shared__ float sred[4];
    const float sk = warpSum(kv * kv);
    if ((d & 31) == 0) sred[d >> 5] = sk;
    __syncthreads();
    const float sumk = sred[0] + sred[1] + sred[2] + sred[3];
    const float rk = rsqrtf(sumk * (1.0f / HDim) + EPSV);
    const float kn = kw[d] * kv * rk;

    const long long ki = (((long long)(b * Hn + h)) * Sk + (Nq + m)) * HDim + d;
    split_write(kn, Kh, Kl, ki);
    Vb[ki] = vv;
}

// ---------------- launch ----------------
extern "C" void kernel_launch(void* const* d_in, const int* in_sizes, int n_in,
                              void* d_out, int out_size)
{
    const float* x    = (const float*)d_in[0];
    const float* y    = (const float*)d_in[1];
    const float* pos  = (const float*)d_in[2];
    const float* ytw  = (const float*)d_in[3];
    const float* Wqkv = (const float*)d_in[4];
    const float* Wkv  = (const float*)d_in[5];
    const float* qw   = (const float*)d_in[6];
    const float* kw   = (const float*)d_in[7];
    const float* Wproj= (const float*)d_in[8];
    const float* bproj= (const float*)d_in[9];
    float* out = (float*)d_out;

    float *qkv, *kvr, *Vb;
    cudaGetSymbolAddress((void**)&qkv, g_qkv);
    cudaGetSymbolAddress((void**)&kvr, g_kvr);
    cudaGetSymbolAddress((void**)&Vb,  g_Vb);

    __half *xh,*yh,*Wqh,*Wql,*Wkh,*Wkl,*Wph,*Wpl,*Oh;
    __nv_bfloat16 *Qh,*Ql,*Kh,*Kl,*Vth,*Vtl;
    cudaGetSymbolAddress((void**)&xh, g_xh);
    cudaGetSymbolAddress((void**)&yh, g_yh);
    cudaGetSymbolAddress((void**)&Wqh, g_Wqkvh); cudaGetSymbolAddress((void**)&Wql, g_Wqkvl);
    cudaGetSymbolAddress((void**)&Wkh, g_Wkvh);  cudaGetSymbolAddress((void**)&Wkl, g_Wkvl);
    cudaGetSymbolAddress((void**)&Wph, g_Wph);   cudaGetSymbolAddress((void**)&Wpl, g_Wpl);
    cudaGetSymbolAddress((void**)&Oh, g_Oh);
    cudaGetSymbolAddress((void**)&Qh, g_Qh);     cudaGetSymbolAddress((void**)&Ql, g_Ql);
    cudaGetSymbolAddress((void**)&Kh, g_Kh);     cudaGetSymbolAddress((void**)&Kl, g_Kl);
    cudaGetSymbolAddress((void**)&Vth, g_Vth);   cudaGetSymbolAddress((void**)&Vtl, g_Vtl);

    cudaFuncSetAttribute(mma_gemm_fused, cudaFuncAttributeMaxDynamicSharedMemorySize, MM_SMEM_B);
    cudaFuncSetAttribute(mma_gemm_proj,  cudaFuncAttributeMaxDynamicSharedMemorySize, MM_SMEM_B);
    cudaFuncSetAttribute(fused_attn, cudaFuncAttributeMaxDynamicSharedMemorySize, FA_SMEM);

    // 0) conversions: activations -> single fp16; weights -> split fp16 transposed
    const long long nx = (long long)Bsz * Nq * Cdim;
    const long long ny = (long long)Bsz * My * Cdim;
    cvt_single2<<<(int)(((nx + ny) / 4 + 255) / 256), 256>>>(x, xh, nx, y, yh, ny);
    cvt_split_T2<<<WQ_BLKS + WK_BLKS, 256>>>(Wqkv, Wqh, Wql, Wkv, Wkh, Wkl);
    cvt_split_T<<<dim3(Cdim / 32, Cdim / 32), dim3(32, 8)>>>(Wproj, Wph, Wpl, Cdim, Cdim);

    // 1+2) fused QKV + KV weight GEMM (fp16 2-product)
    mma_gemm_fused<<<FUSED_CTAS, 256, MM_SMEM_B>>>(
        xh, Wqh, Wql, qkv, yh, Wkh, Wkl, kvr);

    // 3) postprocess (unchanged bf16-split attention operands)
    qkv_post<<<Bsz * Nq * Hn, HDim>>>(qkv, pos, qw, kw, Qh, Ql, Kh, Kl, Vb);
    kv_post<<<Bsz * My * Hn, HDim>>>(kvr, kw, Kh, Kl, Vb);
    v_transpose_split<<<dim3(Sk / 32, HDim / 32, Bsz * Hn), dim3(32, 8)>>>(Vb, Vth, Vtl);

    // 4-6) fused attention v3 -> single fp16 O
    fused_attn<<<dim3(Nq / 128, Bsz * Hn), 256, FA_SMEM>>>(
        Qh, Ql, Kh, Kl, Vth, Vtl, ytw, Oh);

    // 7) out = O @ Wproj + bproj (fp16 2-product)
    mma_gemm_proj<<<dim3(Cdim / 128, Bsz * Nq / 128), 256, MM_SMEM_B>>>(
        Oh, Wph, Wpl, out, bproj);
}